// round 2
// baseline (speedup 1.0000x reference)
#include <cuda_runtime.h>
#include <math.h>

// Problem constants
#define BB   4
#define SS   2048
#define DD   1024
#define HH   16
#define HDIM 64
#define FF   4096
#define MM   (BB*SS)   // 8192 rows
#define LN_EPS 1e-5f

// ---------------- scratch (device globals; no allocation allowed) ----------------
__device__ float g_q[(size_t)BB*HH*SS*HDIM];     // [B,H,S,HD]
__device__ float g_k[(size_t)BB*HH*SS*HDIM];
__device__ float g_v[(size_t)BB*HH*SS*HDIM];
__device__ float g_attn[(size_t)MM*DD];          // attention out, natural (B,H,S,HD) memory order
__device__ float g_tmp[(size_t)MM*DD];           // pre-LN GEMM results
__device__ float g_x1[(size_t)MM*DD];            // post LN1
__device__ float g_h1[(size_t)MM*FF];            // FFN hidden

// ---------------- generic 64x64 SGEMM tile (256 threads, 4x4 per thread) ----------
template<bool BIAS, bool RELU>
__device__ __forceinline__ void gemm_tile(
    const float* __restrict__ A, int lda,
    const float* __restrict__ W, int ldw,
    const float* __restrict__ bias,
    float* __restrict__ C, int ldc,
    int K, int row0, int col0)
{
    __shared__ __align__(16) float As[16][68];   // k-major, padded
    __shared__ __align__(16) float Bs[16][64];

    const int tid = threadIdx.x;
    const int tx = tid & 15, ty = tid >> 4;
    const int a_row = tid >> 2;          // 0..63
    const int a_k   = (tid & 3) << 2;    // 0,4,8,12
    const int b_k   = tid >> 4;          // 0..15
    const int b_col = (tid & 15) << 2;   // 0..60

    const float* Aptr = A + (size_t)(row0 + a_row) * lda + a_k;
    const float* Wptr = W + (size_t)b_k * ldw + col0 + b_col;

    float acc[4][4] = {};

    for (int k0 = 0; k0 < K; k0 += 16) {
        float4 av = *(const float4*)(Aptr + k0);
        As[a_k+0][a_row] = av.x;
        As[a_k+1][a_row] = av.y;
        As[a_k+2][a_row] = av.z;
        As[a_k+3][a_row] = av.w;
        *(float4*)(&Bs[b_k][b_col]) = *(const float4*)(Wptr + (size_t)k0 * ldw);
        __syncthreads();

        #pragma unroll
        for (int k = 0; k < 16; k++) {
            float4 a  = *(const float4*)(&As[k][ty << 2]);
            float4 bv = *(const float4*)(&Bs[k][tx << 2]);
            float ar[4] = {a.x, a.y, a.z, a.w};
            float br[4] = {bv.x, bv.y, bv.z, bv.w};
            #pragma unroll
            for (int i = 0; i < 4; i++)
                #pragma unroll
                for (int j = 0; j < 4; j++)
                    acc[i][j] += ar[i] * br[j];
        }
        __syncthreads();
    }

    float bv[4] = {0.f, 0.f, 0.f, 0.f};
    if (BIAS) {
        float4 bb = *(const float4*)(bias + col0 + (tx << 2));
        bv[0] = bb.x; bv[1] = bb.y; bv[2] = bb.z; bv[3] = bb.w;
    }
    #pragma unroll
    for (int i = 0; i < 4; i++) {
        float4 o;
        o.x = acc[i][0] + bv[0];
        o.y = acc[i][1] + bv[1];
        o.z = acc[i][2] + bv[2];
        o.w = acc[i][3] + bv[3];
        if (RELU) {
            o.x = fmaxf(o.x, 0.f); o.y = fmaxf(o.y, 0.f);
            o.z = fmaxf(o.z, 0.f); o.w = fmaxf(o.w, 0.f);
        }
        *(float4*)(C + (size_t)(row0 + (ty << 2) + i) * ldc + col0 + (tx << 2)) = o;
    }
}

template<bool BIAS, bool RELU>
__global__ void gemm_kernel(const float* __restrict__ A,
                            const float* __restrict__ W,
                            const float* __restrict__ bias,
                            float* __restrict__ C,
                            int M, int N, int K)
{
    gemm_tile<BIAS, RELU>(A, K, W, N, bias, C, N, K,
                          blockIdx.y * 64, blockIdx.x * 64);
}

// QKV projections: q[b,h,s,e] = sum_d x[b,s,d] * Wq[h,d,e]  (and k,v)
__global__ void gemm_qkv_kernel(const float* __restrict__ x,
                                const float* __restrict__ Wq,
                                const float* __restrict__ Wk,
                                const float* __restrict__ Wv)
{
    int z   = blockIdx.z;            // 0..191
    int mat = z / (BB * HH);         // 0=q,1=k,2=v
    int bh  = z - mat * (BB * HH);
    int b   = bh / HH;
    int h   = bh - b * HH;

    const float* A = x + (size_t)b * SS * DD;
    const float* W = (mat == 0 ? Wq : mat == 1 ? Wk : Wv) + (size_t)h * DD * HDIM;
    float* C = (mat == 0 ? g_q : mat == 1 ? g_k : g_v) + (size_t)bh * SS * HDIM;

    gemm_tile<false, false>(A, DD, W, HDIM, nullptr, C, HDIM, DD,
                            blockIdx.y * 64, 0);
}

// ---------------- causal flash attention (fp32, BM=BN=64, HD=64) -----------------
// smem floats: Qt 64*68, Kt 64*68, Ps 64*68, Vs 64*64, red 64*16, red2 64*16, m 64, l 64
#define FA_SMEM_FLOATS (64*68*3 + 64*64 + 64*16*2 + 64 + 64)

__global__ void flash_attn_kernel()
{
    const int bh = blockIdx.y;                   // 0..63
    const int qt = blockIdx.x;                   // 0..31

    const float* Qg = g_q + (size_t)bh * SS * HDIM;
    const float* Kg = g_k + (size_t)bh * SS * HDIM;
    const float* Vg = g_v + (size_t)bh * SS * HDIM;

    extern __shared__ __align__(16) float sm[];
    float* Qt_  = sm;                 // [64 dims][68] (d-major, transposed)
    float* Kt_  = Qt_  + 64*68;
    float* Ps   = Kt_  + 64*68;       // [64 rows][68]
    float* Vs   = Ps   + 64*68;       // [64 keys][64]
    float* red  = Vs   + 64*64;       // [64][16]
    float* red2 = red  + 64*16;       // [64][16]
    float* m_s  = red2 + 64*16;       // [64]
    float* l_s  = m_s  + 64;          // [64]

    const int tid = threadIdx.x;
    const int tx = tid & 15, ty = tid >> 4;
    const int r0 = ty << 2, c0 = tx << 2;
    const int lrow = tid >> 4;            // 0..15
    const int lcol = (tid & 15) << 2;     // 0..60

    // load Q tile, transposed to d-major
    #pragma unroll
    for (int it = 0; it < 4; it++) {
        int row = it * 16 + lrow;
        float4 v = *(const float4*)(Qg + (size_t)(qt * 64 + row) * HDIM + lcol);
        Qt_[(lcol+0)*68 + row] = v.x;
        Qt_[(lcol+1)*68 + row] = v.y;
        Qt_[(lcol+2)*68 + row] = v.z;
        Qt_[(lcol+3)*68 + row] = v.w;
    }
    if (tid < 64) { m_s[tid] = -1e30f; l_s[tid] = 0.f; }

    float o[4][4] = {};
    const float scale = 0.125f;   // 1/sqrt(64)

    for (int kt = 0; kt <= qt; kt++) {
        __syncthreads();   // guards Q/K/V/red reuse (and Q load on first iter)

        // load K (transposed) and V tiles
        #pragma unroll
        for (int it = 0; it < 4; it++) {
            int row = it * 16 + lrow;
            float4 kv = *(const float4*)(Kg + (size_t)(kt * 64 + row) * HDIM + lcol);
            Kt_[(lcol+0)*68 + row] = kv.x;
            Kt_[(lcol+1)*68 + row] = kv.y;
            Kt_[(lcol+2)*68 + row] = kv.z;
            Kt_[(lcol+3)*68 + row] = kv.w;
            float4 vv = *(const float4*)(Vg + (size_t)(kt * 64 + row) * HDIM + lcol);
            *(float4*)(Vs + row * 64 + lcol) = vv;
        }
        __syncthreads();

        // scores S = Q K^T
        float s[4][4] = {};
        #pragma unroll 16
        for (int d = 0; d < 64; d++) {
            float4 a  = *(const float4*)(Qt_ + d*68 + r0);
            float4 kk = *(const float4*)(Kt_ + d*68 + c0);
            float ar[4] = {a.x, a.y, a.z, a.w};
            float br[4] = {kk.x, kk.y, kk.z, kk.w};
            #pragma unroll
            for (int i = 0; i < 4; i++)
                #pragma unroll
                for (int j = 0; j < 4; j++)
                    s[i][j] += ar[i] * br[j];
        }

        // scale + causal mask + per-thread row max
        #pragma unroll
        for (int i = 0; i < 4; i++) {
            int grow = qt * 64 + r0 + i;
            float mx = -1e30f;
            #pragma unroll
            for (int j = 0; j < 4; j++) {
                int gcol = kt * 64 + c0 + j;
                float v = s[i][j] * scale;
                if (gcol > grow) v = -1e30f;
                s[i][j] = v;
                mx = fmaxf(mx, v);
            }
            red[(r0 + i) * 16 + tx] = mx;
        }
        __syncthreads();

        // online softmax: new row max, correction, P tile, partial row sums
        float m_new[4], cfac[4];
        #pragma unroll
        for (int i = 0; i < 4; i++) {
            int r = r0 + i;
            float m_old = m_s[r];
            float mx = m_old;
            #pragma unroll
            for (int t = 0; t < 16; t++) mx = fmaxf(mx, red[r * 16 + t]);
            m_new[i] = mx;
            cfac[i]  = __expf(m_old - mx);
            float p0 = __expf(s[i][0] - mx);
            float p1 = __expf(s[i][1] - mx);
            float p2 = __expf(s[i][2] - mx);
            float p3 = __expf(s[i][3] - mx);
            *(float4*)(Ps + r * 68 + c0) = make_float4(p0, p1, p2, p3);
            red2[r * 16 + tx] = p0 + p1 + p2 + p3;
            #pragma unroll
            for (int j = 0; j < 4; j++) o[i][j] *= cfac[i];
        }
        __syncthreads();

        // one thread per row updates running stats
        if (tx == 0) {
            #pragma unroll
            for (int i = 0; i < 4; i++) {
                int r = r0 + i;
                float sum = 0.f;
                #pragma unroll
                for (int t = 0; t < 16; t++) sum += red2[r * 16 + t];
                l_s[r] = l_s[r] * cfac[i] + sum;
                m_s[r] = m_new[i];
            }
        }

        // O += P @ V
        #pragma unroll 16
        for (int k = 0; k < 64; k++) {
            float4 vv = *(const float4*)(Vs + k * 64 + c0);
            float p[4];
            #pragma unroll
            for (int i = 0; i < 4; i++) p[i] = Ps[(r0 + i) * 68 + k];
            #pragma unroll
            for (int i = 0; i < 4; i++) {
                o[i][0] += p[i] * vv.x;
                o[i][1] += p[i] * vv.y;
                o[i][2] += p[i] * vv.z;
                o[i][3] += p[i] * vv.w;
            }
        }
    }
    __syncthreads();

    // epilogue: normalize and write in NATURAL (bh, s, e) contiguous order.
    // The reference's reshape is a raw view of the contiguous (B,H,S,HD)
    // buffer as (B, S, H*HD), so the flat [8192 x 1024] matrix for the Wo
    // GEMM is exactly this natural memory order.
    float* outp = g_attn + (size_t)bh * SS * HDIM + (size_t)(qt * 64) * HDIM;
    #pragma unroll
    for (int i = 0; i < 4; i++) {
        int r = r0 + i;
        float inv = 1.f / l_s[r];
        float4 v = make_float4(o[i][0]*inv, o[i][1]*inv, o[i][2]*inv, o[i][3]*inv);
        *(float4*)(outp + (size_t)r * HDIM + c0) = v;
    }
}

// ---------------- LayerNorm(resid + y) * gamma + beta ----------------------------
__device__ __forceinline__ float blk_sum(float v, float* sred)
{
    #pragma unroll
    for (int o = 16; o; o >>= 1) v += __shfl_xor_sync(0xffffffffu, v, o);
    int w = threadIdx.x >> 5;
    if ((threadIdx.x & 31) == 0) sred[w] = v;
    __syncthreads();
    float t = (threadIdx.x < 8) ? sred[threadIdx.x] : 0.f;
    if (threadIdx.x < 32) {
        #pragma unroll
        for (int o = 4; o; o >>= 1) t += __shfl_xor_sync(0xffffffffu, t, o);
        if (threadIdx.x == 0) sred[0] = t;
    }
    __syncthreads();
    float r = sred[0];
    __syncthreads();
    return r;
}

__global__ void ln_kernel(const float* __restrict__ resid,
                          const float* __restrict__ y,
                          const float* __restrict__ gamma,
                          const float* __restrict__ beta,
                          float* __restrict__ out)
{
    __shared__ float sred[32];
    const int row = blockIdx.x;
    const int tid = threadIdx.x;     // 256 threads, 4 elems each (D=1024)

    float4 a = ((const float4*)(resid + (size_t)row * DD))[tid];
    float4 b = ((const float4*)(y     + (size_t)row * DD))[tid];
    float4 v = make_float4(a.x + b.x, a.y + b.y, a.z + b.z, a.w + b.w);

    float total = blk_sum(v.x + v.y + v.z + v.w, sred);
    float mu = total * (1.f / DD);

    float dx = v.x - mu, dy = v.y - mu, dz = v.z - mu, dw = v.w - mu;
    float tot2 = blk_sum(dx*dx + dy*dy + dz*dz + dw*dw, sred);
    float inv = rsqrtf(tot2 * (1.f / DD) + LN_EPS);

    float4 g = ((const float4*)gamma)[tid];
    float4 be = ((const float4*)beta)[tid];
    float4 o = make_float4(dx * inv * g.x + be.x,
                           dy * inv * g.y + be.y,
                           dz * inv * g.z + be.z,
                           dw * inv * g.w + be.w);
    ((float4*)(out + (size_t)row * DD))[tid] = o;
}

// ---------------- launch ----------------------------------------------------------
extern "C" void kernel_launch(void* const* d_in, const int* in_sizes, int n_in,
                              void* d_out, int out_size)
{
    (void)in_sizes; (void)n_in; (void)out_size;

    const float* x     = (const float*)d_in[0];
    const float* Wq    = (const float*)d_in[1];
    const float* Wk    = (const float*)d_in[2];
    const float* Wv    = (const float*)d_in[3];
    const float* Wo    = (const float*)d_in[4];
    const float* g1    = (const float*)d_in[5];
    const float* be1   = (const float*)d_in[6];
    const float* w_in  = (const float*)d_in[7];
    const float* b_in  = (const float*)d_in[8];
    const float* w_out = (const float*)d_in[9];
    const float* b_out = (const float*)d_in[10];
    const float* g2    = (const float*)d_in[11];
    const float* be2   = (const float*)d_in[12];
    float* out = (float*)d_out;

    float *attn, *tmp, *x1, *h1;
    cudaGetSymbolAddress((void**)&attn, g_attn);
    cudaGetSymbolAddress((void**)&tmp,  g_tmp);
    cudaGetSymbolAddress((void**)&x1,   g_x1);
    cudaGetSymbolAddress((void**)&h1,   g_h1);

    // 1) QKV projections
    gemm_qkv_kernel<<<dim3(1, SS/64, 3*BB*HH), 256>>>(x, Wq, Wk, Wv);

    // 2) causal flash attention
    const size_t fa_smem = FA_SMEM_FLOATS * sizeof(float);   // ~77 KB
    cudaFuncSetAttribute(flash_attn_kernel,
                         cudaFuncAttributeMaxDynamicSharedMemorySize, (int)fa_smem);
    flash_attn_kernel<<<dim3(SS/64, BB*HH), 256, fa_smem>>>();

    // 3) output projection (attn buffer viewed flat as [8192 x 1024])
    gemm_kernel<false,false><<<dim3(DD/64, MM/64), 256>>>(attn, Wo, nullptr, tmp, MM, DD, DD);

    // 4) LN1 (x + attn@Wo)
    ln_kernel<<<MM, 256>>>(x, tmp, g1, be1, x1);

    // 5) FFN up + ReLU
    gemm_kernel<true,true><<<dim3(FF/64, MM/64), 256>>>(x1, w_in, b_in, h1, MM, FF, DD);

    // 6) FFN down
    gemm_kernel<true,false><<<dim3(DD/64, MM/64), 256>>>(h1, w_out, b_out, tmp, MM, DD, FF);

    // 7) LN2 (x1 + ffn) -> output
    ln_kernel<<<MM, 256>>>(x1, tmp, g2, be2, out);
}

// round 4
// speedup vs baseline: 1.7983x; 1.7983x over previous
#include <cuda_runtime.h>
#include <cuda_bf16.h>
#include <math.h>

// Problem constants
#define BB   4
#define SS   2048
#define DD   1024
#define HH   16
#define HDIM 64
#define FF   4096
#define MM   (BB*SS)   // 8192 rows
#define LN_EPS 1e-5f

// ===================== low-level helpers =====================
__device__ __forceinline__ unsigned int smem_u32(const void* p) {
    unsigned int a;
    asm("{ .reg .u64 t; cvta.to.shared.u64 t, %1; cvt.u32.u64 %0, t; }" : "=r"(a) : "l"(p));
    return a;
}
__device__ __forceinline__ void cp16(unsigned int s, const void* g) {
    asm volatile("cp.async.cg.shared.global [%0], [%1], 16;" :: "r"(s), "l"(g));
}
#define CP_COMMIT() asm volatile("cp.async.commit_group;" ::: "memory")
#define CP_WAIT1()  asm volatile("cp.async.wait_group 1;" ::: "memory")

__device__ __forceinline__ void ldsm4(unsigned int* r, unsigned int addr) {
    asm volatile("ldmatrix.sync.aligned.m8n8.x4.shared.b16 {%0,%1,%2,%3}, [%4];"
        : "=r"(r[0]), "=r"(r[1]), "=r"(r[2]), "=r"(r[3]) : "r"(addr));
}
__device__ __forceinline__ void mma_bf16(float* c, const unsigned int* a,
                                         unsigned int b0, unsigned int b1) {
    asm volatile("mma.sync.aligned.m16n8k16.row.col.f32.bf16.bf16.f32 "
        "{%0,%1,%2,%3}, {%4,%5,%6,%7}, {%8,%9}, {%0,%1,%2,%3};"
        : "+f"(c[0]), "+f"(c[1]), "+f"(c[2]), "+f"(c[3])
        : "r"(a[0]), "r"(a[1]), "r"(a[2]), "r"(a[3]), "r"(b0), "r"(b1));
}
__device__ __forceinline__ unsigned int pack_bf16(__nv_bfloat16 a, __nv_bfloat16 b) {
    return (unsigned int)__bfloat16_as_ushort(a) | ((unsigned int)__bfloat16_as_ushort(b) << 16);
}

// ===================== scratch (device globals) =====================
__device__ float g_qkv[(size_t)MM*3072];
__device__ __nv_bfloat16 g_xh[(size_t)MM*DD],  g_xl[(size_t)MM*DD];
__device__ __nv_bfloat16 g_ah[(size_t)MM*DD],  g_al[(size_t)MM*DD];
__device__ float g_tmp[(size_t)MM*DD];
__device__ float g_x1[(size_t)MM*DD];
__device__ __nv_bfloat16 g_x1h[(size_t)MM*DD], g_x1l[(size_t)MM*DD];
__device__ __nv_bfloat16 g_h1h[(size_t)MM*FF], g_h1l[(size_t)MM*FF];
// transposed + split weights ([N,K] row-major bf16)
__device__ __nv_bfloat16 g_wqkvh[(size_t)3072*1024], g_wqkvl[(size_t)3072*1024];
__device__ __nv_bfloat16 g_woh[(size_t)1024*1024],   g_wol[(size_t)1024*1024];
__device__ __nv_bfloat16 g_winh[(size_t)4096*1024],  g_winl[(size_t)4096*1024];
__device__ __nv_bfloat16 g_wouth[(size_t)1024*4096], g_woutl[(size_t)1024*4096];

// ===================== prep kernels =====================
__global__ void fsplit_kernel(const float* __restrict__ in,
                              __nv_bfloat16* __restrict__ h,
                              __nv_bfloat16* __restrict__ l, int n4)
{
    int i = blockIdx.x * blockDim.x + threadIdx.x;
    if (i >= n4) return;
    float4 v = ((const float4*)in)[i];
    float vv[4] = {v.x, v.y, v.z, v.w};
    unsigned int ph[2], pl[2];
    #pragma unroll
    for (int q = 0; q < 2; q++) {
        __nv_bfloat16 h0 = __float2bfloat16(vv[2*q]);
        __nv_bfloat16 h1 = __float2bfloat16(vv[2*q+1]);
        __nv_bfloat16 l0 = __float2bfloat16(vv[2*q]   - __bfloat162float(h0));
        __nv_bfloat16 l1 = __float2bfloat16(vv[2*q+1] - __bfloat162float(h1));
        ph[q] = pack_bf16(h0, h1);
        pl[q] = pack_bf16(l0, l1);
    }
    ((uint2*)h)[i] = make_uint2(ph[0], ph[1]);
    ((uint2*)l)[i] = make_uint2(pl[0], pl[1]);
}

__global__ void wsplitT_kernel(const float* __restrict__ W,
                               __nv_bfloat16* __restrict__ Th,
                               __nv_bfloat16* __restrict__ Tl, int K, int N)
{
    __shared__ float t[32][33];
    int k0 = blockIdx.y * 32, n0 = blockIdx.x * 32;
    int tx = threadIdx.x, ty = threadIdx.y;
    #pragma unroll
    for (int i = 0; i < 32; i += 8)
        t[ty + i][tx] = W[(size_t)(k0 + ty + i) * N + n0 + tx];
    __syncthreads();
    #pragma unroll
    for (int i = 0; i < 32; i += 8) {
        float v = t[tx][ty + i];
        __nv_bfloat16 h = __float2bfloat16(v);
        size_t o = (size_t)(n0 + ty + i) * K + k0 + tx;
        Th[o] = h;
        Tl[o] = __float2bfloat16(v - __bfloat162float(h));
    }
}

__global__ void qkvT_kernel(const float* __restrict__ Wq,
                            const float* __restrict__ Wk,
                            const float* __restrict__ Wv,
                            __nv_bfloat16* __restrict__ Th,
                            __nv_bfloat16* __restrict__ Tl)
{
    __shared__ float t[32][33];
    int z = blockIdx.z;
    int mat = z / HH, h = z - mat * HH;
    const float* W = (mat == 0 ? Wq : mat == 1 ? Wk : Wv) + (size_t)h * DD * HDIM;
    int k0 = blockIdx.y * 32, e0 = blockIdx.x * 32;
    int tx = threadIdx.x, ty = threadIdx.y;
    #pragma unroll
    for (int i = 0; i < 32; i += 8)
        t[ty + i][tx] = W[(size_t)(k0 + ty + i) * HDIM + e0 + tx];
    __syncthreads();
    int nbase = mat * 1024 + h * HDIM;
    #pragma unroll
    for (int i = 0; i < 32; i += 8) {
        float v = t[tx][ty + i];
        __nv_bfloat16 hv = __float2bfloat16(v);
        size_t o = (size_t)(nbase + e0 + ty + i) * DD + k0 + tx;
        Th[o] = hv;
        Tl[o] = __float2bfloat16(v - __bfloat162float(hv));
    }
}

// ===================== mma.sync bf16x3 GEMM =====================
// Block 128x128, K-chunk 32, 3-stage cp.async pipeline, 8 warps (2x4), warp 64x32.
#define GPITCH 80
#define MAT_B  (128*GPITCH)     // 10240
#define STG_B  (4*MAT_B)        // 40960
#define NSTG   3
#define GT_SMEM (NSTG*STG_B)    // 122880

template<bool BIAS, bool RELU, bool F32OUT, bool SPLIT>
__global__ void __launch_bounds__(256, 1) gemm_tc_kernel(
    const __nv_bfloat16* __restrict__ Ah, const __nv_bfloat16* __restrict__ Al,
    const __nv_bfloat16* __restrict__ BTh, const __nv_bfloat16* __restrict__ BTl,
    const float* __restrict__ bias,
    float* __restrict__ C,
    __nv_bfloat16* __restrict__ Ch, __nv_bfloat16* __restrict__ Cl,
    int M, int N, int K)
{
    extern __shared__ __align__(16) char smem[];
    const unsigned int sb = smem_u32(smem);
    const int tid = threadIdx.x;
    const int row0 = blockIdx.y * 128;
    const int col0 = blockIdx.x * 128;

    const int wid = tid >> 5, lane = tid & 31;
    const int wm0 = (wid & 1) * 64, wn0 = (wid >> 1) * 32;
    const int lr = lane & 15, lh = lane >> 4;

    auto load_stage = [&](int c, int s) {
        unsigned int base = sb + s * STG_B;
        int k0 = c * 32;
        #pragma unroll
        for (int i = 0; i < 2; i++) {
            int lin = tid + (i << 8);          // 0..511
            int r = lin >> 2, ck = lin & 3;
            unsigned int so = r * GPITCH + ck * 16;
            size_t ga = (size_t)(row0 + r) * K + k0 + ck * 8;
            size_t gb = (size_t)(col0 + r) * K + k0 + ck * 8;
            cp16(base + so,             Ah  + ga);
            cp16(base + MAT_B + so,     Al  + ga);
            cp16(base + 2*MAT_B + so,   BTh + gb);
            cp16(base + 3*MAT_B + so,   BTl + gb);
        }
        CP_COMMIT();
    };

    float acc[4][4][4] = {};

    load_stage(0, 0);
    load_stage(1, 1);

    const int NC = K >> 5;
    for (int c = 0; c < NC; c++) {
        CP_WAIT1();
        __syncthreads();
        if (c + 2 < NC) load_stage(c + 2, (c + 2) % NSTG);

        unsigned int base = sb + (c % NSTG) * STG_B;
        #pragma unroll
        for (int ks = 0; ks < 2; ks++) {
            unsigned int a_h[4][4], a_l[4][4], b_h[2][4], b_l[2][4];
            #pragma unroll
            for (int mt = 0; mt < 4; mt++) {
                unsigned int ro = (unsigned int)(wm0 + mt*16 + lr) * GPITCH + (ks*2 + lh) * 16;
                ldsm4(a_h[mt], base + ro);
                ldsm4(a_l[mt], base + MAT_B + ro);
            }
            #pragma unroll
            for (int bt = 0; bt < 2; bt++) {
                unsigned int ro = (unsigned int)(wn0 + bt*16 + lr) * GPITCH + (ks*2 + lh) * 16;
                ldsm4(b_h[bt], base + 2*MAT_B + ro);
                ldsm4(b_l[bt], base + 3*MAT_B + ro);
            }
            #pragma unroll
            for (int mt = 0; mt < 4; mt++) {
                #pragma unroll
                for (int nt = 0; nt < 4; nt++) {
                    int bt = nt >> 1, hf = nt & 1;
                    mma_bf16(acc[mt][nt], a_h[mt], b_h[bt][hf], b_h[bt][hf+2]);
                    mma_bf16(acc[mt][nt], a_l[mt], b_h[bt][hf], b_h[bt][hf+2]);
                    mma_bf16(acc[mt][nt], a_h[mt], b_l[bt][hf], b_l[bt][hf+2]);
                }
            }
        }
    }

    // ---- epilogue (register fragments -> gmem) ----
    const int gq = lane >> 2, pq = lane & 3;
    #pragma unroll
    for (int mt = 0; mt < 4; mt++) {
        #pragma unroll
        for (int nt = 0; nt < 4; nt++) {
            int col = col0 + wn0 + nt*8 + pq*2;
            float b0 = 0.f, b1 = 0.f;
            if (BIAS) { b0 = bias[col]; b1 = bias[col+1]; }
            #pragma unroll
            for (int h2 = 0; h2 < 2; h2++) {
                int row = row0 + wm0 + mt*16 + gq + h2*8;
                float v0 = acc[mt][nt][h2*2+0] + b0;
                float v1 = acc[mt][nt][h2*2+1] + b1;
                if (RELU) { v0 = fmaxf(v0, 0.f); v1 = fmaxf(v1, 0.f); }
                if (F32OUT)
                    *(float2*)(C + (size_t)row * N + col) = make_float2(v0, v1);
                if (SPLIT) {
                    __nv_bfloat16 h0 = __float2bfloat16(v0);
                    __nv_bfloat16 h1 = __float2bfloat16(v1);
                    __nv_bfloat16 l0 = __float2bfloat16(v0 - __bfloat162float(h0));
                    __nv_bfloat16 l1 = __float2bfloat16(v1 - __bfloat162float(h1));
                    *(unsigned int*)(Ch + (size_t)row * N + col) = pack_bf16(h0, h1);
                    *(unsigned int*)(Cl + (size_t)row * N + col) = pack_bf16(l0, l1);
                }
            }
        }
    }
}

// ===================== causal flash attention (fp32) =====================
#define FA_SMEM_FLOATS (64*68*3 + 64*64 + 64*16*2 + 64 + 64)

__global__ void flash_attn_kernel()
{
    const int bh = blockIdx.y;                   // 0..63
    const int qt = blockIdx.x;                   // 0..31
    const int b  = bh / HH, h = bh - b * HH;

    const float* Qg = g_qkv + (size_t)b * SS * 3072 + h * HDIM;
    const float* Kg = Qg + 1024;
    const float* Vg = Qg + 2048;

    extern __shared__ __align__(16) float sm[];
    float* Qt_  = sm;
    float* Kt_  = Qt_  + 64*68;
    float* Ps   = Kt_  + 64*68;
    float* Vs   = Ps   + 64*68;
    float* red  = Vs   + 64*64;
    float* red2 = red  + 64*16;
    float* m_s  = red2 + 64*16;
    float* l_s  = m_s  + 64;

    const int tid = threadIdx.x;
    const int tx = tid & 15, ty = tid >> 4;
    const int r0 = ty << 2, c0 = tx << 2;
    const int lrow = tid >> 4;
    const int lcol = (tid & 15) << 2;

    #pragma unroll
    for (int it = 0; it < 4; it++) {
        int row = it * 16 + lrow;
        float4 v = *(const float4*)(Qg + (size_t)(qt * 64 + row) * 3072 + lcol);
        Qt_[(lcol+0)*68 + row] = v.x;
        Qt_[(lcol+1)*68 + row] = v.y;
        Qt_[(lcol+2)*68 + row] = v.z;
        Qt_[(lcol+3)*68 + row] = v.w;
    }
    if (tid < 64) { m_s[tid] = -1e30f; l_s[tid] = 0.f; }

    float o[4][4] = {};
    const float scale = 0.125f;

    for (int kt = 0; kt <= qt; kt++) {
        __syncthreads();
        #pragma unroll
        for (int it = 0; it < 4; it++) {
            int row = it * 16 + lrow;
            float4 kv = *(const float4*)(Kg + (size_t)(kt * 64 + row) * 3072 + lcol);
            Kt_[(lcol+0)*68 + row] = kv.x;
            Kt_[(lcol+1)*68 + row] = kv.y;
            Kt_[(lcol+2)*68 + row] = kv.z;
            Kt_[(lcol+3)*68 + row] = kv.w;
            float4 vv = *(const float4*)(Vg + (size_t)(kt * 64 + row) * 3072 + lcol);
            *(float4*)(Vs + row * 64 + lcol) = vv;
        }
        __syncthreads();

        float s[4][4] = {};
        #pragma unroll 16
        for (int d = 0; d < 64; d++) {
            float4 a  = *(const float4*)(Qt_ + d*68 + r0);
            float4 kk = *(const float4*)(Kt_ + d*68 + c0);
            float ar[4] = {a.x, a.y, a.z, a.w};
            float br[4] = {kk.x, kk.y, kk.z, kk.w};
            #pragma unroll
            for (int i = 0; i < 4; i++)
                #pragma unroll
                for (int j = 0; j < 4; j++)
                    s[i][j] += ar[i] * br[j];
        }

        #pragma unroll
        for (int i = 0; i < 4; i++) {
            int grow = qt * 64 + r0 + i;
            float mx = -1e30f;
            #pragma unroll
            for (int j = 0; j < 4; j++) {
                int gcol = kt * 64 + c0 + j;
                float v = s[i][j] * scale;
                if (gcol > grow) v = -1e30f;
                s[i][j] = v;
                mx = fmaxf(mx, v);
            }
            red[(r0 + i) * 16 + tx] = mx;
        }
        __syncthreads();

        float m_new[4], cfac[4];
        #pragma unroll
        for (int i = 0; i < 4; i++) {
            int r = r0 + i;
            float m_old = m_s[r];
            float mx = m_old;
            #pragma unroll
            for (int t = 0; t < 16; t++) mx = fmaxf(mx, red[r * 16 + t]);
            m_new[i] = mx;
            cfac[i]  = __expf(m_old - mx);
            float p0 = __expf(s[i][0] - mx);
            float p1 = __expf(s[i][1] - mx);
            float p2 = __expf(s[i][2] - mx);
            float p3 = __expf(s[i][3] - mx);
            *(float4*)(Ps + r * 68 + c0) = make_float4(p0, p1, p2, p3);
            red2[r * 16 + tx] = p0 + p1 + p2 + p3;
            #pragma unroll
            for (int j = 0; j < 4; j++) o[i][j] *= cfac[i];
        }
        __syncthreads();

        if (tx == 0) {
            #pragma unroll
            for (int i = 0; i < 4; i++) {
                int r = r0 + i;
                float sum = 0.f;
                #pragma unroll
                for (int t = 0; t < 16; t++) sum += red2[r * 16 + t];
                l_s[r] = l_s[r] * cfac[i] + sum;
                m_s[r] = m_new[i];
            }
        }

        #pragma unroll 16
        for (int k = 0; k < 64; k++) {
            float4 vv = *(const float4*)(Vs + k * 64 + c0);
            float p[4];
            #pragma unroll
            for (int i = 0; i < 4; i++) p[i] = Ps[(r0 + i) * 68 + k];
            #pragma unroll
            for (int i = 0; i < 4; i++) {
                o[i][0] += p[i] * vv.x;
                o[i][1] += p[i] * vv.y;
                o[i][2] += p[i] * vv.z;
                o[i][3] += p[i] * vv.w;
            }
        }
    }
    __syncthreads();

    // epilogue: bf16 hi/lo in natural (bh, s, e) flat order (== reference view)
    __nv_bfloat16* oh = g_ah + (size_t)bh * SS * HDIM + (size_t)(qt * 64) * HDIM;
    __nv_bfloat16* ol = g_al + (size_t)bh * SS * HDIM + (size_t)(qt * 64) * HDIM;
    #pragma unroll
    for (int i = 0; i < 4; i++) {
        int r = r0 + i;
        float inv = 1.f / l_s[r];
        unsigned int wh[2], wl[2];
        #pragma unroll
        for (int q = 0; q < 2; q++) {
            float a = o[i][2*q] * inv, bqv = o[i][2*q+1] * inv;
            __nv_bfloat16 h0 = __float2bfloat16(a);
            __nv_bfloat16 h1 = __float2bfloat16(bqv);
            __nv_bfloat16 l0 = __float2bfloat16(a   - __bfloat162float(h0));
            __nv_bfloat16 l1 = __float2bfloat16(bqv - __bfloat162float(h1));
            wh[q] = pack_bf16(h0, h1);
            wl[q] = pack_bf16(l0, l1);
        }
        *(uint2*)(oh + (size_t)r * HDIM + c0) = make_uint2(wh[0], wh[1]);
        *(uint2*)(ol + (size_t)r * HDIM + c0) = make_uint2(wl[0], wl[1]);
    }
}

// ===================== LayerNorm =====================
__device__ __forceinline__ float blk_sum(float v, float* sred)
{
    #pragma unroll
    for (int o = 16; o; o >>= 1) v += __shfl_xor_sync(0xffffffffu, v, o);
    int w = threadIdx.x >> 5;
    if ((threadIdx.x & 31) == 0) sred[w] = v;
    __syncthreads();
    float t = (threadIdx.x < 8) ? sred[threadIdx.x] : 0.f;
    if (threadIdx.x < 32) {
        #pragma unroll
        for (int o = 4; o; o >>= 1) t += __shfl_xor_sync(0xffffffffu, t, o);
        if (threadIdx.x == 0) sred[0] = t;
    }
    __syncthreads();
    float r = sred[0];
    __syncthreads();
    return r;
}

template<bool SPLIT>
__global__ void ln_kernel(const float* __restrict__ resid,
                          const float* __restrict__ y,
                          const float* __restrict__ gamma,
                          const float* __restrict__ beta,
                          float* __restrict__ outf,
                          __nv_bfloat16* __restrict__ oh,
                          __nv_bfloat16* __restrict__ ol)
{
    __shared__ float sred[32];
    const int row = blockIdx.x;
    const int tid = threadIdx.x;

    float4 a = ((const float4*)(resid + (size_t)row * DD))[tid];
    float4 b = ((const float4*)(y     + (size_t)row * DD))[tid];
    float4 v = make_float4(a.x + b.x, a.y + b.y, a.z + b.z, a.w + b.w);

    float total = blk_sum(v.x + v.y + v.z + v.w, sred);
    float mu = total * (1.f / DD);

    float dx = v.x - mu, dy = v.y - mu, dz = v.z - mu, dw = v.w - mu;
    float tot2 = blk_sum(dx*dx + dy*dy + dz*dz + dw*dw, sred);
    float inv = rsqrtf(tot2 * (1.f / DD) + LN_EPS);

    float4 g = ((const float4*)gamma)[tid];
    float4 be = ((const float4*)beta)[tid];
    float ov[4];
    ov[0] = dx * inv * g.x + be.x;
    ov[1] = dy * inv * g.y + be.y;
    ov[2] = dz * inv * g.z + be.z;
    ov[3] = dw * inv * g.w + be.w;
    ((float4*)(outf + (size_t)row * DD))[tid] = make_float4(ov[0], ov[1], ov[2], ov[3]);

    if (SPLIT) {
        unsigned int wh[2], wl[2];
        #pragma unroll
        for (int q = 0; q < 2; q++) {
            __nv_bfloat16 h0 = __float2bfloat16(ov[2*q]);
            __nv_bfloat16 h1 = __float2bfloat16(ov[2*q+1]);
            __nv_bfloat16 l0 = __float2bfloat16(ov[2*q]   - __bfloat162float(h0));
            __nv_bfloat16 l1 = __float2bfloat16(ov[2*q+1] - __bfloat162float(h1));
            wh[q] = pack_bf16(h0, h1);
            wl[q] = pack_bf16(l0, l1);
        }
        *(uint2*)(oh + (size_t)row * DD + tid * 4) = make_uint2(wh[0], wh[1]);
        *(uint2*)(ol + (size_t)row * DD + tid * 4) = make_uint2(wl[0], wl[1]);
    }
}

// ===================== launch =====================
extern "C" void kernel_launch(void* const* d_in, const int* in_sizes, int n_in,
                              void* d_out, int out_size)
{
    (void)in_sizes; (void)n_in; (void)out_size;

    const float* x     = (const float*)d_in[0];
    const float* Wq    = (const float*)d_in[1];
    const float* Wk    = (const float*)d_in[2];
    const float* Wv    = (const float*)d_in[3];
    const float* Wo    = (const float*)d_in[4];
    const float* g1    = (const float*)d_in[5];
    const float* be1   = (const float*)d_in[6];
    const float* w_in  = (const float*)d_in[7];
    const float* b_in  = (const float*)d_in[8];
    const float* w_out = (const float*)d_in[9];
    const float* b_out = (const float*)d_in[10];
    const float* g2    = (const float*)d_in[11];
    const float* be2   = (const float*)d_in[12];
    float* out = (float*)d_out;

    float *qkv, *tmp, *x1;
    __nv_bfloat16 *xh, *xl, *ah, *al, *x1h, *x1l, *h1h, *h1l;
    __nv_bfloat16 *wqkvh, *wqkvl, *woh, *wol, *winh, *winl, *wouth, *woutl;
    cudaGetSymbolAddress((void**)&qkv,  g_qkv);
    cudaGetSymbolAddress((void**)&tmp,  g_tmp);
    cudaGetSymbolAddress((void**)&x1,   g_x1);
    cudaGetSymbolAddress((void**)&xh,   g_xh);   cudaGetSymbolAddress((void**)&xl,   g_xl);
    cudaGetSymbolAddress((void**)&ah,   g_ah);   cudaGetSymbolAddress((void**)&al,   g_al);
    cudaGetSymbolAddress((void**)&x1h,  g_x1h);  cudaGetSymbolAddress((void**)&x1l,  g_x1l);
    cudaGetSymbolAddress((void**)&h1h,  g_h1h);  cudaGetSymbolAddress((void**)&h1l,  g_h1l);
    cudaGetSymbolAddress((void**)&wqkvh, g_wqkvh); cudaGetSymbolAddress((void**)&wqkvl, g_wqkvl);
    cudaGetSymbolAddress((void**)&woh,   g_woh);   cudaGetSymbolAddress((void**)&wol,   g_wol);
    cudaGetSymbolAddress((void**)&winh,  g_winh);  cudaGetSymbolAddress((void**)&winl,  g_winl);
    cudaGetSymbolAddress((void**)&wouth, g_wouth); cudaGetSymbolAddress((void**)&woutl, g_woutl);

    const size_t fa_smem = FA_SMEM_FLOATS * sizeof(float);
    cudaFuncSetAttribute(flash_attn_kernel, cudaFuncAttributeMaxDynamicSharedMemorySize, (int)fa_smem);
    cudaFuncSetAttribute(gemm_tc_kernel<false,false,true,false>, cudaFuncAttributeMaxDynamicSharedMemorySize, GT_SMEM);
    cudaFuncSetAttribute(gemm_tc_kernel<true,true,false,true>,   cudaFuncAttributeMaxDynamicSharedMemorySize, GT_SMEM);
    cudaFuncSetAttribute(gemm_tc_kernel<true,false,true,false>,  cudaFuncAttributeMaxDynamicSharedMemorySize, GT_SMEM);

    // ---- prep: split x; transpose+split weights ----
    fsplit_kernel<<<MM*DD/1024, 256>>>(x, xh, xl, MM*DD/4);
    qkvT_kernel<<<dim3(2, 32, 48), dim3(32, 8)>>>(Wq, Wk, Wv, wqkvh, wqkvl);
    wsplitT_kernel<<<dim3(32, 32),  dim3(32, 8)>>>(Wo,    woh,   wol,   1024, 1024);
    wsplitT_kernel<<<dim3(128, 32), dim3(32, 8)>>>(w_in,  winh,  winl,  1024, 4096);
    wsplitT_kernel<<<dim3(32, 128), dim3(32, 8)>>>(w_out, wouth, woutl, 4096, 1024);

    // ---- 1) fused QKV projection: [8192,1024] x [1024,3072] ----
    gemm_tc_kernel<false,false,true,false><<<dim3(3072/128, MM/128), 256, GT_SMEM>>>(
        xh, xl, wqkvh, wqkvl, nullptr, qkv, nullptr, nullptr, MM, 3072, 1024);

    // ---- 2) causal flash attention (fp32) ----
    flash_attn_kernel<<<dim3(SS/64, BB*HH), 256, fa_smem>>>();

    // ---- 3) output projection ----
    gemm_tc_kernel<false,false,true,false><<<dim3(1024/128, MM/128), 256, GT_SMEM>>>(
        ah, al, woh, wol, nullptr, tmp, nullptr, nullptr, MM, 1024, 1024);

    // ---- 4) LN1 (x + attn@Wo), also split to bf16 ----
    ln_kernel<true><<<MM, 256>>>(x, tmp, g1, be1, x1, x1h, x1l);

    // ---- 5) FFN up + bias + ReLU, split output ----
    gemm_tc_kernel<true,true,false,true><<<dim3(4096/128, MM/128), 256, GT_SMEM>>>(
        x1h, x1l, winh, winl, b_in, nullptr, h1h, h1l, MM, 4096, 1024);

    // ---- 6) FFN down + bias ----
    gemm_tc_kernel<true,false,true,false><<<dim3(1024/128, MM/128), 256, GT_SMEM>>>(
        h1h, h1l, wouth, woutl, b_out, tmp, nullptr, nullptr, MM, 1024, 4096);

    // ---- 7) LN2 -> output ----
    ln_kernel<false><<<MM, 256>>>(x1, tmp, g2, be2, out, nullptr, nullptr);
}

// round 5
// speedup vs baseline: 2.2891x; 1.2730x over previous
#include <cuda_runtime.h>
#include <cuda_bf16.h>
#include <math.h>

// Problem constants
#define BB   4
#define SS   2048
#define DD   1024
#define HH   16
#define HDIM 64
#define FF   4096
#define MM   (BB*SS)   // 8192 rows
#define LN_EPS 1e-5f

// ===================== low-level helpers =====================
__device__ __forceinline__ unsigned int smem_u32(const void* p) {
    unsigned int a;
    asm("{ .reg .u64 t; cvta.to.shared.u64 t, %1; cvt.u32.u64 %0, t; }" : "=r"(a) : "l"(p));
    return a;
}
__device__ __forceinline__ void cp16(unsigned int s, const void* g) {
    asm volatile("cp.async.cg.shared.global [%0], [%1], 16;" :: "r"(s), "l"(g));
}
#define CP_COMMIT() asm volatile("cp.async.commit_group;" ::: "memory")
#define CP_WAIT1()  asm volatile("cp.async.wait_group 1;" ::: "memory")
#define CP_WAIT0()  asm volatile("cp.async.wait_group 0;" ::: "memory")

__device__ __forceinline__ void ldsm4(unsigned int* r, unsigned int addr) {
    asm volatile("ldmatrix.sync.aligned.m8n8.x4.shared.b16 {%0,%1,%2,%3}, [%4];"
        : "=r"(r[0]), "=r"(r[1]), "=r"(r[2]), "=r"(r[3]) : "r"(addr));
}
__device__ __forceinline__ void ldsm4t(unsigned int* r, unsigned int addr) {
    asm volatile("ldmatrix.sync.aligned.m8n8.x4.trans.shared.b16 {%0,%1,%2,%3}, [%4];"
        : "=r"(r[0]), "=r"(r[1]), "=r"(r[2]), "=r"(r[3]) : "r"(addr));
}
__device__ __forceinline__ void mma_bf16(float* c, const unsigned int* a,
                                         unsigned int b0, unsigned int b1) {
    asm volatile("mma.sync.aligned.m16n8k16.row.col.f32.bf16.bf16.f32 "
        "{%0,%1,%2,%3}, {%4,%5,%6,%7}, {%8,%9}, {%0,%1,%2,%3};"
        : "+f"(c[0]), "+f"(c[1]), "+f"(c[2]), "+f"(c[3])
        : "r"(a[0]), "r"(a[1]), "r"(a[2]), "r"(a[3]), "r"(b0), "r"(b1));
}
__device__ __forceinline__ unsigned int pack_bf16(__nv_bfloat16 a, __nv_bfloat16 b) {
    return (unsigned int)__bfloat16_as_ushort(a) | ((unsigned int)__bfloat16_as_ushort(b) << 16);
}
__device__ __forceinline__ void split2(float v0, float v1, unsigned int& hi, unsigned int& lo) {
    __nv_bfloat16 h0 = __float2bfloat16(v0);
    __nv_bfloat16 h1 = __float2bfloat16(v1);
    __nv_bfloat16 l0 = __float2bfloat16(v0 - __bfloat162float(h0));
    __nv_bfloat16 l1 = __float2bfloat16(v1 - __bfloat162float(h1));
    hi = pack_bf16(h0, h1);
    lo = pack_bf16(l0, l1);
}

// ===================== scratch (device globals) =====================
__device__ __nv_bfloat16 g_qkvh[(size_t)MM*3072], g_qkvl[(size_t)MM*3072];
__device__ __nv_bfloat16 g_xh[(size_t)MM*DD],  g_xl[(size_t)MM*DD];
__device__ __nv_bfloat16 g_ah[(size_t)MM*DD],  g_al[(size_t)MM*DD];
__device__ float g_tmp[(size_t)MM*DD];
__device__ float g_x1[(size_t)MM*DD];
__device__ __nv_bfloat16 g_x1h[(size_t)MM*DD], g_x1l[(size_t)MM*DD];
__device__ __nv_bfloat16 g_h1h[(size_t)MM*FF], g_h1l[(size_t)MM*FF];
// transposed + split weights ([N,K] row-major bf16)
__device__ __nv_bfloat16 g_wqkvh[(size_t)3072*1024], g_wqkvl[(size_t)3072*1024];
__device__ __nv_bfloat16 g_woh[(size_t)1024*1024],   g_wol[(size_t)1024*1024];
__device__ __nv_bfloat16 g_winh[(size_t)4096*1024],  g_winl[(size_t)4096*1024];
__device__ __nv_bfloat16 g_wouth[(size_t)1024*4096], g_woutl[(size_t)1024*4096];

// ===================== prep kernels =====================
__global__ void fsplit_kernel(const float* __restrict__ in,
                              __nv_bfloat16* __restrict__ h,
                              __nv_bfloat16* __restrict__ l, int n4)
{
    int i = blockIdx.x * blockDim.x + threadIdx.x;
    if (i >= n4) return;
    float4 v = ((const float4*)in)[i];
    unsigned int ph[2], pl[2];
    split2(v.x, v.y, ph[0], pl[0]);
    split2(v.z, v.w, ph[1], pl[1]);
    ((uint2*)h)[i] = make_uint2(ph[0], ph[1]);
    ((uint2*)l)[i] = make_uint2(pl[0], pl[1]);
}

__global__ void wsplitT_kernel(const float* __restrict__ W,
                               __nv_bfloat16* __restrict__ Th,
                               __nv_bfloat16* __restrict__ Tl, int K, int N)
{
    __shared__ float t[32][33];
    int k0 = blockIdx.y * 32, n0 = blockIdx.x * 32;
    int tx = threadIdx.x, ty = threadIdx.y;
    #pragma unroll
    for (int i = 0; i < 32; i += 8)
        t[ty + i][tx] = W[(size_t)(k0 + ty + i) * N + n0 + tx];
    __syncthreads();
    #pragma unroll
    for (int i = 0; i < 32; i += 8) {
        float v = t[tx][ty + i];
        __nv_bfloat16 h = __float2bfloat16(v);
        size_t o = (size_t)(n0 + ty + i) * K + k0 + tx;
        Th[o] = h;
        Tl[o] = __float2bfloat16(v - __bfloat162float(h));
    }
}

__global__ void qkvT_kernel(const float* __restrict__ Wq,
                            const float* __restrict__ Wk,
                            const float* __restrict__ Wv,
                            __nv_bfloat16* __restrict__ Th,
                            __nv_bfloat16* __restrict__ Tl)
{
    __shared__ float t[32][33];
    int z = blockIdx.z;
    int mat = z / HH, h = z - mat * HH;
    const float* W = (mat == 0 ? Wq : mat == 1 ? Wk : Wv) + (size_t)h * DD * HDIM;
    int k0 = blockIdx.y * 32, e0 = blockIdx.x * 32;
    int tx = threadIdx.x, ty = threadIdx.y;
    #pragma unroll
    for (int i = 0; i < 32; i += 8)
        t[ty + i][tx] = W[(size_t)(k0 + ty + i) * HDIM + e0 + tx];
    __syncthreads();
    int nbase = mat * 1024 + h * HDIM;
    #pragma unroll
    for (int i = 0; i < 32; i += 8) {
        float v = t[tx][ty + i];
        __nv_bfloat16 hv = __float2bfloat16(v);
        size_t o = (size_t)(nbase + e0 + ty + i) * DD + k0 + tx;
        Th[o] = hv;
        Tl[o] = __float2bfloat16(v - __bfloat162float(hv));
    }
}

// ===================== mma.sync bf16x3 GEMM =====================
// Block 128x128, K-chunk 32, 3-stage cp.async pipeline, 8 warps (2x4), warp 64x32.
#define GPITCH 80
#define MAT_B  (128*GPITCH)     // 10240
#define STG_B  (4*MAT_B)        // 40960
#define NSTG   3
#define GT_SMEM (NSTG*STG_B)    // 122880

template<bool BIAS, bool RELU, bool F32OUT, bool SPLIT>
__global__ void __launch_bounds__(256, 1) gemm_tc_kernel(
    const __nv_bfloat16* __restrict__ Ah, const __nv_bfloat16* __restrict__ Al,
    const __nv_bfloat16* __restrict__ BTh, const __nv_bfloat16* __restrict__ BTl,
    const float* __restrict__ bias,
    float* __restrict__ C,
    __nv_bfloat16* __restrict__ Ch, __nv_bfloat16* __restrict__ Cl,
    int M, int N, int K)
{
    extern __shared__ __align__(16) char smem[];
    const unsigned int sb = smem_u32(smem);
    const int tid = threadIdx.x;
    const int row0 = blockIdx.y * 128;
    const int col0 = blockIdx.x * 128;

    const int wid = tid >> 5, lane = tid & 31;
    const int wm0 = (wid & 1) * 64, wn0 = (wid >> 1) * 32;
    const int lr = lane & 15, lh = lane >> 4;

    auto load_stage = [&](int c, int s) {
        unsigned int base = sb + s * STG_B;
        int k0 = c * 32;
        #pragma unroll
        for (int i = 0; i < 2; i++) {
            int lin = tid + (i << 8);          // 0..511
            int r = lin >> 2, ck = lin & 3;
            unsigned int so = r * GPITCH + ck * 16;
            size_t ga = (size_t)(row0 + r) * K + k0 + ck * 8;
            size_t gb = (size_t)(col0 + r) * K + k0 + ck * 8;
            cp16(base + so,             Ah  + ga);
            cp16(base + MAT_B + so,     Al  + ga);
            cp16(base + 2*MAT_B + so,   BTh + gb);
            cp16(base + 3*MAT_B + so,   BTl + gb);
        }
        CP_COMMIT();
    };

    float acc[4][4][4] = {};

    load_stage(0, 0);
    load_stage(1, 1);

    const int NC = K >> 5;
    for (int c = 0; c < NC; c++) {
        CP_WAIT1();
        __syncthreads();
        if (c + 2 < NC) load_stage(c + 2, (c + 2) % NSTG);

        unsigned int base = sb + (c % NSTG) * STG_B;
        #pragma unroll
        for (int ks = 0; ks < 2; ks++) {
            unsigned int a_h[4][4], a_l[4][4], b_h[2][4], b_l[2][4];
            #pragma unroll
            for (int mt = 0; mt < 4; mt++) {
                unsigned int ro = (unsigned int)(wm0 + mt*16 + lr) * GPITCH + (ks*2 + lh) * 16;
                ldsm4(a_h[mt], base + ro);
                ldsm4(a_l[mt], base + MAT_B + ro);
            }
            #pragma unroll
            for (int bt = 0; bt < 2; bt++) {
                unsigned int ro = (unsigned int)(wn0 + bt*16 + lr) * GPITCH + (ks*2 + lh) * 16;
                ldsm4(b_h[bt], base + 2*MAT_B + ro);
                ldsm4(b_l[bt], base + 3*MAT_B + ro);
            }
            #pragma unroll
            for (int mt = 0; mt < 4; mt++) {
                #pragma unroll
                for (int nt = 0; nt < 4; nt++) {
                    int bt = nt >> 1, hf = nt & 1;
                    mma_bf16(acc[mt][nt], a_h[mt], b_h[bt][hf], b_h[bt][hf+2]);
                    mma_bf16(acc[mt][nt], a_l[mt], b_h[bt][hf], b_h[bt][hf+2]);
                    mma_bf16(acc[mt][nt], a_h[mt], b_l[bt][hf], b_l[bt][hf+2]);
                }
            }
        }
    }

    // ---- epilogue (register fragments -> gmem) ----
    const int gq = lane >> 2, pq = lane & 3;
    #pragma unroll
    for (int mt = 0; mt < 4; mt++) {
        #pragma unroll
        for (int nt = 0; nt < 4; nt++) {
            int col = col0 + wn0 + nt*8 + pq*2;
            float b0 = 0.f, b1 = 0.f;
            if (BIAS) { b0 = bias[col]; b1 = bias[col+1]; }
            #pragma unroll
            for (int h2 = 0; h2 < 2; h2++) {
                int row = row0 + wm0 + mt*16 + gq + h2*8;
                float v0 = acc[mt][nt][h2*2+0] + b0;
                float v1 = acc[mt][nt][h2*2+1] + b1;
                if (RELU) { v0 = fmaxf(v0, 0.f); v1 = fmaxf(v1, 0.f); }
                if (F32OUT)
                    *(float2*)(C + (size_t)row * N + col) = make_float2(v0, v1);
                if (SPLIT) {
                    unsigned int hi, lo;
                    split2(v0, v1, hi, lo);
                    *(unsigned int*)(Ch + (size_t)row * N + col) = hi;
                    *(unsigned int*)(Cl + (size_t)row * N + col) = lo;
                }
            }
        }
    }
}

// ===================== tensor-core causal flash attention (bf16x3) ============
// CTA: 64 q-rows, 4 warps (16 rows each), K/V tiles 64x64, double-buffered.
// smem: Qh,Ql [64][72] bf16 (pitch 144B), stages: Kh,Kl,Vh,Vl same pitch.
#define AP 144
#define AMAT 9216              // 64*144
#define FA_Q (2*AMAT)          // 18432
#define FA_STG (4*AMAT)        // 36864
#define FA_SMEM (FA_Q + 2*FA_STG)   // 92160

__global__ void __launch_bounds__(128, 1) flash_tc_kernel()
{
    const int qt = blockIdx.x, bh = blockIdx.y;
    const int b = bh >> 4, h = bh & 15;
    const int tid = threadIdx.x, wid = tid >> 5, lane = tid & 31;
    const int wm = wid * 16;
    const int lr = lane & 15, lh = lane >> 4;

    extern __shared__ __align__(16) char smem[];
    const unsigned int sb = smem_u32(smem);
    const unsigned int sQh = sb, sQl = sb + AMAT;

    // ---- load Q (hi/lo) ----
    {
        const __nv_bfloat16* qh = g_qkvh + (size_t)(b*SS + qt*64)*3072 + h*HDIM;
        const __nv_bfloat16* ql = g_qkvl + (size_t)(b*SS + qt*64)*3072 + h*HDIM;
        #pragma unroll
        for (int i = 0; i < 4; i++) {
            int lin = tid + (i << 7);
            int r = lin >> 3, ck = lin & 7;
            unsigned int so = r*AP + ck*16;
            size_t g = (size_t)r*3072 + ck*8;
            cp16(sQh + so, qh + g);
            cp16(sQl + so, ql + g);
        }
        CP_COMMIT();
    }

    auto load_kv = [&](int kt, int s) {
        unsigned int base = sb + FA_Q + s * FA_STG;
        size_t rowb = (size_t)(b*SS + kt*64)*3072;
        const __nv_bfloat16* kh = g_qkvh + rowb + 1024 + h*HDIM;
        const __nv_bfloat16* kl = g_qkvl + rowb + 1024 + h*HDIM;
        const __nv_bfloat16* vh = g_qkvh + rowb + 2048 + h*HDIM;
        const __nv_bfloat16* vl = g_qkvl + rowb + 2048 + h*HDIM;
        #pragma unroll
        for (int i = 0; i < 4; i++) {
            int lin = tid + (i << 7);
            int r = lin >> 3, ck = lin & 7;
            unsigned int so = r*AP + ck*16;
            size_t g = (size_t)r*3072 + ck*8;
            cp16(base + so,          kh + g);
            cp16(base + AMAT + so,   kl + g);
            cp16(base + 2*AMAT + so, vh + g);
            cp16(base + 3*AMAT + so, vl + g);
        }
        CP_COMMIT();
    };

    load_kv(0, 0);
    if (qt >= 1) load_kv(1, 1);

    float o[8][4] = {};
    float m0 = -1e30f, m1 = -1e30f, l0 = 0.f, l1 = 0.f;

    for (int kt = 0; kt <= qt; kt++) {
        if (kt < qt) CP_WAIT1(); else CP_WAIT0();
        __syncthreads();

        const unsigned int kb = sb + FA_Q + (kt & 1) * FA_STG;

        // ---- S = Q K^T (bf16x3) ----
        float sc[8][4] = {};
        #pragma unroll
        for (int kd = 0; kd < 4; kd++) {
            unsigned int aqh[4], aql[4];
            unsigned int qro = (unsigned int)(wm + lr)*AP + (kd*2 + lh)*16;
            ldsm4(aqh, sQh + qro);
            ldsm4(aql, sQl + qro);
            #pragma unroll
            for (int g = 0; g < 4; g++) {
                unsigned int rkh[4], rkl[4];
                unsigned int kro = (unsigned int)(g*16 + lr)*AP + (kd*2 + lh)*16;
                ldsm4(rkh, kb + kro);
                ldsm4(rkl, kb + AMAT + kro);
                mma_bf16(sc[2*g],   aqh, rkh[0], rkh[2]);
                mma_bf16(sc[2*g+1], aqh, rkh[1], rkh[3]);
                mma_bf16(sc[2*g],   aqh, rkl[0], rkl[2]);
                mma_bf16(sc[2*g+1], aqh, rkl[1], rkl[3]);
                mma_bf16(sc[2*g],   aql, rkh[0], rkh[2]);
                mma_bf16(sc[2*g+1], aql, rkh[1], rkh[3]);
            }
        }

        // ---- scale + causal mask ----
        const int lrow0 = wm + (lane >> 2), lrow1 = lrow0 + 8;
        if (kt == qt) {
            #pragma unroll
            for (int nt = 0; nt < 8; nt++) {
                int c0l = nt*8 + (lane & 3)*2;
                sc[nt][0] = (c0l     > lrow0) ? -1e30f : sc[nt][0]*0.125f;
                sc[nt][1] = (c0l + 1 > lrow0) ? -1e30f : sc[nt][1]*0.125f;
                sc[nt][2] = (c0l     > lrow1) ? -1e30f : sc[nt][2]*0.125f;
                sc[nt][3] = (c0l + 1 > lrow1) ? -1e30f : sc[nt][3]*0.125f;
            }
        } else {
            #pragma unroll
            for (int nt = 0; nt < 8; nt++) {
                sc[nt][0] *= 0.125f; sc[nt][1] *= 0.125f;
                sc[nt][2] *= 0.125f; sc[nt][3] *= 0.125f;
            }
        }

        // ---- online softmax (register state, 4-lane reductions) ----
        float mx0 = -1e30f, mx1 = -1e30f;
        #pragma unroll
        for (int nt = 0; nt < 8; nt++) {
            mx0 = fmaxf(mx0, fmaxf(sc[nt][0], sc[nt][1]));
            mx1 = fmaxf(mx1, fmaxf(sc[nt][2], sc[nt][3]));
        }
        mx0 = fmaxf(mx0, __shfl_xor_sync(0xffffffffu, mx0, 1));
        mx0 = fmaxf(mx0, __shfl_xor_sync(0xffffffffu, mx0, 2));
        mx1 = fmaxf(mx1, __shfl_xor_sync(0xffffffffu, mx1, 1));
        mx1 = fmaxf(mx1, __shfl_xor_sync(0xffffffffu, mx1, 2));
        float mn0 = fmaxf(m0, mx0), mn1 = fmaxf(m1, mx1);
        float cf0 = __expf(m0 - mn0), cf1 = __expf(m1 - mn1);
        m0 = mn0; m1 = mn1;
        float s0 = 0.f, s1 = 0.f;
        #pragma unroll
        for (int nt = 0; nt < 8; nt++) {
            sc[nt][0] = __expf(sc[nt][0] - mn0);
            sc[nt][1] = __expf(sc[nt][1] - mn0);
            sc[nt][2] = __expf(sc[nt][2] - mn1);
            sc[nt][3] = __expf(sc[nt][3] - mn1);
            s0 += sc[nt][0] + sc[nt][1];
            s1 += sc[nt][2] + sc[nt][3];
        }
        s0 += __shfl_xor_sync(0xffffffffu, s0, 1);
        s0 += __shfl_xor_sync(0xffffffffu, s0, 2);
        s1 += __shfl_xor_sync(0xffffffffu, s1, 1);
        s1 += __shfl_xor_sync(0xffffffffu, s1, 2);
        l0 = l0 * cf0 + s0;
        l1 = l1 * cf1 + s1;
        #pragma unroll
        for (int dt = 0; dt < 8; dt++) {
            o[dt][0] *= cf0; o[dt][1] *= cf0;
            o[dt][2] *= cf1; o[dt][3] *= cf1;
        }

        // ---- O += P V (bf16x3, P fragments from registers) ----
        #pragma unroll
        for (int j = 0; j < 4; j++) {
            unsigned int ph[4], pl[4];
            split2(sc[2*j][0],   sc[2*j][1],   ph[0], pl[0]);
            split2(sc[2*j][2],   sc[2*j][3],   ph[1], pl[1]);
            split2(sc[2*j+1][0], sc[2*j+1][1], ph[2], pl[2]);
            split2(sc[2*j+1][2], sc[2*j+1][3], ph[3], pl[3]);
            #pragma unroll
            for (int g = 0; g < 4; g++) {
                unsigned int rvh[4], rvl[4];
                unsigned int vro = (unsigned int)(j*16 + lr)*AP + (g*2 + lh)*16;
                ldsm4t(rvh, kb + 2*AMAT + vro);
                ldsm4t(rvl, kb + 3*AMAT + vro);
                mma_bf16(o[2*g],   ph, rvh[0], rvh[1]);
                mma_bf16(o[2*g+1], ph, rvh[2], rvh[3]);
                mma_bf16(o[2*g],   ph, rvl[0], rvl[1]);
                mma_bf16(o[2*g+1], ph, rvl[2], rvl[3]);
                mma_bf16(o[2*g],   pl, rvh[0], rvh[1]);
                mma_bf16(o[2*g+1], pl, rvh[2], rvh[3]);
            }
        }

        __syncthreads();
        if (kt + 2 <= qt) load_kv(kt + 2, kt & 1);
    }

    // ---- epilogue: normalize, split to bf16 hi/lo, natural (bh,s,e) order ----
    const float inv0 = 1.f / l0, inv1 = 1.f / l1;
    const int row0g = qt*64 + wm + (lane >> 2);
    __nv_bfloat16* ohp = g_ah + ((size_t)bh*SS)*HDIM;
    __nv_bfloat16* olp = g_al + ((size_t)bh*SS)*HDIM;
    #pragma unroll
    for (int dt = 0; dt < 8; dt++) {
        int d = dt*8 + (lane & 3)*2;
        unsigned int hi, lo;
        split2(o[dt][0]*inv0, o[dt][1]*inv0, hi, lo);
        *(unsigned int*)(ohp + (size_t)row0g*HDIM + d) = hi;
        *(unsigned int*)(olp + (size_t)row0g*HDIM + d) = lo;
        split2(o[dt][2]*inv1, o[dt][3]*inv1, hi, lo);
        *(unsigned int*)(ohp + (size_t)(row0g+8)*HDIM + d) = hi;
        *(unsigned int*)(olp + (size_t)(row0g+8)*HDIM + d) = lo;
    }
}

// ===================== LayerNorm =====================
__device__ __forceinline__ float blk_sum(float v, float* sred)
{
    #pragma unroll
    for (int o = 16; o; o >>= 1) v += __shfl_xor_sync(0xffffffffu, v, o);
    int w = threadIdx.x >> 5;
    if ((threadIdx.x & 31) == 0) sred[w] = v;
    __syncthreads();
    float t = (threadIdx.x < 8) ? sred[threadIdx.x] : 0.f;
    if (threadIdx.x < 32) {
        #pragma unroll
        for (int o = 4; o; o >>= 1) t += __shfl_xor_sync(0xffffffffu, t, o);
        if (threadIdx.x == 0) sred[0] = t;
    }
    __syncthreads();
    float r = sred[0];
    __syncthreads();
    return r;
}

template<bool SPLIT>
__global__ void ln_kernel(const float* __restrict__ resid,
                          const float* __restrict__ y,
                          const float* __restrict__ gamma,
                          const float* __restrict__ beta,
                          float* __restrict__ outf,
                          __nv_bfloat16* __restrict__ oh,
                          __nv_bfloat16* __restrict__ ol)
{
    __shared__ float sred[32];
    const int row = blockIdx.x;
    const int tid = threadIdx.x;

    float4 a = ((const float4*)(resid + (size_t)row * DD))[tid];
    float4 b = ((const float4*)(y     + (size_t)row * DD))[tid];
    float4 v = make_float4(a.x + b.x, a.y + b.y, a.z + b.z, a.w + b.w);

    float total = blk_sum(v.x + v.y + v.z + v.w, sred);
    float mu = total * (1.f / DD);

    float dx = v.x - mu, dy = v.y - mu, dz = v.z - mu, dw = v.w - mu;
    float tot2 = blk_sum(dx*dx + dy*dy + dz*dz + dw*dw, sred);
    float inv = rsqrtf(tot2 * (1.f / DD) + LN_EPS);

    float4 g = ((const float4*)gamma)[tid];
    float4 be = ((const float4*)beta)[tid];
    float ov[4];
    ov[0] = dx * inv * g.x + be.x;
    ov[1] = dy * inv * g.y + be.y;
    ov[2] = dz * inv * g.z + be.z;
    ov[3] = dw * inv * g.w + be.w;
    ((float4*)(outf + (size_t)row * DD))[tid] = make_float4(ov[0], ov[1], ov[2], ov[3]);

    if (SPLIT) {
        unsigned int wh[2], wl[2];
        split2(ov[0], ov[1], wh[0], wl[0]);
        split2(ov[2], ov[3], wh[1], wl[1]);
        *(uint2*)(oh + (size_t)row * DD + tid * 4) = make_uint2(wh[0], wh[1]);
        *(uint2*)(ol + (size_t)row * DD + tid * 4) = make_uint2(wl[0], wl[1]);
    }
}

// ===================== launch =====================
extern "C" void kernel_launch(void* const* d_in, const int* in_sizes, int n_in,
                              void* d_out, int out_size)
{
    (void)in_sizes; (void)n_in; (void)out_size;

    const float* x     = (const float*)d_in[0];
    const float* Wq    = (const float*)d_in[1];
    const float* Wk    = (const float*)d_in[2];
    const float* Wv    = (const float*)d_in[3];
    const float* Wo    = (const float*)d_in[4];
    const float* g1    = (const float*)d_in[5];
    const float* be1   = (const float*)d_in[6];
    const float* w_in  = (const float*)d_in[7];
    const float* b_in  = (const float*)d_in[8];
    const float* w_out = (const float*)d_in[9];
    const float* b_out = (const float*)d_in[10];
    const float* g2    = (const float*)d_in[11];
    const float* be2   = (const float*)d_in[12];
    float* out = (float*)d_out;

    float *tmp, *x1;
    __nv_bfloat16 *qkvh, *qkvl, *xh, *xl, *ah, *al, *x1h, *x1l, *h1h, *h1l;
    __nv_bfloat16 *wqkvh, *wqkvl, *woh, *wol, *winh, *winl, *wouth, *woutl;
    cudaGetSymbolAddress((void**)&tmp,  g_tmp);
    cudaGetSymbolAddress((void**)&x1,   g_x1);
    cudaGetSymbolAddress((void**)&qkvh, g_qkvh);  cudaGetSymbolAddress((void**)&qkvl, g_qkvl);
    cudaGetSymbolAddress((void**)&xh,   g_xh);    cudaGetSymbolAddress((void**)&xl,   g_xl);
    cudaGetSymbolAddress((void**)&ah,   g_ah);    cudaGetSymbolAddress((void**)&al,   g_al);
    cudaGetSymbolAddress((void**)&x1h,  g_x1h);   cudaGetSymbolAddress((void**)&x1l,  g_x1l);
    cudaGetSymbolAddress((void**)&h1h,  g_h1h);   cudaGetSymbolAddress((void**)&h1l,  g_h1l);
    cudaGetSymbolAddress((void**)&wqkvh, g_wqkvh); cudaGetSymbolAddress((void**)&wqkvl, g_wqkvl);
    cudaGetSymbolAddress((void**)&woh,   g_woh);   cudaGetSymbolAddress((void**)&wol,   g_wol);
    cudaGetSymbolAddress((void**)&winh,  g_winh);  cudaGetSymbolAddress((void**)&winl,  g_winl);
    cudaGetSymbolAddress((void**)&wouth, g_wouth); cudaGetSymbolAddress((void**)&woutl, g_woutl);

    cudaFuncSetAttribute(flash_tc_kernel, cudaFuncAttributeMaxDynamicSharedMemorySize, FA_SMEM);
    cudaFuncSetAttribute(gemm_tc_kernel<false,false,false,true>, cudaFuncAttributeMaxDynamicSharedMemorySize, GT_SMEM);
    cudaFuncSetAttribute(gemm_tc_kernel<false,false,true,false>, cudaFuncAttributeMaxDynamicSharedMemorySize, GT_SMEM);
    cudaFuncSetAttribute(gemm_tc_kernel<true,true,false,true>,   cudaFuncAttributeMaxDynamicSharedMemorySize, GT_SMEM);
    cudaFuncSetAttribute(gemm_tc_kernel<true,false,true,false>,  cudaFuncAttributeMaxDynamicSharedMemorySize, GT_SMEM);

    // ---- prep: split x; transpose+split weights ----
    fsplit_kernel<<<MM*DD/1024, 256>>>(x, xh, xl, MM*DD/4);
    qkvT_kernel<<<dim3(2, 32, 48), dim3(32, 8)>>>(Wq, Wk, Wv, wqkvh, wqkvl);
    wsplitT_kernel<<<dim3(32, 32),  dim3(32, 8)>>>(Wo,    woh,   wol,   1024, 1024);
    wsplitT_kernel<<<dim3(128, 32), dim3(32, 8)>>>(w_in,  winh,  winl,  1024, 4096);
    wsplitT_kernel<<<dim3(32, 128), dim3(32, 8)>>>(w_out, wouth, woutl, 4096, 1024);

    // ---- 1) fused QKV projection -> split bf16 hi/lo directly ----
    gemm_tc_kernel<false,false,false,true><<<dim3(3072/128, MM/128), 256, GT_SMEM>>>(
        xh, xl, wqkvh, wqkvl, nullptr, nullptr, qkvh, qkvl, MM, 3072, 1024);

    // ---- 2) causal flash attention (tensor cores, bf16x3) ----
    flash_tc_kernel<<<dim3(SS/64, BB*HH), 128, FA_SMEM>>>();

    // ---- 3) output projection ----
    gemm_tc_kernel<false,false,true,false><<<dim3(1024/128, MM/128), 256, GT_SMEM>>>(
        ah, al, woh, wol, nullptr, tmp, nullptr, nullptr, MM, 1024, 1024);

    // ---- 4) LN1 (x + attn@Wo), also split to bf16 ----
    ln_kernel<true><<<MM, 256>>>(x, tmp, g1, be1, x1, x1h, x1l);

    // ---- 5) FFN up + bias + ReLU, split output ----
    gemm_tc_kernel<true,true,false,true><<<dim3(4096/128, MM/128), 256, GT_SMEM>>>(
        x1h, x1l, winh, winl, b_in, nullptr, h1h, h1l, MM, 4096, 1024);

    // ---- 6) FFN down + bias ----
    gemm_tc_kernel<true,false,true,false><<<dim3(1024/128, MM/128), 256, GT_SMEM>>>(
        h1h, h1l, wouth, woutl, b_out, tmp, nullptr, nullptr, MM, 1024, 4096);

    // ---- 7) LN2 -> output ----
    ln_kernel<false><<<MM, 256>>>(x1, tmp, g2, be2, out, nullptr, nullptr);
}

// round 6
// speedup vs baseline: 2.4057x; 1.0509x over previous
#include <cuda_runtime.h>
#include <cuda_bf16.h>
#include <math.h>

// Problem constants
#define BB   4
#define SS   2048
#define DD   1024
#define HH   16
#define HDIM 64
#define FF   4096
#define MM   (BB*SS)   // 8192 rows
#define LN_EPS 1e-5f

// ===================== low-level helpers =====================
__device__ __forceinline__ unsigned int smem_u32(const void* p) {
    unsigned int a;
    asm("{ .reg .u64 t; cvta.to.shared.u64 t, %1; cvt.u32.u64 %0, t; }" : "=r"(a) : "l"(p));
    return a;
}
__device__ __forceinline__ void cp16(unsigned int s, const void* g) {
    asm volatile("cp.async.cg.shared.global [%0], [%1], 16;" :: "r"(s), "l"(g));
}
#define CP_COMMIT() asm volatile("cp.async.commit_group;" ::: "memory")
#define CP_WAIT1()  asm volatile("cp.async.wait_group 1;" ::: "memory")
#define CP_WAIT0()  asm volatile("cp.async.wait_group 0;" ::: "memory")

__device__ __forceinline__ void ldsm4(unsigned int* r, unsigned int addr) {
    asm volatile("ldmatrix.sync.aligned.m8n8.x4.shared.b16 {%0,%1,%2,%3}, [%4];"
        : "=r"(r[0]), "=r"(r[1]), "=r"(r[2]), "=r"(r[3]) : "r"(addr));
}
__device__ __forceinline__ void ldsm4t(unsigned int* r, unsigned int addr) {
    asm volatile("ldmatrix.sync.aligned.m8n8.x4.trans.shared.b16 {%0,%1,%2,%3}, [%4];"
        : "=r"(r[0]), "=r"(r[1]), "=r"(r[2]), "=r"(r[3]) : "r"(addr));
}
__device__ __forceinline__ void mma_bf16(float* c, const unsigned int* a,
                                         unsigned int b0, unsigned int b1) {
    asm volatile("mma.sync.aligned.m16n8k16.row.col.f32.bf16.bf16.f32 "
        "{%0,%1,%2,%3}, {%4,%5,%6,%7}, {%8,%9}, {%0,%1,%2,%3};"
        : "+f"(c[0]), "+f"(c[1]), "+f"(c[2]), "+f"(c[3])
        : "r"(a[0]), "r"(a[1]), "r"(a[2]), "r"(a[3]), "r"(b0), "r"(b1));
}
__device__ __forceinline__ unsigned int pack_bf16(__nv_bfloat16 a, __nv_bfloat16 b) {
    return (unsigned int)__bfloat16_as_ushort(a) | ((unsigned int)__bfloat16_as_ushort(b) << 16);
}
__device__ __forceinline__ void split2(float v0, float v1, unsigned int& hi, unsigned int& lo) {
    __nv_bfloat16 h0 = __float2bfloat16(v0);
    __nv_bfloat16 h1 = __float2bfloat16(v1);
    __nv_bfloat16 l0 = __float2bfloat16(v0 - __bfloat162float(h0));
    __nv_bfloat16 l1 = __float2bfloat16(v1 - __bfloat162float(h1));
    hi = pack_bf16(h0, h1);
    lo = pack_bf16(l0, l1);
}

// ===================== scratch (device globals) =====================
__device__ __nv_bfloat16 g_qkvh[(size_t)MM*3072], g_qkvl[(size_t)MM*3072];
__device__ __nv_bfloat16 g_xh[(size_t)MM*DD],  g_xl[(size_t)MM*DD];
__device__ __nv_bfloat16 g_ah[(size_t)MM*DD],  g_al[(size_t)MM*DD];
__device__ float g_tmp[(size_t)MM*DD];
__device__ float g_x1[(size_t)MM*DD];
__device__ __nv_bfloat16 g_x1h[(size_t)MM*DD], g_x1l[(size_t)MM*DD];
__device__ __nv_bfloat16 g_h1h[(size_t)MM*FF], g_h1l[(size_t)MM*FF];
// transposed + split weights ([N,K] row-major bf16)
__device__ __nv_bfloat16 g_wqkvh[(size_t)3072*1024], g_wqkvl[(size_t)3072*1024];
__device__ __nv_bfloat16 g_woh[(size_t)1024*1024],   g_wol[(size_t)1024*1024];
__device__ __nv_bfloat16 g_winh[(size_t)4096*1024],  g_winl[(size_t)4096*1024];
__device__ __nv_bfloat16 g_wouth[(size_t)1024*4096], g_woutl[(size_t)1024*4096];

// ===================== prep kernels =====================
__global__ void fsplit_kernel(const float* __restrict__ in,
                              __nv_bfloat16* __restrict__ h,
                              __nv_bfloat16* __restrict__ l, int n4)
{
    int i = blockIdx.x * blockDim.x + threadIdx.x;
    if (i >= n4) return;
    float4 v = ((const float4*)in)[i];
    unsigned int ph[2], pl[2];
    split2(v.x, v.y, ph[0], pl[0]);
    split2(v.z, v.w, ph[1], pl[1]);
    ((uint2*)h)[i] = make_uint2(ph[0], ph[1]);
    ((uint2*)l)[i] = make_uint2(pl[0], pl[1]);
}

__global__ void wsplitT_kernel(const float* __restrict__ W,
                               __nv_bfloat16* __restrict__ Th,
                               __nv_bfloat16* __restrict__ Tl, int K, int N)
{
    __shared__ float t[32][33];
    int k0 = blockIdx.y * 32, n0 = blockIdx.x * 32;
    int tx = threadIdx.x, ty = threadIdx.y;
    #pragma unroll
    for (int i = 0; i < 32; i += 8)
        t[ty + i][tx] = W[(size_t)(k0 + ty + i) * N + n0 + tx];
    __syncthreads();
    #pragma unroll
    for (int i = 0; i < 32; i += 8) {
        float v = t[tx][ty + i];
        __nv_bfloat16 h = __float2bfloat16(v);
        size_t o = (size_t)(n0 + ty + i) * K + k0 + tx;
        Th[o] = h;
        Tl[o] = __float2bfloat16(v - __bfloat162float(h));
    }
}

__global__ void qkvT_kernel(const float* __restrict__ Wq,
                            const float* __restrict__ Wk,
                            const float* __restrict__ Wv,
                            __nv_bfloat16* __restrict__ Th,
                            __nv_bfloat16* __restrict__ Tl)
{
    __shared__ float t[32][33];
    int z = blockIdx.z;
    int mat = z / HH, h = z - mat * HH;
    const float* W = (mat == 0 ? Wq : mat == 1 ? Wk : Wv) + (size_t)h * DD * HDIM;
    int k0 = blockIdx.y * 32, e0 = blockIdx.x * 32;
    int tx = threadIdx.x, ty = threadIdx.y;
    #pragma unroll
    for (int i = 0; i < 32; i += 8)
        t[ty + i][tx] = W[(size_t)(k0 + ty + i) * HDIM + e0 + tx];
    __syncthreads();
    int nbase = mat * 1024 + h * HDIM;
    #pragma unroll
    for (int i = 0; i < 32; i += 8) {
        float v = t[tx][ty + i];
        __nv_bfloat16 hv = __float2bfloat16(v);
        size_t o = (size_t)(nbase + e0 + ty + i) * DD + k0 + tx;
        Th[o] = hv;
        Tl[o] = __float2bfloat16(v - __bfloat162float(hv));
    }
}

// ===================== mma.sync bf16x3 GEMM =====================
// Block 128x256, K-chunk 32, 3-stage cp.async pipeline, 8 warps (2x4), warp 64x64.
#define GPITCH 80
#define AMAT_G (128*GPITCH)      // 10240
#define BMAT_G (256*GPITCH)      // 20480
#define OFF_AH 0
#define OFF_AL AMAT_G
#define OFF_BH (2*AMAT_G)
#define OFF_BL (2*AMAT_G + BMAT_G)
#define STG_B  (2*AMAT_G + 2*BMAT_G)   // 61440
#define NSTG   3
#define GT_SMEM (NSTG*STG_B)           // 184320

template<bool BIAS, bool RELU, bool F32OUT, bool SPLIT>
__global__ void __launch_bounds__(256, 1) gemm_tc_kernel(
    const __nv_bfloat16* __restrict__ Ah, const __nv_bfloat16* __restrict__ Al,
    const __nv_bfloat16* __restrict__ BTh, const __nv_bfloat16* __restrict__ BTl,
    const float* __restrict__ bias,
    float* __restrict__ C,
    __nv_bfloat16* __restrict__ Ch, __nv_bfloat16* __restrict__ Cl,
    int M, int N, int K)
{
    extern __shared__ __align__(16) char smem[];
    const unsigned int sb = smem_u32(smem);
    const int tid = threadIdx.x;
    const int row0 = blockIdx.y * 128;
    const int col0 = blockIdx.x * 256;

    const int wid = tid >> 5, lane = tid & 31;
    const int wm0 = (wid & 1) * 64, wn0 = (wid >> 1) * 64;
    const int lr = lane & 15, lh = lane >> 4;

    auto load_stage = [&](int c, int s) {
        unsigned int base = sb + s * STG_B;
        int k0 = c * 32;
        #pragma unroll
        for (int i = 0; i < 2; i++) {
            int lin = tid + (i << 8);          // 0..511
            int r = lin >> 2, ck = lin & 3;
            unsigned int so = r * GPITCH + ck * 16;
            size_t ga = (size_t)(row0 + r) * K + k0 + ck * 8;
            cp16(base + OFF_AH + so, Ah + ga);
            cp16(base + OFF_AL + so, Al + ga);
        }
        #pragma unroll
        for (int i = 0; i < 4; i++) {
            int lin = tid + (i << 8);          // 0..1023
            int r = lin >> 2, ck = lin & 3;
            unsigned int so = r * GPITCH + ck * 16;
            size_t gb = (size_t)(col0 + r) * K + k0 + ck * 8;
            cp16(base + OFF_BH + so, BTh + gb);
            cp16(base + OFF_BL + so, BTl + gb);
        }
        CP_COMMIT();
    };

    float acc[4][8][4] = {};

    load_stage(0, 0);
    load_stage(1, 1);

    const int NC = K >> 5;
    for (int c = 0; c < NC; c++) {
        CP_WAIT1();
        __syncthreads();
        if (c + 2 < NC) load_stage(c + 2, (c + 2) % NSTG);

        unsigned int base = sb + (c % NSTG) * STG_B;
        #pragma unroll
        for (int ks = 0; ks < 2; ks++) {
            unsigned int a_h[4][4], a_l[4][4], b_h[4][4], b_l[4][4];
            #pragma unroll
            for (int mt = 0; mt < 4; mt++) {
                unsigned int ro = (unsigned int)(wm0 + mt*16 + lr) * GPITCH + (ks*2 + lh) * 16;
                ldsm4(a_h[mt], base + OFF_AH + ro);
                ldsm4(a_l[mt], base + OFF_AL + ro);
            }
            #pragma unroll
            for (int bt = 0; bt < 4; bt++) {
                unsigned int ro = (unsigned int)(wn0 + bt*16 + lr) * GPITCH + (ks*2 + lh) * 16;
                ldsm4(b_h[bt], base + OFF_BH + ro);
                ldsm4(b_l[bt], base + OFF_BL + ro);
            }
            #pragma unroll
            for (int mt = 0; mt < 4; mt++) {
                #pragma unroll
                for (int nt = 0; nt < 8; nt++) {
                    int bt = nt >> 1, hf = nt & 1;
                    mma_bf16(acc[mt][nt], a_h[mt], b_h[bt][hf], b_h[bt][hf+2]);
                    mma_bf16(acc[mt][nt], a_l[mt], b_h[bt][hf], b_h[bt][hf+2]);
                    mma_bf16(acc[mt][nt], a_h[mt], b_l[bt][hf], b_l[bt][hf+2]);
                }
            }
        }
    }

    // ---- epilogue (register fragments -> gmem) ----
    const int gq = lane >> 2, pq = lane & 3;
    #pragma unroll
    for (int mt = 0; mt < 4; mt++) {
        #pragma unroll
        for (int nt = 0; nt < 8; nt++) {
            int col = col0 + wn0 + nt*8 + pq*2;
            float b0 = 0.f, b1 = 0.f;
            if (BIAS) { b0 = bias[col]; b1 = bias[col+1]; }
            #pragma unroll
            for (int h2 = 0; h2 < 2; h2++) {
                int row = row0 + wm0 + mt*16 + gq + h2*8;
                float v0 = acc[mt][nt][h2*2+0] + b0;
                float v1 = acc[mt][nt][h2*2+1] + b1;
                if (RELU) { v0 = fmaxf(v0, 0.f); v1 = fmaxf(v1, 0.f); }
                if (F32OUT)
                    *(float2*)(C + (size_t)row * N + col) = make_float2(v0, v1);
                if (SPLIT) {
                    unsigned int hi, lo;
                    split2(v0, v1, hi, lo);
                    *(unsigned int*)(Ch + (size_t)row * N + col) = hi;
                    *(unsigned int*)(Cl + (size_t)row * N + col) = lo;
                }
            }
        }
    }
}

// ===================== tensor-core causal flash attention (bf16x3) ============
// CTA: 64 q-rows, 4 warps (16 rows each), K/V tiles 64x64, double-buffered.
#define AP 144
#define AMAT 9216              // 64*144
#define FA_Q (2*AMAT)          // 18432
#define FA_STG (4*AMAT)        // 36864
#define FA_SMEM (FA_Q + 2*FA_STG)   // 92160

__global__ void __launch_bounds__(128, 1) flash_tc_kernel()
{
    const int qt = blockIdx.x, bh = blockIdx.y;
    const int b = bh >> 4, h = bh & 15;
    const int tid = threadIdx.x, wid = tid >> 5, lane = tid & 31;
    const int wm = wid * 16;
    const int lr = lane & 15, lh = lane >> 4;

    extern __shared__ __align__(16) char smem[];
    const unsigned int sb = smem_u32(smem);
    const unsigned int sQh = sb, sQl = sb + AMAT;

    // ---- load Q (hi/lo) ----
    {
        const __nv_bfloat16* qh = g_qkvh + (size_t)(b*SS + qt*64)*3072 + h*HDIM;
        const __nv_bfloat16* ql = g_qkvl + (size_t)(b*SS + qt*64)*3072 + h*HDIM;
        #pragma unroll
        for (int i = 0; i < 4; i++) {
            int lin = tid + (i << 7);
            int r = lin >> 3, ck = lin & 7;
            unsigned int so = r*AP + ck*16;
            size_t g = (size_t)r*3072 + ck*8;
            cp16(sQh + so, qh + g);
            cp16(sQl + so, ql + g);
        }
        CP_COMMIT();
    }

    auto load_kv = [&](int kt, int s) {
        unsigned int base = sb + FA_Q + s * FA_STG;
        size_t rowb = (size_t)(b*SS + kt*64)*3072;
        const __nv_bfloat16* kh = g_qkvh + rowb + 1024 + h*HDIM;
        const __nv_bfloat16* kl = g_qkvl + rowb + 1024 + h*HDIM;
        const __nv_bfloat16* vh = g_qkvh + rowb + 2048 + h*HDIM;
        const __nv_bfloat16* vl = g_qkvl + rowb + 2048 + h*HDIM;
        #pragma unroll
        for (int i = 0; i < 4; i++) {
            int lin = tid + (i << 7);
            int r = lin >> 3, ck = lin & 7;
            unsigned int so = r*AP + ck*16;
            size_t g = (size_t)r*3072 + ck*8;
            cp16(base + so,          kh + g);
            cp16(base + AMAT + so,   kl + g);
            cp16(base + 2*AMAT + so, vh + g);
            cp16(base + 3*AMAT + so, vl + g);
        }
        CP_COMMIT();
    };

    load_kv(0, 0);
    if (qt >= 1) load_kv(1, 1);

    float o[8][4] = {};
    float m0 = -1e30f, m1 = -1e30f, l0 = 0.f, l1 = 0.f;

    for (int kt = 0; kt <= qt; kt++) {
        if (kt < qt) CP_WAIT1(); else CP_WAIT0();
        __syncthreads();

        const unsigned int kb = sb + FA_Q + (kt & 1) * FA_STG;

        // ---- S = Q K^T (bf16x3) ----
        float sc[8][4] = {};
        #pragma unroll
        for (int kd = 0; kd < 4; kd++) {
            unsigned int aqh[4], aql[4];
            unsigned int qro = (unsigned int)(wm + lr)*AP + (kd*2 + lh)*16;
            ldsm4(aqh, sQh + qro);
            ldsm4(aql, sQl + qro);
            #pragma unroll
            for (int g = 0; g < 4; g++) {
                unsigned int rkh[4], rkl[4];
                unsigned int kro = (unsigned int)(g*16 + lr)*AP + (kd*2 + lh)*16;
                ldsm4(rkh, kb + kro);
                ldsm4(rkl, kb + AMAT + kro);
                mma_bf16(sc[2*g],   aqh, rkh[0], rkh[2]);
                mma_bf16(sc[2*g+1], aqh, rkh[1], rkh[3]);
                mma_bf16(sc[2*g],   aqh, rkl[0], rkl[2]);
                mma_bf16(sc[2*g+1], aqh, rkl[1], rkl[3]);
                mma_bf16(sc[2*g],   aql, rkh[0], rkh[2]);
                mma_bf16(sc[2*g+1], aql, rkh[1], rkh[3]);
            }
        }

        // ---- scale + causal mask ----
        const int lrow0 = wm + (lane >> 2), lrow1 = lrow0 + 8;
        if (kt == qt) {
            #pragma unroll
            for (int nt = 0; nt < 8; nt++) {
                int c0l = nt*8 + (lane & 3)*2;
                sc[nt][0] = (c0l     > lrow0) ? -1e30f : sc[nt][0]*0.125f;
                sc[nt][1] = (c0l + 1 > lrow0) ? -1e30f : sc[nt][1]*0.125f;
                sc[nt][2] = (c0l     > lrow1) ? -1e30f : sc[nt][2]*0.125f;
                sc[nt][3] = (c0l + 1 > lrow1) ? -1e30f : sc[nt][3]*0.125f;
            }
        } else {
            #pragma unroll
            for (int nt = 0; nt < 8; nt++) {
                sc[nt][0] *= 0.125f; sc[nt][1] *= 0.125f;
                sc[nt][2] *= 0.125f; sc[nt][3] *= 0.125f;
            }
        }

        // ---- online softmax (register state, 4-lane reductions) ----
        float mx0 = -1e30f, mx1 = -1e30f;
        #pragma unroll
        for (int nt = 0; nt < 8; nt++) {
            mx0 = fmaxf(mx0, fmaxf(sc[nt][0], sc[nt][1]));
            mx1 = fmaxf(mx1, fmaxf(sc[nt][2], sc[nt][3]));
        }
        mx0 = fmaxf(mx0, __shfl_xor_sync(0xffffffffu, mx0, 1));
        mx0 = fmaxf(mx0, __shfl_xor_sync(0xffffffffu, mx0, 2));
        mx1 = fmaxf(mx1, __shfl_xor_sync(0xffffffffu, mx1, 1));
        mx1 = fmaxf(mx1, __shfl_xor_sync(0xffffffffu, mx1, 2));
        float mn0 = fmaxf(m0, mx0), mn1 = fmaxf(m1, mx1);
        float cf0 = __expf(m0 - mn0), cf1 = __expf(m1 - mn1);
        m0 = mn0; m1 = mn1;
        float s0 = 0.f, s1 = 0.f;
        #pragma unroll
        for (int nt = 0; nt < 8; nt++) {
            sc[nt][0] = __expf(sc[nt][0] - mn0);
            sc[nt][1] = __expf(sc[nt][1] - mn0);
            sc[nt][2] = __expf(sc[nt][2] - mn1);
            sc[nt][3] = __expf(sc[nt][3] - mn1);
            s0 += sc[nt][0] + sc[nt][1];
            s1 += sc[nt][2] + sc[nt][3];
        }
        s0 += __shfl_xor_sync(0xffffffffu, s0, 1);
        s0 += __shfl_xor_sync(0xffffffffu, s0, 2);
        s1 += __shfl_xor_sync(0xffffffffu, s1, 1);
        s1 += __shfl_xor_sync(0xffffffffu, s1, 2);
        l0 = l0 * cf0 + s0;
        l1 = l1 * cf1 + s1;
        #pragma unroll
        for (int dt = 0; dt < 8; dt++) {
            o[dt][0] *= cf0; o[dt][1] *= cf0;
            o[dt][2] *= cf1; o[dt][3] *= cf1;
        }

        // ---- O += P V (bf16x3, P fragments from registers) ----
        #pragma unroll
        for (int j = 0; j < 4; j++) {
            unsigned int ph[4], pl[4];
            split2(sc[2*j][0],   sc[2*j][1],   ph[0], pl[0]);
            split2(sc[2*j][2],   sc[2*j][3],   ph[1], pl[1]);
            split2(sc[2*j+1][0], sc[2*j+1][1], ph[2], pl[2]);
            split2(sc[2*j+1][2], sc[2*j+1][3], ph[3], pl[3]);
            #pragma unroll
            for (int g = 0; g < 4; g++) {
                unsigned int rvh[4], rvl[4];
                unsigned int vro = (unsigned int)(j*16 + lr)*AP + (g*2 + lh)*16;
                ldsm4t(rvh, kb + 2*AMAT + vro);
                ldsm4t(rvl, kb + 3*AMAT + vro);
                mma_bf16(o[2*g],   ph, rvh[0], rvh[1]);
                mma_bf16(o[2*g+1], ph, rvh[2], rvh[3]);
                mma_bf16(o[2*g],   ph, rvl[0], rvl[1]);
                mma_bf16(o[2*g+1], ph, rvl[2], rvl[3]);
                mma_bf16(o[2*g],   pl, rvh[0], rvh[1]);
                mma_bf16(o[2*g+1], pl, rvh[2], rvh[3]);
            }
        }

        __syncthreads();
        if (kt + 2 <= qt) load_kv(kt + 2, kt & 1);
    }

    // ---- epilogue: normalize, split to bf16 hi/lo, natural (bh,s,e) order ----
    const float inv0 = 1.f / l0, inv1 = 1.f / l1;
    const int row0g = qt*64 + wm + (lane >> 2);
    __nv_bfloat16* ohp = g_ah + ((size_t)bh*SS)*HDIM;
    __nv_bfloat16* olp = g_al + ((size_t)bh*SS)*HDIM;
    #pragma unroll
    for (int dt = 0; dt < 8; dt++) {
        int d = dt*8 + (lane & 3)*2;
        unsigned int hi, lo;
        split2(o[dt][0]*inv0, o[dt][1]*inv0, hi, lo);
        *(unsigned int*)(ohp + (size_t)row0g*HDIM + d) = hi;
        *(unsigned int*)(olp + (size_t)row0g*HDIM + d) = lo;
        split2(o[dt][2]*inv1, o[dt][3]*inv1, hi, lo);
        *(unsigned int*)(ohp + (size_t)(row0g+8)*HDIM + d) = hi;
        *(unsigned int*)(olp + (size_t)(row0g+8)*HDIM + d) = lo;
    }
}

// ===================== LayerNorm =====================
__device__ __forceinline__ float blk_sum(float v, float* sred)
{
    #pragma unroll
    for (int o = 16; o; o >>= 1) v += __shfl_xor_sync(0xffffffffu, v, o);
    int w = threadIdx.x >> 5;
    if ((threadIdx.x & 31) == 0) sred[w] = v;
    __syncthreads();
    float t = (threadIdx.x < 8) ? sred[threadIdx.x] : 0.f;
    if (threadIdx.x < 32) {
        #pragma unroll
        for (int o = 4; o; o >>= 1) t += __shfl_xor_sync(0xffffffffu, t, o);
        if (threadIdx.x == 0) sred[0] = t;
    }
    __syncthreads();
    float r = sred[0];
    __syncthreads();
    return r;
}

template<bool SPLIT>
__global__ void ln_kernel(const float* __restrict__ resid,
                          const float* __restrict__ y,
                          const float* __restrict__ gamma,
                          const float* __restrict__ beta,
                          float* __restrict__ outf,
                          __nv_bfloat16* __restrict__ oh,
                          __nv_bfloat16* __restrict__ ol)
{
    __shared__ float sred[32];
    const int row = blockIdx.x;
    const int tid = threadIdx.x;

    float4 a = ((const float4*)(resid + (size_t)row * DD))[tid];
    float4 b = ((const float4*)(y     + (size_t)row * DD))[tid];
    float4 v = make_float4(a.x + b.x, a.y + b.y, a.z + b.z, a.w + b.w);

    float total = blk_sum(v.x + v.y + v.z + v.w, sred);
    float mu = total * (1.f / DD);

    float dx = v.x - mu, dy = v.y - mu, dz = v.z - mu, dw = v.w - mu;
    float tot2 = blk_sum(dx*dx + dy*dy + dz*dz + dw*dw, sred);
    float inv = rsqrtf(tot2 * (1.f / DD) + LN_EPS);

    float4 g = ((const float4*)gamma)[tid];
    float4 be = ((const float4*)beta)[tid];
    float ov[4];
    ov[0] = dx * inv * g.x + be.x;
    ov[1] = dy * inv * g.y + be.y;
    ov[2] = dz * inv * g.z + be.z;
    ov[3] = dw * inv * g.w + be.w;
    ((float4*)(outf + (size_t)row * DD))[tid] = make_float4(ov[0], ov[1], ov[2], ov[3]);

    if (SPLIT) {
        unsigned int wh[2], wl[2];
        split2(ov[0], ov[1], wh[0], wl[0]);
        split2(ov[2], ov[3], wh[1], wl[1]);
        *(uint2*)(oh + (size_t)row * DD + tid * 4) = make_uint2(wh[0], wh[1]);
        *(uint2*)(ol + (size_t)row * DD + tid * 4) = make_uint2(wl[0], wl[1]);
    }
}

// ===================== launch =====================
extern "C" void kernel_launch(void* const* d_in, const int* in_sizes, int n_in,
                              void* d_out, int out_size)
{
    (void)in_sizes; (void)n_in; (void)out_size;

    const float* x     = (const float*)d_in[0];
    const float* Wq    = (const float*)d_in[1];
    const float* Wk    = (const float*)d_in[2];
    const float* Wv    = (const float*)d_in[3];
    const float* Wo    = (const float*)d_in[4];
    const float* g1    = (const float*)d_in[5];
    const float* be1   = (const float*)d_in[6];
    const float* w_in  = (const float*)d_in[7];
    const float* b_in  = (const float*)d_in[8];
    const float* w_out = (const float*)d_in[9];
    const float* b_out = (const float*)d_in[10];
    const float* g2    = (const float*)d_in[11];
    const float* be2   = (const float*)d_in[12];
    float* out = (float*)d_out;

    float *tmp, *x1;
    __nv_bfloat16 *qkvh, *qkvl, *xh, *xl, *ah, *al, *x1h, *x1l, *h1h, *h1l;
    __nv_bfloat16 *wqkvh, *wqkvl, *woh, *wol, *winh, *winl, *wouth, *woutl;
    cudaGetSymbolAddress((void**)&tmp,  g_tmp);
    cudaGetSymbolAddress((void**)&x1,   g_x1);
    cudaGetSymbolAddress((void**)&qkvh, g_qkvh);  cudaGetSymbolAddress((void**)&qkvl, g_qkvl);
    cudaGetSymbolAddress((void**)&xh,   g_xh);    cudaGetSymbolAddress((void**)&xl,   g_xl);
    cudaGetSymbolAddress((void**)&ah,   g_ah);    cudaGetSymbolAddress((void**)&al,   g_al);
    cudaGetSymbolAddress((void**)&x1h,  g_x1h);   cudaGetSymbolAddress((void**)&x1l,  g_x1l);
    cudaGetSymbolAddress((void**)&h1h,  g_h1h);   cudaGetSymbolAddress((void**)&h1l,  g_h1l);
    cudaGetSymbolAddress((void**)&wqkvh, g_wqkvh); cudaGetSymbolAddress((void**)&wqkvl, g_wqkvl);
    cudaGetSymbolAddress((void**)&woh,   g_woh);   cudaGetSymbolAddress((void**)&wol,   g_wol);
    cudaGetSymbolAddress((void**)&winh,  g_winh);  cudaGetSymbolAddress((void**)&winl,  g_winl);
    cudaGetSymbolAddress((void**)&wouth, g_wouth); cudaGetSymbolAddress((void**)&woutl, g_woutl);

    cudaFuncSetAttribute(flash_tc_kernel, cudaFuncAttributeMaxDynamicSharedMemorySize, FA_SMEM);
    cudaFuncSetAttribute(gemm_tc_kernel<false,false,false,true>, cudaFuncAttributeMaxDynamicSharedMemorySize, GT_SMEM);
    cudaFuncSetAttribute(gemm_tc_kernel<false,false,true,false>, cudaFuncAttributeMaxDynamicSharedMemorySize, GT_SMEM);
    cudaFuncSetAttribute(gemm_tc_kernel<true,true,false,true>,   cudaFuncAttributeMaxDynamicSharedMemorySize, GT_SMEM);
    cudaFuncSetAttribute(gemm_tc_kernel<true,false,true,false>,  cudaFuncAttributeMaxDynamicSharedMemorySize, GT_SMEM);

    // ---- prep: split x; transpose+split weights ----
    fsplit_kernel<<<MM*DD/1024, 256>>>(x, xh, xl, MM*DD/4);
    qkvT_kernel<<<dim3(2, 32, 48), dim3(32, 8)>>>(Wq, Wk, Wv, wqkvh, wqkvl);
    wsplitT_kernel<<<dim3(32, 32),  dim3(32, 8)>>>(Wo,    woh,   wol,   1024, 1024);
    wsplitT_kernel<<<dim3(128, 32), dim3(32, 8)>>>(w_in,  winh,  winl,  1024, 4096);
    wsplitT_kernel<<<dim3(32, 128), dim3(32, 8)>>>(w_out, wouth, woutl, 4096, 1024);

    // ---- 1) fused QKV projection -> split bf16 hi/lo directly ----
    gemm_tc_kernel<false,false,false,true><<<dim3(3072/256, MM/128), 256, GT_SMEM>>>(
        xh, xl, wqkvh, wqkvl, nullptr, nullptr, qkvh, qkvl, MM, 3072, 1024);

    // ---- 2) causal flash attention (tensor cores, bf16x3) ----
    flash_tc_kernel<<<dim3(SS/64, BB*HH), 128, FA_SMEM>>>();

    // ---- 3) output projection ----
    gemm_tc_kernel<false,false,true,false><<<dim3(1024/256, MM/128), 256, GT_SMEM>>>(
        ah, al, woh, wol, nullptr, tmp, nullptr, nullptr, MM, 1024, 1024);

    // ---- 4) LN1 (x + attn@Wo), also split to bf16 ----
    ln_kernel<true><<<MM, 256>>>(x, tmp, g1, be1, x1, x1h, x1l);

    // ---- 5) FFN up + bias + ReLU, split output ----
    gemm_tc_kernel<true,true,false,true><<<dim3(4096/256, MM/128), 256, GT_SMEM>>>(
        x1h, x1l, winh, winl, b_in, nullptr, h1h, h1l, MM, 4096, 1024);

    // ---- 6) FFN down + bias ----
    gemm_tc_kernel<true,false,true,false><<<dim3(1024/256, MM/128), 256, GT_SMEM>>>(
        h1h, h1l, wouth, woutl, b_out, tmp, nullptr, nullptr, MM, 1024, 4096);

    // ---- 7) LN2 -> output ----
    ln_kernel<false><<<MM, 256>>>(x1, tmp, g2, be2, out, nullptr, nullptr);
}

// round 7
// speedup vs baseline: 2.4207x; 1.0062x over previous
#include <cuda_runtime.h>
#include <cuda_bf16.h>
#include <math.h>

// Problem constants
#define BB   4
#define SS   2048
#define DD   1024
#define HH   16
#define HDIM 64
#define FF   4096
#define MM   (BB*SS)   // 8192 rows
#define LN_EPS 1e-5f

// ===================== low-level helpers =====================
__device__ __forceinline__ unsigned int smem_u32(const void* p) {
    unsigned int a;
    asm("{ .reg .u64 t; cvta.to.shared.u64 t, %1; cvt.u32.u64 %0, t; }" : "=r"(a) : "l"(p));
    return a;
}
__device__ __forceinline__ void cp16(unsigned int s, const void* g) {
    asm volatile("cp.async.cg.shared.global [%0], [%1], 16;" :: "r"(s), "l"(g));
}
#define CP_COMMIT() asm volatile("cp.async.commit_group;" ::: "memory")
#define CP_WAIT1()  asm volatile("cp.async.wait_group 1;" ::: "memory")
#define CP_WAIT0()  asm volatile("cp.async.wait_group 0;" ::: "memory")

__device__ __forceinline__ void ldsm4(unsigned int* r, unsigned int addr) {
    asm volatile("ldmatrix.sync.aligned.m8n8.x4.shared.b16 {%0,%1,%2,%3}, [%4];"
        : "=r"(r[0]), "=r"(r[1]), "=r"(r[2]), "=r"(r[3]) : "r"(addr));
}
__device__ __forceinline__ void ldsm4t(unsigned int* r, unsigned int addr) {
    asm volatile("ldmatrix.sync.aligned.m8n8.x4.trans.shared.b16 {%0,%1,%2,%3}, [%4];"
        : "=r"(r[0]), "=r"(r[1]), "=r"(r[2]), "=r"(r[3]) : "r"(addr));
}
__device__ __forceinline__ void mma_bf16(float* c, const unsigned int* a,
                                         unsigned int b0, unsigned int b1) {
    asm volatile("mma.sync.aligned.m16n8k16.row.col.f32.bf16.bf16.f32 "
        "{%0,%1,%2,%3}, {%4,%5,%6,%7}, {%8,%9}, {%0,%1,%2,%3};"
        : "+f"(c[0]), "+f"(c[1]), "+f"(c[2]), "+f"(c[3])
        : "r"(a[0]), "r"(a[1]), "r"(a[2]), "r"(a[3]), "r"(b0), "r"(b1));
}
__device__ __forceinline__ unsigned int pack_bf16(__nv_bfloat16 a, __nv_bfloat16 b) {
    return (unsigned int)__bfloat16_as_ushort(a) | ((unsigned int)__bfloat16_as_ushort(b) << 16);
}
__device__ __forceinline__ void split2(float v0, float v1, unsigned int& hi, unsigned int& lo) {
    __nv_bfloat16 h0 = __float2bfloat16(v0);
    __nv_bfloat16 h1 = __float2bfloat16(v1);
    __nv_bfloat16 l0 = __float2bfloat16(v0 - __bfloat162float(h0));
    __nv_bfloat16 l1 = __float2bfloat16(v1 - __bfloat162float(h1));
    hi = pack_bf16(h0, h1);
    lo = pack_bf16(l0, l1);
}

// ===================== scratch (device globals) =====================
__device__ __nv_bfloat16 g_qkvh[(size_t)MM*3072], g_qkvl[(size_t)MM*3072];
__device__ __nv_bfloat16 g_xh[(size_t)MM*DD],  g_xl[(size_t)MM*DD];
__device__ __nv_bfloat16 g_ah[(size_t)MM*DD],  g_al[(size_t)MM*DD];
__device__ float g_tmp[(size_t)MM*DD];
__device__ float g_x1[(size_t)MM*DD];
__device__ __nv_bfloat16 g_x1h[(size_t)MM*DD], g_x1l[(size_t)MM*DD];
__device__ __nv_bfloat16 g_h1h[(size_t)MM*FF], g_h1l[(size_t)MM*FF];
// transposed + split weights ([N,K] row-major bf16)
__device__ __nv_bfloat16 g_wqkvh[(size_t)3072*1024], g_wqkvl[(size_t)3072*1024];
__device__ __nv_bfloat16 g_woh[(size_t)1024*1024],   g_wol[(size_t)1024*1024];
__device__ __nv_bfloat16 g_winh[(size_t)4096*1024],  g_winl[(size_t)4096*1024];
__device__ __nv_bfloat16 g_wouth[(size_t)1024*4096], g_woutl[(size_t)1024*4096];

// ===================== prep kernels =====================
__global__ void fsplit_kernel(const float* __restrict__ in,
                              __nv_bfloat16* __restrict__ h,
                              __nv_bfloat16* __restrict__ l, int n4)
{
    int i = blockIdx.x * blockDim.x + threadIdx.x;
    if (i >= n4) return;
    float4 v = ((const float4*)in)[i];
    unsigned int ph[2], pl[2];
    split2(v.x, v.y, ph[0], pl[0]);
    split2(v.z, v.w, ph[1], pl[1]);
    ((uint2*)h)[i] = make_uint2(ph[0], ph[1]);
    ((uint2*)l)[i] = make_uint2(pl[0], pl[1]);
}

// transpose+split one 32x32 block of W [K,N] -> T [N,K]
__device__ __forceinline__ void wsplit_block(const float* __restrict__ W,
                                             __nv_bfloat16* __restrict__ Th,
                                             __nv_bfloat16* __restrict__ Tl,
                                             int K, int N, int k0, int n0,
                                             float t[32][33])
{
    int tx = threadIdx.x, ty = threadIdx.y;
    #pragma unroll
    for (int i = 0; i < 32; i += 8)
        t[ty + i][tx] = W[(size_t)(k0 + ty + i) * N + n0 + tx];
    __syncthreads();
    #pragma unroll
    for (int i = 0; i < 32; i += 8) {
        float v = t[tx][ty + i];
        __nv_bfloat16 h = __float2bfloat16(v);
        size_t o = (size_t)(n0 + ty + i) * K + k0 + tx;
        Th[o] = h;
        Tl[o] = __float2bfloat16(v - __bfloat162float(h));
    }
}

// merged: Wo (1024 blocks), w_in (4096), w_out (4096) -> 9216 blocks linear
__global__ void wsplit3_kernel(const float* __restrict__ Wo,
                               const float* __restrict__ Win,
                               const float* __restrict__ Wout)
{
    __shared__ float t[32][33];
    int idx = blockIdx.x;
    if (idx < 1024) {
        wsplit_block(Wo, g_woh, g_wol, 1024, 1024,
                     (idx >> 5) * 32, (idx & 31) * 32, t);
    } else if (idx < 1024 + 4096) {
        int i2 = idx - 1024;
        wsplit_block(Win, g_winh, g_winl, 1024, 4096,
                     (i2 >> 7) * 32, (i2 & 127) * 32, t);
    } else {
        int i2 = idx - 5120;
        wsplit_block(Wout, g_wouth, g_woutl, 4096, 1024,
                     (i2 >> 5) * 32, (i2 & 31) * 32, t);
    }
}

__global__ void qkvT_kernel(const float* __restrict__ Wq,
                            const float* __restrict__ Wk,
                            const float* __restrict__ Wv,
                            __nv_bfloat16* __restrict__ Th,
                            __nv_bfloat16* __restrict__ Tl)
{
    __shared__ float t[32][33];
    int z = blockIdx.z;
    int mat = z / HH, h = z - mat * HH;
    const float* W = (mat == 0 ? Wq : mat == 1 ? Wk : Wv) + (size_t)h * DD * HDIM;
    int k0 = blockIdx.y * 32, e0 = blockIdx.x * 32;
    int tx = threadIdx.x, ty = threadIdx.y;
    #pragma unroll
    for (int i = 0; i < 32; i += 8)
        t[ty + i][tx] = W[(size_t)(k0 + ty + i) * HDIM + e0 + tx];
    __syncthreads();
    int nbase = mat * 1024 + h * HDIM;
    #pragma unroll
    for (int i = 0; i < 32; i += 8) {
        float v = t[tx][ty + i];
        __nv_bfloat16 hv = __float2bfloat16(v);
        size_t o = (size_t)(nbase + e0 + ty + i) * DD + k0 + tx;
        Th[o] = hv;
        Tl[o] = __float2bfloat16(v - __bfloat162float(hv));
    }
}

// ===================== mma.sync bf16x3 GEMM =====================
// Block 128x256, K-chunk 32, 3-stage cp.async pipeline, 16 warps (2x8), warp 64x32.
#define GPITCH 80
#define AMAT_G (128*GPITCH)      // 10240
#define BMAT_G (256*GPITCH)      // 20480
#define OFF_AH 0
#define OFF_AL AMAT_G
#define OFF_BH (2*AMAT_G)
#define OFF_BL (2*AMAT_G + BMAT_G)
#define STG_B  (2*AMAT_G + 2*BMAT_G)   // 61440
#define NSTG   3
#define GT_SMEM (NSTG*STG_B)           // 184320

template<bool BIAS, bool RELU, bool F32OUT, bool SPLIT>
__global__ void __launch_bounds__(512, 1) gemm_tc_kernel(
    const __nv_bfloat16* __restrict__ Ah, const __nv_bfloat16* __restrict__ Al,
    const __nv_bfloat16* __restrict__ BTh, const __nv_bfloat16* __restrict__ BTl,
    const float* __restrict__ bias,
    float* __restrict__ C,
    __nv_bfloat16* __restrict__ Ch, __nv_bfloat16* __restrict__ Cl,
    int M, int N, int K)
{
    extern __shared__ __align__(16) char smem[];
    const unsigned int sb = smem_u32(smem);
    const int tid = threadIdx.x;
    const int row0 = blockIdx.y * 128;
    const int col0 = blockIdx.x * 256;

    const int wid = tid >> 5, lane = tid & 31;
    const int wm0 = (wid & 1) * 64, wn0 = (wid >> 1) * 32;
    const int lr = lane & 15, lh = lane >> 4;

    auto load_stage = [&](int c, int s) {
        unsigned int base = sb + s * STG_B;
        int k0 = c * 32;
        {
            int r = tid >> 2, ck = tid & 3;              // 0..127
            unsigned int so = r * GPITCH + ck * 16;
            size_t ga = (size_t)(row0 + r) * K + k0 + ck * 8;
            cp16(base + OFF_AH + so, Ah + ga);
            cp16(base + OFF_AL + so, Al + ga);
        }
        #pragma unroll
        for (int i = 0; i < 2; i++) {
            int lin = tid + (i << 9);                    // 0..1023
            int r = lin >> 2, ck = lin & 3;
            unsigned int so = r * GPITCH + ck * 16;
            size_t gb = (size_t)(col0 + r) * K + k0 + ck * 8;
            cp16(base + OFF_BH + so, BTh + gb);
            cp16(base + OFF_BL + so, BTl + gb);
        }
        CP_COMMIT();
    };

    float acc[4][4][4] = {};

    load_stage(0, 0);
    load_stage(1, 1);

    const int NC = K >> 5;
    for (int c = 0; c < NC; c++) {
        CP_WAIT1();
        __syncthreads();
        if (c + 2 < NC) load_stage(c + 2, (c + 2) % NSTG);

        unsigned int base = sb + (c % NSTG) * STG_B;
        #pragma unroll
        for (int ks = 0; ks < 2; ks++) {
            unsigned int a_h[4][4], a_l[4][4], b_h[2][4], b_l[2][4];
            #pragma unroll
            for (int mt = 0; mt < 4; mt++) {
                unsigned int ro = (unsigned int)(wm0 + mt*16 + lr) * GPITCH + (ks*2 + lh) * 16;
                ldsm4(a_h[mt], base + OFF_AH + ro);
                ldsm4(a_l[mt], base + OFF_AL + ro);
            }
            #pragma unroll
            for (int bt = 0; bt < 2; bt++) {
                unsigned int ro = (unsigned int)(wn0 + bt*16 + lr) * GPITCH + (ks*2 + lh) * 16;
                ldsm4(b_h[bt], base + OFF_BH + ro);
                ldsm4(b_l[bt], base + OFF_BL + ro);
            }
            #pragma unroll
            for (int mt = 0; mt < 4; mt++) {
                #pragma unroll
                for (int nt = 0; nt < 4; nt++) {
                    int bt = nt >> 1, hf = nt & 1;
                    mma_bf16(acc[mt][nt], a_h[mt], b_h[bt][hf], b_h[bt][hf+2]);
                    mma_bf16(acc[mt][nt], a_l[mt], b_h[bt][hf], b_h[bt][hf+2]);
                    mma_bf16(acc[mt][nt], a_h[mt], b_l[bt][hf], b_l[bt][hf+2]);
                }
            }
        }
    }

    // ---- epilogue (register fragments -> gmem) ----
    const int gq = lane >> 2, pq = lane & 3;
    #pragma unroll
    for (int mt = 0; mt < 4; mt++) {
        #pragma unroll
        for (int nt = 0; nt < 4; nt++) {
            int col = col0 + wn0 + nt*8 + pq*2;
            float b0 = 0.f, b1 = 0.f;
            if (BIAS) { b0 = bias[col]; b1 = bias[col+1]; }
            #pragma unroll
            for (int h2 = 0; h2 < 2; h2++) {
                int row = row0 + wm0 + mt*16 + gq + h2*8;
                float v0 = acc[mt][nt][h2*2+0] + b0;
                float v1 = acc[mt][nt][h2*2+1] + b1;
                if (RELU) { v0 = fmaxf(v0, 0.f); v1 = fmaxf(v1, 0.f); }
                if (F32OUT)
                    *(float2*)(C + (size_t)row * N + col) = make_float2(v0, v1);
                if (SPLIT) {
                    unsigned int hi, lo;
                    split2(v0, v1, hi, lo);
                    *(unsigned int*)(Ch + (size_t)row * N + col) = hi;
                    *(unsigned int*)(Cl + (size_t)row * N + col) = lo;
                }
            }
        }
    }
}

// ===================== tensor-core causal flash attention (bf16x3) ============
// CTA: 256 threads / 8 warps; processes TWO paired q-tiles of 128 rows each
// (qt0 = pid and 15-pid) for uniform work. K/V tiles 64x64, double-buffered.
#define AP 144
#define KMAT 9216              // 64*AP
#define QMAT 18432             // 128*AP
#define FA_Q (2*QMAT)          // 36864
#define FA_STG (4*KMAT)        // 36864
#define FA_SMEM (FA_Q + 2*FA_STG)   // 110592

__global__ void __launch_bounds__(256, 1) flash_tc_kernel()
{
    const int pid = blockIdx.x, bh = blockIdx.y;
    const int b = bh >> 4, h = bh & 15;
    const int tid = threadIdx.x, wid = tid >> 5, lane = tid & 31;
    const int wm = wid * 16;
    const int lr = lane & 15, lh = lane >> 4;

    extern __shared__ __align__(16) char smem[];
    const unsigned int sb = smem_u32(smem);
    const unsigned int sQh = sb, sQl = sb + QMAT;

    for (int run = 0; run < 2; run++) {
        const int qt0 = run ? (15 - pid) : pid;
        const int NKT = 2 * qt0 + 2;

        __syncthreads();   // previous run fully done with smem

        // ---- load Q tile (128 rows, hi/lo) ----
        {
            const __nv_bfloat16* qh = g_qkvh + (size_t)(b*SS + qt0*128)*3072 + h*HDIM;
            const __nv_bfloat16* ql = g_qkvl + (size_t)(b*SS + qt0*128)*3072 + h*HDIM;
            #pragma unroll
            for (int i = 0; i < 4; i++) {
                int lin = tid + (i << 8);
                int r = lin >> 3, ck = lin & 7;
                unsigned int so = r*AP + ck*16;
                size_t g = (size_t)r*3072 + ck*8;
                cp16(sQh + so, qh + g);
                cp16(sQl + so, ql + g);
            }
            CP_COMMIT();
        }

        auto load_kv = [&](int kt, int s) {
            unsigned int base = sb + FA_Q + s * FA_STG;
            size_t rowb = (size_t)(b*SS + kt*64)*3072;
            const __nv_bfloat16* kh = g_qkvh + rowb + 1024 + h*HDIM;
            const __nv_bfloat16* kl = g_qkvl + rowb + 1024 + h*HDIM;
            const __nv_bfloat16* vh = g_qkvh + rowb + 2048 + h*HDIM;
            const __nv_bfloat16* vl = g_qkvl + rowb + 2048 + h*HDIM;
            #pragma unroll
            for (int i = 0; i < 2; i++) {
                int lin = tid + (i << 8);
                int r = lin >> 3, ck = lin & 7;
                unsigned int so = r*AP + ck*16;
                size_t g = (size_t)r*3072 + ck*8;
                cp16(base + so,          kh + g);
                cp16(base + KMAT + so,   kl + g);
                cp16(base + 2*KMAT + so, vh + g);
                cp16(base + 3*KMAT + so, vl + g);
            }
            CP_COMMIT();
        };

        load_kv(0, 0);
        load_kv(1, 1);

        float o[8][4] = {};
        float m0 = -1e30f, m1 = -1e30f, l0 = 0.f, l1 = 0.f;

        for (int kt = 0; kt < NKT; kt++) {
            if (kt < NKT - 1) CP_WAIT1(); else CP_WAIT0();
            __syncthreads();

            const unsigned int kb = sb + FA_Q + (kt & 1) * FA_STG;

            // ---- S = Q K^T (bf16x3) ----
            float sc[8][4] = {};
            #pragma unroll
            for (int kd = 0; kd < 4; kd++) {
                unsigned int aqh[4], aql[4];
                unsigned int qro = (unsigned int)(wm + lr)*AP + (kd*2 + lh)*16;
                ldsm4(aqh, sQh + qro);
                ldsm4(aql, sQl + qro);
                #pragma unroll
                for (int g = 0; g < 4; g++) {
                    unsigned int rkh[4], rkl[4];
                    unsigned int kro = (unsigned int)(g*16 + lr)*AP + (kd*2 + lh)*16;
                    ldsm4(rkh, kb + kro);
                    ldsm4(rkl, kb + KMAT + kro);
                    mma_bf16(sc[2*g],   aqh, rkh[0], rkh[2]);
                    mma_bf16(sc[2*g+1], aqh, rkh[1], rkh[3]);
                    mma_bf16(sc[2*g],   aqh, rkl[0], rkl[2]);
                    mma_bf16(sc[2*g+1], aqh, rkl[1], rkl[3]);
                    mma_bf16(sc[2*g],   aql, rkh[0], rkh[2]);
                    mma_bf16(sc[2*g+1], aql, rkh[1], rkh[3]);
                }
            }

            // ---- scale + causal mask ----
            if (kt >= 2*qt0) {
                const int grow0 = qt0*128 + wm + (lane >> 2);
                const int gc0 = kt*64 + (lane & 3)*2;
                #pragma unroll
                for (int nt = 0; nt < 8; nt++) {
                    int c0l = gc0 + nt*8;
                    sc[nt][0] = (c0l     > grow0)   ? -1e30f : sc[nt][0]*0.125f;
                    sc[nt][1] = (c0l + 1 > grow0)   ? -1e30f : sc[nt][1]*0.125f;
                    sc[nt][2] = (c0l     > grow0+8) ? -1e30f : sc[nt][2]*0.125f;
                    sc[nt][3] = (c0l + 1 > grow0+8) ? -1e30f : sc[nt][3]*0.125f;
                }
            } else {
                #pragma unroll
                for (int nt = 0; nt < 8; nt++) {
                    sc[nt][0] *= 0.125f; sc[nt][1] *= 0.125f;
                    sc[nt][2] *= 0.125f; sc[nt][3] *= 0.125f;
                }
            }

            // ---- online softmax ----
            float mx0 = -1e30f, mx1 = -1e30f;
            #pragma unroll
            for (int nt = 0; nt < 8; nt++) {
                mx0 = fmaxf(mx0, fmaxf(sc[nt][0], sc[nt][1]));
                mx1 = fmaxf(mx1, fmaxf(sc[nt][2], sc[nt][3]));
            }
            mx0 = fmaxf(mx0, __shfl_xor_sync(0xffffffffu, mx0, 1));
            mx0 = fmaxf(mx0, __shfl_xor_sync(0xffffffffu, mx0, 2));
            mx1 = fmaxf(mx1, __shfl_xor_sync(0xffffffffu, mx1, 1));
            mx1 = fmaxf(mx1, __shfl_xor_sync(0xffffffffu, mx1, 2));
            float mn0 = fmaxf(m0, mx0), mn1 = fmaxf(m1, mx1);
            float cf0 = __expf(m0 - mn0), cf1 = __expf(m1 - mn1);
            m0 = mn0; m1 = mn1;
            float s0 = 0.f, s1 = 0.f;
            #pragma unroll
            for (int nt = 0; nt < 8; nt++) {
                sc[nt][0] = __expf(sc[nt][0] - mn0);
                sc[nt][1] = __expf(sc[nt][1] - mn0);
                sc[nt][2] = __expf(sc[nt][2] - mn1);
                sc[nt][3] = __expf(sc[nt][3] - mn1);
                s0 += sc[nt][0] + sc[nt][1];
                s1 += sc[nt][2] + sc[nt][3];
            }
            s0 += __shfl_xor_sync(0xffffffffu, s0, 1);
            s0 += __shfl_xor_sync(0xffffffffu, s0, 2);
            s1 += __shfl_xor_sync(0xffffffffu, s1, 1);
            s1 += __shfl_xor_sync(0xffffffffu, s1, 2);
            l0 = l0 * cf0 + s0;
            l1 = l1 * cf1 + s1;
            #pragma unroll
            for (int dt = 0; dt < 8; dt++) {
                o[dt][0] *= cf0; o[dt][1] *= cf0;
                o[dt][2] *= cf1; o[dt][3] *= cf1;
            }

            // ---- O += P V (bf16x3, P fragments from registers) ----
            #pragma unroll
            for (int j = 0; j < 4; j++) {
                unsigned int ph[4], pl[4];
                split2(sc[2*j][0],   sc[2*j][1],   ph[0], pl[0]);
                split2(sc[2*j][2],   sc[2*j][3],   ph[1], pl[1]);
                split2(sc[2*j+1][0], sc[2*j+1][1], ph[2], pl[2]);
                split2(sc[2*j+1][2], sc[2*j+1][3], ph[3], pl[3]);
                #pragma unroll
                for (int g = 0; g < 4; g++) {
                    unsigned int rvh[4], rvl[4];
                    unsigned int vro = (unsigned int)(j*16 + lr)*AP + (g*2 + lh)*16;
                    ldsm4t(rvh, kb + 2*KMAT + vro);
                    ldsm4t(rvl, kb + 3*KMAT + vro);
                    mma_bf16(o[2*g],   ph, rvh[0], rvh[1]);
                    mma_bf16(o[2*g+1], ph, rvh[2], rvh[3]);
                    mma_bf16(o[2*g],   ph, rvl[0], rvl[1]);
                    mma_bf16(o[2*g+1], ph, rvl[2], rvl[3]);
                    mma_bf16(o[2*g],   pl, rvh[0], rvh[1]);
                    mma_bf16(o[2*g+1], pl, rvh[2], rvh[3]);
                }
            }

            __syncthreads();
            if (kt + 2 < NKT) load_kv(kt + 2, kt & 1);
        }

        // ---- epilogue: normalize, split to bf16 hi/lo ----
        const float inv0 = 1.f / l0, inv1 = 1.f / l1;
        const int row0g = qt0*128 + wm + (lane >> 2);
        __nv_bfloat16* ohp = g_ah + ((size_t)bh*SS)*HDIM;
        __nv_bfloat16* olp = g_al + ((size_t)bh*SS)*HDIM;
        #pragma unroll
        for (int dt = 0; dt < 8; dt++) {
            int d = dt*8 + (lane & 3)*2;
            unsigned int hi, lo;
            split2(o[dt][0]*inv0, o[dt][1]*inv0, hi, lo);
            *(unsigned int*)(ohp + (size_t)row0g*HDIM + d) = hi;
            *(unsigned int*)(olp + (size_t)row0g*HDIM + d) = lo;
            split2(o[dt][2]*inv1, o[dt][3]*inv1, hi, lo);
            *(unsigned int*)(ohp + (size_t)(row0g+8)*HDIM + d) = hi;
            *(unsigned int*)(olp + (size_t)(row0g+8)*HDIM + d) = lo;
        }
    }
}

// ===================== LayerNorm =====================
__device__ __forceinline__ float blk_sum(float v, float* sred)
{
    #pragma unroll
    for (int o = 16; o; o >>= 1) v += __shfl_xor_sync(0xffffffffu, v, o);
    int w = threadIdx.x >> 5;
    if ((threadIdx.x & 31) == 0) sred[w] = v;
    __syncthreads();
    float t = (threadIdx.x < 8) ? sred[threadIdx.x] : 0.f;
    if (threadIdx.x < 32) {
        #pragma unroll
        for (int o = 4; o; o >>= 1) t += __shfl_xor_sync(0xffffffffu, t, o);
        if (threadIdx.x == 0) sred[0] = t;
    }
    __syncthreads();
    float r = sred[0];
    __syncthreads();
    return r;
}

template<bool SPLIT>
__global__ void ln_kernel(const float* __restrict__ resid,
                          const float* __restrict__ y,
                          const float* __restrict__ gamma,
                          const float* __restrict__ beta,
                          float* __restrict__ outf,
                          __nv_bfloat16* __restrict__ oh,
                          __nv_bfloat16* __restrict__ ol)
{
    __shared__ float sred[32];
    const int row = blockIdx.x;
    const int tid = threadIdx.x;

    float4 a = ((const float4*)(resid + (size_t)row * DD))[tid];
    float4 b = ((const float4*)(y     + (size_t)row * DD))[tid];
    float4 v = make_float4(a.x + b.x, a.y + b.y, a.z + b.z, a.w + b.w);

    float total = blk_sum(v.x + v.y + v.z + v.w, sred);
    float mu = total * (1.f / DD);

    float dx = v.x - mu, dy = v.y - mu, dz = v.z - mu, dw = v.w - mu;
    float tot2 = blk_sum(dx*dx + dy*dy + dz*dz + dw*dw, sred);
    float inv = rsqrtf(tot2 * (1.f / DD) + LN_EPS);

    float4 g = ((const float4*)gamma)[tid];
    float4 be = ((const float4*)beta)[tid];
    float ov[4];
    ov[0] = dx * inv * g.x + be.x;
    ov[1] = dy * inv * g.y + be.y;
    ov[2] = dz * inv * g.z + be.z;
    ov[3] = dw * inv * g.w + be.w;
    ((float4*)(outf + (size_t)row * DD))[tid] = make_float4(ov[0], ov[1], ov[2], ov[3]);

    if (SPLIT) {
        unsigned int wh[2], wl[2];
        split2(ov[0], ov[1], wh[0], wl[0]);
        split2(ov[2], ov[3], wh[1], wl[1]);
        *(uint2*)(oh + (size_t)row * DD + tid * 4) = make_uint2(wh[0], wh[1]);
        *(uint2*)(ol + (size_t)row * DD + tid * 4) = make_uint2(wl[0], wl[1]);
    }
}

// ===================== launch =====================
extern "C" void kernel_launch(void* const* d_in, const int* in_sizes, int n_in,
                              void* d_out, int out_size)
{
    (void)in_sizes; (void)n_in; (void)out_size;

    const float* x     = (const float*)d_in[0];
    const float* Wq    = (const float*)d_in[1];
    const float* Wk    = (const float*)d_in[2];
    const float* Wv    = (const float*)d_in[3];
    const float* Wo    = (const float*)d_in[4];
    const float* g1    = (const float*)d_in[5];
    const float* be1   = (const float*)d_in[6];
    const float* w_in  = (const float*)d_in[7];
    const float* b_in  = (const float*)d_in[8];
    const float* w_out = (const float*)d_in[9];
    const float* b_out = (const float*)d_in[10];
    const float* g2    = (const float*)d_in[11];
    const float* be2   = (const float*)d_in[12];
    float* out = (float*)d_out;

    float *tmp, *x1;
    __nv_bfloat16 *qkvh, *qkvl, *xh, *xl, *ah, *al, *x1h, *x1l, *h1h, *h1l;
    __nv_bfloat16 *wqkvh, *wqkvl, *woh, *wol, *winh, *winl, *wouth, *woutl;
    cudaGetSymbolAddress((void**)&tmp,  g_tmp);
    cudaGetSymbolAddress((void**)&x1,   g_x1);
    cudaGetSymbolAddress((void**)&qkvh, g_qkvh);  cudaGetSymbolAddress((void**)&qkvl, g_qkvl);
    cudaGetSymbolAddress((void**)&xh,   g_xh);    cudaGetSymbolAddress((void**)&xl,   g_xl);
    cudaGetSymbolAddress((void**)&ah,   g_ah);    cudaGetSymbolAddress((void**)&al,   g_al);
    cudaGetSymbolAddress((void**)&x1h,  g_x1h);   cudaGetSymbolAddress((void**)&x1l,  g_x1l);
    cudaGetSymbolAddress((void**)&h1h,  g_h1h);   cudaGetSymbolAddress((void**)&h1l,  g_h1l);
    cudaGetSymbolAddress((void**)&wqkvh, g_wqkvh); cudaGetSymbolAddress((void**)&wqkvl, g_wqkvl);
    cudaGetSymbolAddress((void**)&woh,   g_woh);   cudaGetSymbolAddress((void**)&wol,   g_wol);
    cudaGetSymbolAddress((void**)&winh,  g_winh);  cudaGetSymbolAddress((void**)&winl,  g_winl);
    cudaGetSymbolAddress((void**)&wouth, g_wouth); cudaGetSymbolAddress((void**)&woutl, g_woutl);

    cudaFuncSetAttribute(flash_tc_kernel, cudaFuncAttributeMaxDynamicSharedMemorySize, FA_SMEM);
    cudaFuncSetAttribute(gemm_tc_kernel<false,false,false,true>, cudaFuncAttributeMaxDynamicSharedMemorySize, GT_SMEM);
    cudaFuncSetAttribute(gemm_tc_kernel<false,false,true,false>, cudaFuncAttributeMaxDynamicSharedMemorySize, GT_SMEM);
    cudaFuncSetAttribute(gemm_tc_kernel<true,true,false,true>,   cudaFuncAttributeMaxDynamicSharedMemorySize, GT_SMEM);
    cudaFuncSetAttribute(gemm_tc_kernel<true,false,true,false>,  cudaFuncAttributeMaxDynamicSharedMemorySize, GT_SMEM);

    // ---- prep: split x; transpose+split weights ----
    fsplit_kernel<<<MM*DD/1024, 256>>>(x, xh, xl, MM*DD/4);
    qkvT_kernel<<<dim3(2, 32, 48), dim3(32, 8)>>>(Wq, Wk, Wv, wqkvh, wqkvl);
    wsplit3_kernel<<<9216, dim3(32, 8)>>>(Wo, w_in, w_out);

    // ---- 1) fused QKV projection -> split bf16 hi/lo directly ----
    gemm_tc_kernel<false,false,false,true><<<dim3(3072/256, MM/128), 512, GT_SMEM>>>(
        xh, xl, wqkvh, wqkvl, nullptr, nullptr, qkvh, qkvl, MM, 3072, 1024);

    // ---- 2) causal flash attention (tensor cores, bf16x3, paired tiles) ----
    flash_tc_kernel<<<dim3(SS/256, BB*HH), 256, FA_SMEM>>>();

    // ---- 3) output projection ----
    gemm_tc_kernel<false,false,true,false><<<dim3(1024/256, MM/128), 512, GT_SMEM>>>(
        ah, al, woh, wol, nullptr, tmp, nullptr, nullptr, MM, 1024, 1024);

    // ---- 4) LN1 (x + attn@Wo), also split to bf16 ----
    ln_kernel<true><<<MM, 256>>>(x, tmp, g1, be1, x1, x1h, x1l);

    // ---- 5) FFN up + bias + ReLU, split output ----
    gemm_tc_kernel<true,true,false,true><<<dim3(4096/256, MM/128), 512, GT_SMEM>>>(
        x1h, x1l, winh, winl, b_in, nullptr, h1h, h1l, MM, 4096, 1024);

    // ---- 6) FFN down + bias ----
    gemm_tc_kernel<true,false,true,false><<<dim3(1024/256, MM/128), 512, GT_SMEM>>>(
        h1h, h1l, wouth, woutl, b_out, tmp, nullptr, nullptr, MM, 1024, 4096);

    // ---- 7) LN2 -> output ----
    ln_kernel<false><<<MM, 256>>>(x1, tmp, g2, be2, out, nullptr, nullptr);
}

// round 8
// speedup vs baseline: 2.7918x; 1.1533x over previous
#include <cuda_runtime.h>
#include <cuda_bf16.h>
#include <math.h>

// Problem constants
#define BB   4
#define SS   2048
#define DD   1024
#define HH   16
#define HDIM 64
#define FF   4096
#define MM   (BB*SS)   // 8192 rows
#define LN_EPS 1e-5f

// ===================== low-level helpers =====================
__device__ __forceinline__ unsigned int smem_u32(const void* p) {
    unsigned int a;
    asm("{ .reg .u64 t; cvta.to.shared.u64 t, %1; cvt.u32.u64 %0, t; }" : "=r"(a) : "l"(p));
    return a;
}
__device__ __forceinline__ void cp16(unsigned int s, const void* g) {
    asm volatile("cp.async.cg.shared.global [%0], [%1], 16;" :: "r"(s), "l"(g));
}
#define CP_COMMIT() asm volatile("cp.async.commit_group;" ::: "memory")
#define CP_WAIT1()  asm volatile("cp.async.wait_group 1;" ::: "memory")
#define CP_WAIT0()  asm volatile("cp.async.wait_group 0;" ::: "memory")

__device__ __forceinline__ void ldsm4(unsigned int* r, unsigned int addr) {
    asm volatile("ldmatrix.sync.aligned.m8n8.x4.shared.b16 {%0,%1,%2,%3}, [%4];"
        : "=r"(r[0]), "=r"(r[1]), "=r"(r[2]), "=r"(r[3]) : "r"(addr));
}
__device__ __forceinline__ void ldsm4t(unsigned int* r, unsigned int addr) {
    asm volatile("ldmatrix.sync.aligned.m8n8.x4.trans.shared.b16 {%0,%1,%2,%3}, [%4];"
        : "=r"(r[0]), "=r"(r[1]), "=r"(r[2]), "=r"(r[3]) : "r"(addr));
}
__device__ __forceinline__ void mma_bf16(float* c, const unsigned int* a,
                                         unsigned int b0, unsigned int b1) {
    asm volatile("mma.sync.aligned.m16n8k16.row.col.f32.bf16.bf16.f32 "
        "{%0,%1,%2,%3}, {%4,%5,%6,%7}, {%8,%9}, {%0,%1,%2,%3};"
        : "+f"(c[0]), "+f"(c[1]), "+f"(c[2]), "+f"(c[3])
        : "r"(a[0]), "r"(a[1]), "r"(a[2]), "r"(a[3]), "r"(b0), "r"(b1));
}
__device__ __forceinline__ unsigned int pack_bf16(__nv_bfloat16 a, __nv_bfloat16 b) {
    return (unsigned int)__bfloat16_as_ushort(a) | ((unsigned int)__bfloat16_as_ushort(b) << 16);
}
__device__ __forceinline__ void split2(float v0, float v1, unsigned int& hi, unsigned int& lo) {
    __nv_bfloat16 h0 = __float2bfloat16(v0);
    __nv_bfloat16 h1 = __float2bfloat16(v1);
    __nv_bfloat16 l0 = __float2bfloat16(v0 - __bfloat162float(h0));
    __nv_bfloat16 l1 = __float2bfloat16(v1 - __bfloat162float(h1));
    hi = pack_bf16(h0, h1);
    lo = pack_bf16(l0, l1);
}

// ===================== scratch (device globals) =====================
__device__ __nv_bfloat16 g_qkvh[(size_t)MM*3072], g_qkvl[(size_t)MM*3072];
__device__ __nv_bfloat16 g_xh[(size_t)MM*DD],  g_xl[(size_t)MM*DD];
__device__ __nv_bfloat16 g_ah[(size_t)MM*DD],  g_al[(size_t)MM*DD];
__device__ float g_tmp[(size_t)MM*DD];
__device__ float g_x1[(size_t)MM*DD];
__device__ __nv_bfloat16 g_x1h[(size_t)MM*DD], g_x1l[(size_t)MM*DD];
__device__ __nv_bfloat16 g_h1h[(size_t)MM*FF], g_h1l[(size_t)MM*FF];
// transposed + split weights ([N,K] row-major bf16)
__device__ __nv_bfloat16 g_wqkvh[(size_t)3072*1024], g_wqkvl[(size_t)3072*1024];
__device__ __nv_bfloat16 g_woh[(size_t)1024*1024],   g_wol[(size_t)1024*1024];
__device__ __nv_bfloat16 g_winh[(size_t)4096*1024],  g_winl[(size_t)4096*1024];
__device__ __nv_bfloat16 g_wouth[(size_t)1024*4096], g_woutl[(size_t)1024*4096];

// ===================== prep kernels =====================
__global__ void fsplit_kernel(const float* __restrict__ in,
                              __nv_bfloat16* __restrict__ h,
                              __nv_bfloat16* __restrict__ l, int n4)
{
    int i = blockIdx.x * blockDim.x + threadIdx.x;
    if (i >= n4) return;
    float4 v = ((const float4*)in)[i];
    unsigned int ph[2], pl[2];
    split2(v.x, v.y, ph[0], pl[0]);
    split2(v.z, v.w, ph[1], pl[1]);
    ((uint2*)h)[i] = make_uint2(ph[0], ph[1]);
    ((uint2*)l)[i] = make_uint2(pl[0], pl[1]);
}

// transpose+split one 32x32 block of W [K,N] -> T [N,K]
__device__ __forceinline__ void wsplit_block(const float* __restrict__ W,
                                             __nv_bfloat16* __restrict__ Th,
                                             __nv_bfloat16* __restrict__ Tl,
                                             int K, int N, int k0, int n0,
                                             float t[32][33])
{
    int tx = threadIdx.x, ty = threadIdx.y;
    #pragma unroll
    for (int i = 0; i < 32; i += 8)
        t[ty + i][tx] = W[(size_t)(k0 + ty + i) * N + n0 + tx];
    __syncthreads();
    #pragma unroll
    for (int i = 0; i < 32; i += 8) {
        float v = t[tx][ty + i];
        __nv_bfloat16 h = __float2bfloat16(v);
        size_t o = (size_t)(n0 + ty + i) * K + k0 + tx;
        Th[o] = h;
        Tl[o] = __float2bfloat16(v - __bfloat162float(h));
    }
}

// merged: Wo (1024 blocks), w_in (4096), w_out (4096) -> 9216 blocks linear
__global__ void wsplit3_kernel(const float* __restrict__ Wo,
                               const float* __restrict__ Win,
                               const float* __restrict__ Wout)
{
    __shared__ float t[32][33];
    int idx = blockIdx.x;
    if (idx < 1024) {
        wsplit_block(Wo, g_woh, g_wol, 1024, 1024,
                     (idx >> 5) * 32, (idx & 31) * 32, t);
    } else if (idx < 1024 + 4096) {
        int i2 = idx - 1024;
        wsplit_block(Win, g_winh, g_winl, 1024, 4096,
                     (i2 >> 7) * 32, (i2 & 127) * 32, t);
    } else {
        int i2 = idx - 5120;
        wsplit_block(Wout, g_wouth, g_woutl, 4096, 1024,
                     (i2 >> 5) * 32, (i2 & 31) * 32, t);
    }
}

__global__ void qkvT_kernel(const float* __restrict__ Wq,
                            const float* __restrict__ Wk,
                            const float* __restrict__ Wv,
                            __nv_bfloat16* __restrict__ Th,
                            __nv_bfloat16* __restrict__ Tl)
{
    __shared__ float t[32][33];
    int z = blockIdx.z;
    int mat = z / HH, h = z - mat * HH;
    const float* W = (mat == 0 ? Wq : mat == 1 ? Wk : Wv) + (size_t)h * DD * HDIM;
    int k0 = blockIdx.y * 32, e0 = blockIdx.x * 32;
    int tx = threadIdx.x, ty = threadIdx.y;
    #pragma unroll
    for (int i = 0; i < 32; i += 8)
        t[ty + i][tx] = W[(size_t)(k0 + ty + i) * HDIM + e0 + tx];
    __syncthreads();
    int nbase = mat * 1024 + h * HDIM;
    #pragma unroll
    for (int i = 0; i < 32; i += 8) {
        float v = t[tx][ty + i];
        __nv_bfloat16 hv = __float2bfloat16(v);
        size_t o = (size_t)(nbase + e0 + ty + i) * DD + k0 + tx;
        Th[o] = hv;
        Tl[o] = __float2bfloat16(v - __bfloat162float(hv));
    }
}

// ===================== mma.sync bf16x3 GEMM =====================
// Block 128x256, K-chunk 64, 2-stage cp.async pipeline, 16 warps, warp 64x32.
// SW128-swizzled smem rows (128B data, no pad): conflict-free ldmatrix.
#define OFF_AH 0
#define OFF_AL 16384
#define OFF_BH 32768
#define OFF_BL 65536
#define STG_B  98304
#define GT_SMEM (2*STG_B)      // 196608

// swizzled byte offset for (row, 16B-chunk ck) within a 128B-row matrix
#define GSW(r, ck) ((unsigned int)((r) * 128 + ((((ck) ^ ((r) & 7))) << 4)))

template<bool BIAS, bool RELU, bool F32OUT, bool SPLIT>
__global__ void __launch_bounds__(512, 1) gemm_tc_kernel(
    const __nv_bfloat16* __restrict__ Ah, const __nv_bfloat16* __restrict__ Al,
    const __nv_bfloat16* __restrict__ BTh, const __nv_bfloat16* __restrict__ BTl,
    const float* __restrict__ bias,
    float* __restrict__ C,
    __nv_bfloat16* __restrict__ Ch, __nv_bfloat16* __restrict__ Cl,
    int M, int N, int K)
{
    extern __shared__ __align__(128) char smem[];
    const unsigned int sb = smem_u32(smem);
    const int tid = threadIdx.x;
    const int row0 = blockIdx.y * 128;
    const int col0 = blockIdx.x * 256;

    const int wid = tid >> 5, lane = tid & 31;
    const int wm0 = (wid & 1) * 64, wn0 = (wid >> 1) * 32;
    const int lr = lane & 15, lh = lane >> 4;

    auto load_stage = [&](int c, int s) {
        unsigned int base = sb + s * STG_B;
        int k0 = c * 64;
        #pragma unroll
        for (int i = 0; i < 2; i++) {
            int lin = tid + (i << 9);            // 0..1023 : A rows 0..127, 8 chunks
            int r = lin >> 3, ck = lin & 7;
            unsigned int so = GSW(r, ck);
            size_t ga = (size_t)(row0 + r) * K + k0 + ck * 8;
            cp16(base + OFF_AH + so, Ah + ga);
            cp16(base + OFF_AL + so, Al + ga);
        }
        #pragma unroll
        for (int i = 0; i < 4; i++) {
            int lin = tid + (i << 9);            // 0..2047 : B rows 0..255, 8 chunks
            int r = lin >> 3, ck = lin & 7;
            unsigned int so = GSW(r, ck);
            size_t gb = (size_t)(col0 + r) * K + k0 + ck * 8;
            cp16(base + OFF_BH + so, BTh + gb);
            cp16(base + OFF_BL + so, BTl + gb);
        }
        CP_COMMIT();
    };

    float acc[4][4][4] = {};

    load_stage(0, 0);
    load_stage(1, 1);

    const int NC = K >> 6;
    for (int c = 0; c < NC; c++) {
        CP_WAIT1();
        __syncthreads();

        unsigned int base = sb + (c & 1) * STG_B;
        #pragma unroll
        for (int ks = 0; ks < 4; ks++) {
            unsigned int a_h[4][4], a_l[4][4], b_h[2][4], b_l[2][4];
            #pragma unroll
            for (int mt = 0; mt < 4; mt++) {
                int r = wm0 + mt*16 + lr;
                unsigned int ro = GSW(r, ks*2 + lh);
                ldsm4(a_h[mt], base + OFF_AH + ro);
                ldsm4(a_l[mt], base + OFF_AL + ro);
            }
            #pragma unroll
            for (int bt = 0; bt < 2; bt++) {
                int r = wn0 + bt*16 + lr;
                unsigned int ro = GSW(r, ks*2 + lh);
                ldsm4(b_h[bt], base + OFF_BH + ro);
                ldsm4(b_l[bt], base + OFF_BL + ro);
            }
            #pragma unroll
            for (int mt = 0; mt < 4; mt++) {
                #pragma unroll
                for (int nt = 0; nt < 4; nt++) {
                    int bt = nt >> 1, hf = nt & 1;
                    mma_bf16(acc[mt][nt], a_h[mt], b_h[bt][hf], b_h[bt][hf+2]);
                    mma_bf16(acc[mt][nt], a_l[mt], b_h[bt][hf], b_h[bt][hf+2]);
                    mma_bf16(acc[mt][nt], a_h[mt], b_l[bt][hf], b_l[bt][hf+2]);
                }
            }
        }

        __syncthreads();
        if (c + 2 < NC) load_stage(c + 2, c & 1);
    }

    // ---- epilogue (register fragments -> gmem) ----
    const int gq = lane >> 2, pq = lane & 3;
    #pragma unroll
    for (int mt = 0; mt < 4; mt++) {
        #pragma unroll
        for (int nt = 0; nt < 4; nt++) {
            int col = col0 + wn0 + nt*8 + pq*2;
            float b0 = 0.f, b1 = 0.f;
            if (BIAS) { b0 = bias[col]; b1 = bias[col+1]; }
            #pragma unroll
            for (int h2 = 0; h2 < 2; h2++) {
                int row = row0 + wm0 + mt*16 + gq + h2*8;
                float v0 = acc[mt][nt][h2*2+0] + b0;
                float v1 = acc[mt][nt][h2*2+1] + b1;
                if (RELU) { v0 = fmaxf(v0, 0.f); v1 = fmaxf(v1, 0.f); }
                if (F32OUT)
                    *(float2*)(C + (size_t)row * N + col) = make_float2(v0, v1);
                if (SPLIT) {
                    unsigned int hi, lo;
                    split2(v0, v1, hi, lo);
                    *(unsigned int*)(Ch + (size_t)row * N + col) = hi;
                    *(unsigned int*)(Cl + (size_t)row * N + col) = lo;
                }
            }
        }
    }
}

// ===================== tensor-core causal flash attention (bf16x3) ============
// CTA: 256 threads / 8 warps; processes TWO paired q-tiles of 128 rows each
// (qt0 = pid and 15-pid) for uniform work. K/V tiles 64x64, double-buffered.
#define AP 144
#define KMAT 9216              // 64*AP
#define QMAT 18432             // 128*AP
#define FA_Q (2*QMAT)          // 36864
#define FA_STG (4*KMAT)        // 36864
#define FA_SMEM (FA_Q + 2*FA_STG)   // 110592

__global__ void __launch_bounds__(256, 1) flash_tc_kernel()
{
    const int pid = blockIdx.x, bh = blockIdx.y;
    const int b = bh >> 4, h = bh & 15;
    const int tid = threadIdx.x, wid = tid >> 5, lane = tid & 31;
    const int wm = wid * 16;
    const int lr = lane & 15, lh = lane >> 4;

    extern __shared__ __align__(16) char smem[];
    const unsigned int sb = smem_u32(smem);
    const unsigned int sQh = sb, sQl = sb + QMAT;

    for (int run = 0; run < 2; run++) {
        const int qt0 = run ? (15 - pid) : pid;
        const int NKT = 2 * qt0 + 2;

        __syncthreads();   // previous run fully done with smem

        // ---- load Q tile (128 rows, hi/lo) ----
        {
            const __nv_bfloat16* qh = g_qkvh + (size_t)(b*SS + qt0*128)*3072 + h*HDIM;
            const __nv_bfloat16* ql = g_qkvl + (size_t)(b*SS + qt0*128)*3072 + h*HDIM;
            #pragma unroll
            for (int i = 0; i < 4; i++) {
                int lin = tid + (i << 8);
                int r = lin >> 3, ck = lin & 7;
                unsigned int so = r*AP + ck*16;
                size_t g = (size_t)r*3072 + ck*8;
                cp16(sQh + so, qh + g);
                cp16(sQl + so, ql + g);
            }
            CP_COMMIT();
        }

        auto load_kv = [&](int kt, int s) {
            unsigned int base = sb + FA_Q + s * FA_STG;
            size_t rowb = (size_t)(b*SS + kt*64)*3072;
            const __nv_bfloat16* kh = g_qkvh + rowb + 1024 + h*HDIM;
            const __nv_bfloat16* kl = g_qkvl + rowb + 1024 + h*HDIM;
            const __nv_bfloat16* vh = g_qkvh + rowb + 2048 + h*HDIM;
            const __nv_bfloat16* vl = g_qkvl + rowb + 2048 + h*HDIM;
            #pragma unroll
            for (int i = 0; i < 2; i++) {
                int lin = tid + (i << 8);
                int r = lin >> 3, ck = lin & 7;
                unsigned int so = r*AP + ck*16;
                size_t g = (size_t)r*3072 + ck*8;
                cp16(base + so,          kh + g);
                cp16(base + KMAT + so,   kl + g);
                cp16(base + 2*KMAT + so, vh + g);
                cp16(base + 3*KMAT + so, vl + g);
            }
            CP_COMMIT();
        };

        load_kv(0, 0);
        load_kv(1, 1);

        float o[8][4] = {};
        float m0 = -1e30f, m1 = -1e30f, l0 = 0.f, l1 = 0.f;

        for (int kt = 0; kt < NKT; kt++) {
            if (kt < NKT - 1) CP_WAIT1(); else CP_WAIT0();
            __syncthreads();

            const unsigned int kb = sb + FA_Q + (kt & 1) * FA_STG;

            // ---- S = Q K^T (bf16x3) ----
            float sc[8][4] = {};
            #pragma unroll
            for (int kd = 0; kd < 4; kd++) {
                unsigned int aqh[4], aql[4];
                unsigned int qro = (unsigned int)(wm + lr)*AP + (kd*2 + lh)*16;
                ldsm4(aqh, sQh + qro);
                ldsm4(aql, sQl + qro);
                #pragma unroll
                for (int g = 0; g < 4; g++) {
                    unsigned int rkh[4], rkl[4];
                    unsigned int kro = (unsigned int)(g*16 + lr)*AP + (kd*2 + lh)*16;
                    ldsm4(rkh, kb + kro);
                    ldsm4(rkl, kb + KMAT + kro);
                    mma_bf16(sc[2*g],   aqh, rkh[0], rkh[2]);
                    mma_bf16(sc[2*g+1], aqh, rkh[1], rkh[3]);
                    mma_bf16(sc[2*g],   aqh, rkl[0], rkl[2]);
                    mma_bf16(sc[2*g+1], aqh, rkl[1], rkl[3]);
                    mma_bf16(sc[2*g],   aql, rkh[0], rkh[2]);
                    mma_bf16(sc[2*g+1], aql, rkh[1], rkh[3]);
                }
            }

            // ---- scale + causal mask ----
            if (kt >= 2*qt0) {
                const int grow0 = qt0*128 + wm + (lane >> 2);
                const int gc0 = kt*64 + (lane & 3)*2;
                #pragma unroll
                for (int nt = 0; nt < 8; nt++) {
                    int c0l = gc0 + nt*8;
                    sc[nt][0] = (c0l     > grow0)   ? -1e30f : sc[nt][0]*0.125f;
                    sc[nt][1] = (c0l + 1 > grow0)   ? -1e30f : sc[nt][1]*0.125f;
                    sc[nt][2] = (c0l     > grow0+8) ? -1e30f : sc[nt][2]*0.125f;
                    sc[nt][3] = (c0l + 1 > grow0+8) ? -1e30f : sc[nt][3]*0.125f;
                }
            } else {
                #pragma unroll
                for (int nt = 0; nt < 8; nt++) {
                    sc[nt][0] *= 0.125f; sc[nt][1] *= 0.125f;
                    sc[nt][2] *= 0.125f; sc[nt][3] *= 0.125f;
                }
            }

            // ---- online softmax ----
            float mx0 = -1e30f, mx1 = -1e30f;
            #pragma unroll
            for (int nt = 0; nt < 8; nt++) {
                mx0 = fmaxf(mx0, fmaxf(sc[nt][0], sc[nt][1]));
                mx1 = fmaxf(mx1, fmaxf(sc[nt][2], sc[nt][3]));
            }
            mx0 = fmaxf(mx0, __shfl_xor_sync(0xffffffffu, mx0, 1));
            mx0 = fmaxf(mx0, __shfl_xor_sync(0xffffffffu, mx0, 2));
            mx1 = fmaxf(mx1, __shfl_xor_sync(0xffffffffu, mx1, 1));
            mx1 = fmaxf(mx1, __shfl_xor_sync(0xffffffffu, mx1, 2));
            float mn0 = fmaxf(m0, mx0), mn1 = fmaxf(m1, mx1);
            float cf0 = __expf(m0 - mn0), cf1 = __expf(m1 - mn1);
            m0 = mn0; m1 = mn1;
            float s0 = 0.f, s1 = 0.f;
            #pragma unroll
            for (int nt = 0; nt < 8; nt++) {
                sc[nt][0] = __expf(sc[nt][0] - mn0);
                sc[nt][1] = __expf(sc[nt][1] - mn0);
                sc[nt][2] = __expf(sc[nt][2] - mn1);
                sc[nt][3] = __expf(sc[nt][3] - mn1);
                s0 += sc[nt][0] + sc[nt][1];
                s1 += sc[nt][2] + sc[nt][3];
            }
            s0 += __shfl_xor_sync(0xffffffffu, s0, 1);
            s0 += __shfl_xor_sync(0xffffffffu, s0, 2);
            s1 += __shfl_xor_sync(0xffffffffu, s1, 1);
            s1 += __shfl_xor_sync(0xffffffffu, s1, 2);
            l0 = l0 * cf0 + s0;
            l1 = l1 * cf1 + s1;
            #pragma unroll
            for (int dt = 0; dt < 8; dt++) {
                o[dt][0] *= cf0; o[dt][1] *= cf0;
                o[dt][2] *= cf1; o[dt][3] *= cf1;
            }

            // ---- O += P V (bf16x3, P fragments from registers) ----
            #pragma unroll
            for (int j = 0; j < 4; j++) {
                unsigned int ph[4], pl[4];
                split2(sc[2*j][0],   sc[2*j][1],   ph[0], pl[0]);
                split2(sc[2*j][2],   sc[2*j][3],   ph[1], pl[1]);
                split2(sc[2*j+1][0], sc[2*j+1][1], ph[2], pl[2]);
                split2(sc[2*j+1][2], sc[2*j+1][3], ph[3], pl[3]);
                #pragma unroll
                for (int g = 0; g < 4; g++) {
                    unsigned int rvh[4], rvl[4];
                    unsigned int vro = (unsigned int)(j*16 + lr)*AP + (g*2 + lh)*16;
                    ldsm4t(rvh, kb + 2*KMAT + vro);
                    ldsm4t(rvl, kb + 3*KMAT + vro);
                    mma_bf16(o[2*g],   ph, rvh[0], rvh[1]);
                    mma_bf16(o[2*g+1], ph, rvh[2], rvh[3]);
                    mma_bf16(o[2*g],   ph, rvl[0], rvl[1]);
                    mma_bf16(o[2*g+1], ph, rvl[2], rvl[3]);
                    mma_bf16(o[2*g],   pl, rvh[0], rvh[1]);
                    mma_bf16(o[2*g+1], pl, rvh[2], rvh[3]);
                }
            }

            __syncthreads();
            if (kt + 2 < NKT) load_kv(kt + 2, kt & 1);
        }

        // ---- epilogue: normalize, split to bf16 hi/lo ----
        const float inv0 = 1.f / l0, inv1 = 1.f / l1;
        const int row0g = qt0*128 + wm + (lane >> 2);
        __nv_bfloat16* ohp = g_ah + ((size_t)bh*SS)*HDIM;
        __nv_bfloat16* olp = g_al + ((size_t)bh*SS)*HDIM;
        #pragma unroll
        for (int dt = 0; dt < 8; dt++) {
            int d = dt*8 + (lane & 3)*2;
            unsigned int hi, lo;
            split2(o[dt][0]*inv0, o[dt][1]*inv0, hi, lo);
            *(unsigned int*)(ohp + (size_t)row0g*HDIM + d) = hi;
            *(unsigned int*)(olp + (size_t)row0g*HDIM + d) = lo;
            split2(o[dt][2]*inv1, o[dt][3]*inv1, hi, lo);
            *(unsigned int*)(ohp + (size_t)(row0g+8)*HDIM + d) = hi;
            *(unsigned int*)(olp + (size_t)(row0g+8)*HDIM + d) = lo;
        }
    }
}

// ===================== LayerNorm =====================
__device__ __forceinline__ float blk_sum(float v, float* sred)
{
    #pragma unroll
    for (int o = 16; o; o >>= 1) v += __shfl_xor_sync(0xffffffffu, v, o);
    int w = threadIdx.x >> 5;
    if ((threadIdx.x & 31) == 0) sred[w] = v;
    __syncthreads();
    float t = (threadIdx.x < 8) ? sred[threadIdx.x] : 0.f;
    if (threadIdx.x < 32) {
        #pragma unroll
        for (int o = 4; o; o >>= 1) t += __shfl_xor_sync(0xffffffffu, t, o);
        if (threadIdx.x == 0) sred[0] = t;
    }
    __syncthreads();
    float r = sred[0];
    __syncthreads();
    return r;
}

template<bool SPLIT>
__global__ void ln_kernel(const float* __restrict__ resid,
                          const float* __restrict__ y,
                          const float* __restrict__ gamma,
                          const float* __restrict__ beta,
                          float* __restrict__ outf,
                          __nv_bfloat16* __restrict__ oh,
                          __nv_bfloat16* __restrict__ ol)
{
    __shared__ float sred[32];
    const int row = blockIdx.x;
    const int tid = threadIdx.x;

    float4 a = ((const float4*)(resid + (size_t)row * DD))[tid];
    float4 b = ((const float4*)(y     + (size_t)row * DD))[tid];
    float4 v = make_float4(a.x + b.x, a.y + b.y, a.z + b.z, a.w + b.w);

    float total = blk_sum(v.x + v.y + v.z + v.w, sred);
    float mu = total * (1.f / DD);

    float dx = v.x - mu, dy = v.y - mu, dz = v.z - mu, dw = v.w - mu;
    float tot2 = blk_sum(dx*dx + dy*dy + dz*dz + dw*dw, sred);
    float inv = rsqrtf(tot2 * (1.f / DD) + LN_EPS);

    float4 g = ((const float4*)gamma)[tid];
    float4 be = ((const float4*)beta)[tid];
    float ov[4];
    ov[0] = dx * inv * g.x + be.x;
    ov[1] = dy * inv * g.y + be.y;
    ov[2] = dz * inv * g.z + be.z;
    ov[3] = dw * inv * g.w + be.w;
    ((float4*)(outf + (size_t)row * DD))[tid] = make_float4(ov[0], ov[1], ov[2], ov[3]);

    if (SPLIT) {
        unsigned int wh[2], wl[2];
        split2(ov[0], ov[1], wh[0], wl[0]);
        split2(ov[2], ov[3], wh[1], wl[1]);
        *(uint2*)(oh + (size_t)row * DD + tid * 4) = make_uint2(wh[0], wh[1]);
        *(uint2*)(ol + (size_t)row * DD + tid * 4) = make_uint2(wl[0], wl[1]);
    }
}

// ===================== launch =====================
extern "C" void kernel_launch(void* const* d_in, const int* in_sizes, int n_in,
                              void* d_out, int out_size)
{
    (void)in_sizes; (void)n_in; (void)out_size;

    const float* x     = (const float*)d_in[0];
    const float* Wq    = (const float*)d_in[1];
    const float* Wk    = (const float*)d_in[2];
    const float* Wv    = (const float*)d_in[3];
    const float* Wo    = (const float*)d_in[4];
    const float* g1    = (const float*)d_in[5];
    const float* be1   = (const float*)d_in[6];
    const float* w_in  = (const float*)d_in[7];
    const float* b_in  = (const float*)d_in[8];
    const float* w_out = (const float*)d_in[9];
    const float* b_out = (const float*)d_in[10];
    const float* g2    = (const float*)d_in[11];
    const float* be2   = (const float*)d_in[12];
    float* out = (float*)d_out;

    float *tmp, *x1;
    __nv_bfloat16 *qkvh, *qkvl, *xh, *xl, *ah, *al, *x1h, *x1l, *h1h, *h1l;
    __nv_bfloat16 *wqkvh, *wqkvl, *woh, *wol, *winh, *winl, *wouth, *woutl;
    cudaGetSymbolAddress((void**)&tmp,  g_tmp);
    cudaGetSymbolAddress((void**)&x1,   g_x1);
    cudaGetSymbolAddress((void**)&qkvh, g_qkvh);  cudaGetSymbolAddress((void**)&qkvl, g_qkvl);
    cudaGetSymbolAddress((void**)&xh,   g_xh);    cudaGetSymbolAddress((void**)&xl,   g_xl);
    cudaGetSymbolAddress((void**)&ah,   g_ah);    cudaGetSymbolAddress((void**)&al,   g_al);
    cudaGetSymbolAddress((void**)&x1h,  g_x1h);   cudaGetSymbolAddress((void**)&x1l,  g_x1l);
    cudaGetSymbolAddress((void**)&h1h,  g_h1h);   cudaGetSymbolAddress((void**)&h1l,  g_h1l);
    cudaGetSymbolAddress((void**)&wqkvh, g_wqkvh); cudaGetSymbolAddress((void**)&wqkvl, g_wqkvl);
    cudaGetSymbolAddress((void**)&woh,   g_woh);   cudaGetSymbolAddress((void**)&wol,   g_wol);
    cudaGetSymbolAddress((void**)&winh,  g_winh);  cudaGetSymbolAddress((void**)&winl,  g_winl);
    cudaGetSymbolAddress((void**)&wouth, g_wouth); cudaGetSymbolAddress((void**)&woutl, g_woutl);

    cudaFuncSetAttribute(flash_tc_kernel, cudaFuncAttributeMaxDynamicSharedMemorySize, FA_SMEM);
    cudaFuncSetAttribute(gemm_tc_kernel<false,false,false,true>, cudaFuncAttributeMaxDynamicSharedMemorySize, GT_SMEM);
    cudaFuncSetAttribute(gemm_tc_kernel<false,false,true,false>, cudaFuncAttributeMaxDynamicSharedMemorySize, GT_SMEM);
    cudaFuncSetAttribute(gemm_tc_kernel<true,true,false,true>,   cudaFuncAttributeMaxDynamicSharedMemorySize, GT_SMEM);
    cudaFuncSetAttribute(gemm_tc_kernel<true,false,true,false>,  cudaFuncAttributeMaxDynamicSharedMemorySize, GT_SMEM);

    // ---- prep: split x; transpose+split weights ----
    fsplit_kernel<<<MM*DD/1024, 256>>>(x, xh, xl, MM*DD/4);
    qkvT_kernel<<<dim3(2, 32, 48), dim3(32, 8)>>>(Wq, Wk, Wv, wqkvh, wqkvl);
    wsplit3_kernel<<<9216, dim3(32, 8)>>>(Wo, w_in, w_out);

    // ---- 1) fused QKV projection -> split bf16 hi/lo directly ----
    gemm_tc_kernel<false,false,false,true><<<dim3(3072/256, MM/128), 512, GT_SMEM>>>(
        xh, xl, wqkvh, wqkvl, nullptr, nullptr, qkvh, qkvl, MM, 3072, 1024);

    // ---- 2) causal flash attention (tensor cores, bf16x3, paired tiles) ----
    flash_tc_kernel<<<dim3(SS/256, BB*HH), 256, FA_SMEM>>>();

    // ---- 3) output projection ----
    gemm_tc_kernel<false,false,true,false><<<dim3(1024/256, MM/128), 512, GT_SMEM>>>(
        ah, al, woh, wol, nullptr, tmp, nullptr, nullptr, MM, 1024, 1024);

    // ---- 4) LN1 (x + attn@Wo), also split to bf16 ----
    ln_kernel<true><<<MM, 256>>>(x, tmp, g1, be1, x1, x1h, x1l);

    // ---- 5) FFN up + bias + ReLU, split output ----
    gemm_tc_kernel<true,true,false,true><<<dim3(4096/256, MM/128), 512, GT_SMEM>>>(
        x1h, x1l, winh, winl, b_in, nullptr, h1h, h1l, MM, 4096, 1024);

    // ---- 6) FFN down + bias ----
    gemm_tc_kernel<true,false,true,false><<<dim3(1024/256, MM/128), 512, GT_SMEM>>>(
        h1h, h1l, wouth, woutl, b_out, tmp, nullptr, nullptr, MM, 1024, 4096);

    // ---- 7) LN2 -> output ----
    ln_kernel<false><<<MM, 256>>>(x1, tmp, g2, be2, out, nullptr, nullptr);
}

// round 9
// speedup vs baseline: 3.2601x; 1.1677x over previous
#include <cuda_runtime.h>
#include <cuda_bf16.h>
#include <cuda_fp16.h>
#include <math.h>

// Problem constants
#define BB   4
#define SS   2048
#define DD   1024
#define HH   16
#define HDIM 64
#define FF   4096
#define MM   (BB*SS)   // 8192 rows
#define LN_EPS 1e-5f

// ===================== low-level helpers =====================
__device__ __forceinline__ unsigned int smem_u32(const void* p) {
    unsigned int a;
    asm("{ .reg .u64 t; cvta.to.shared.u64 t, %1; cvt.u32.u64 %0, t; }" : "=r"(a) : "l"(p));
    return a;
}
__device__ __forceinline__ void cp16(unsigned int s, const void* g) {
    asm volatile("cp.async.cg.shared.global [%0], [%1], 16;" :: "r"(s), "l"(g));
}
#define CP_COMMIT() asm volatile("cp.async.commit_group;" ::: "memory")
#define CP_WAIT1()  asm volatile("cp.async.wait_group 1;" ::: "memory")
#define CP_WAIT2()  asm volatile("cp.async.wait_group 2;" ::: "memory")
#define CP_WAIT0()  asm volatile("cp.async.wait_group 0;" ::: "memory")

__device__ __forceinline__ void ldsm4(unsigned int* r, unsigned int addr) {
    asm volatile("ldmatrix.sync.aligned.m8n8.x4.shared.b16 {%0,%1,%2,%3}, [%4];"
        : "=r"(r[0]), "=r"(r[1]), "=r"(r[2]), "=r"(r[3]) : "r"(addr));
}
__device__ __forceinline__ void ldsm4t(unsigned int* r, unsigned int addr) {
    asm volatile("ldmatrix.sync.aligned.m8n8.x4.trans.shared.b16 {%0,%1,%2,%3}, [%4];"
        : "=r"(r[0]), "=r"(r[1]), "=r"(r[2]), "=r"(r[3]) : "r"(addr));
}
__device__ __forceinline__ void mma_bf16(float* c, const unsigned int* a,
                                         unsigned int b0, unsigned int b1) {
    asm volatile("mma.sync.aligned.m16n8k16.row.col.f32.bf16.bf16.f32 "
        "{%0,%1,%2,%3}, {%4,%5,%6,%7}, {%8,%9}, {%0,%1,%2,%3};"
        : "+f"(c[0]), "+f"(c[1]), "+f"(c[2]), "+f"(c[3])
        : "r"(a[0]), "r"(a[1]), "r"(a[2]), "r"(a[3]), "r"(b0), "r"(b1));
}
__device__ __forceinline__ void mma_f16(float* c, const unsigned int* a,
                                        unsigned int b0, unsigned int b1) {
    asm volatile("mma.sync.aligned.m16n8k16.row.col.f32.f16.f16.f32 "
        "{%0,%1,%2,%3}, {%4,%5,%6,%7}, {%8,%9}, {%0,%1,%2,%3};"
        : "+f"(c[0]), "+f"(c[1]), "+f"(c[2]), "+f"(c[3])
        : "r"(a[0]), "r"(a[1]), "r"(a[2]), "r"(a[3]), "r"(b0), "r"(b1));
}
__device__ __forceinline__ unsigned int pack_bf16(__nv_bfloat16 a, __nv_bfloat16 b) {
    return (unsigned int)__bfloat16_as_ushort(a) | ((unsigned int)__bfloat16_as_ushort(b) << 16);
}
__device__ __forceinline__ void split2(float v0, float v1, unsigned int& hi, unsigned int& lo) {
    __nv_bfloat16 h0 = __float2bfloat16(v0);
    __nv_bfloat16 h1 = __float2bfloat16(v1);
    __nv_bfloat16 l0 = __float2bfloat16(v0 - __bfloat162float(h0));
    __nv_bfloat16 l1 = __float2bfloat16(v1 - __bfloat162float(h1));
    hi = pack_bf16(h0, h1);
    lo = pack_bf16(l0, l1);
}
__device__ __forceinline__ unsigned int pack_f16(__half a, __half b) {
    return (unsigned int)__half_as_ushort(a) | ((unsigned int)__half_as_ushort(b) << 16);
}
__device__ __forceinline__ void split2h(float v0, float v1, unsigned int& hi, unsigned int& lo) {
    __half h0 = __float2half(v0);
    __half h1 = __float2half(v1);
    __half l0 = __float2half(v0 - __half2float(h0));
    __half l1 = __float2half(v1 - __half2float(h1));
    hi = pack_f16(h0, h1);
    lo = pack_f16(l0, l1);
}

// ===================== scratch (device globals) =====================
__device__ __nv_bfloat16 g_qkvh[(size_t)MM*3072], g_qkvl[(size_t)MM*3072];
__device__ __nv_bfloat16 g_xh[(size_t)MM*DD],  g_xl[(size_t)MM*DD];
__device__ __nv_bfloat16 g_ah[(size_t)MM*DD],  g_al[(size_t)MM*DD];
__device__ float g_tmp[(size_t)MM*DD];
__device__ float g_x1[(size_t)MM*DD];
__device__ __half g_x1h[(size_t)MM*DD], g_x1l[(size_t)MM*DD];
__device__ __half g_h1h[(size_t)MM*FF], g_h1l[(size_t)MM*FF];
// transposed weights ([N,K] row-major)
__device__ __nv_bfloat16 g_wqkvh[(size_t)3072*1024], g_wqkvl[(size_t)3072*1024];
__device__ __nv_bfloat16 g_woh[(size_t)1024*1024],   g_wol[(size_t)1024*1024];
__device__ __half g_winf[(size_t)4096*1024];   // fp16 single
__device__ __half g_woutf[(size_t)1024*4096];  // fp16 single

// ===================== prep kernels =====================
__global__ void fsplit_kernel(const float* __restrict__ in,
                              __nv_bfloat16* __restrict__ h,
                              __nv_bfloat16* __restrict__ l, int n4)
{
    int i = blockIdx.x * blockDim.x + threadIdx.x;
    if (i >= n4) return;
    float4 v = ((const float4*)in)[i];
    unsigned int ph[2], pl[2];
    split2(v.x, v.y, ph[0], pl[0]);
    split2(v.z, v.w, ph[1], pl[1]);
    ((uint2*)h)[i] = make_uint2(ph[0], ph[1]);
    ((uint2*)l)[i] = make_uint2(pl[0], pl[1]);
}

// transpose+split one 32x32 block of W [K,N] -> bf16 hi/lo T [N,K]
__device__ __forceinline__ void wsplit_block(const float* __restrict__ W,
                                             __nv_bfloat16* __restrict__ Th,
                                             __nv_bfloat16* __restrict__ Tl,
                                             int K, int N, int k0, int n0,
                                             float t[32][33])
{
    int tx = threadIdx.x, ty = threadIdx.y;
    #pragma unroll
    for (int i = 0; i < 32; i += 8)
        t[ty + i][tx] = W[(size_t)(k0 + ty + i) * N + n0 + tx];
    __syncthreads();
    #pragma unroll
    for (int i = 0; i < 32; i += 8) {
        float v = t[tx][ty + i];
        __nv_bfloat16 h = __float2bfloat16(v);
        size_t o = (size_t)(n0 + ty + i) * K + k0 + tx;
        Th[o] = h;
        Tl[o] = __float2bfloat16(v - __bfloat162float(h));
    }
}

// transpose one 32x32 block of W [K,N] -> single fp16 T [N,K]
__device__ __forceinline__ void wsingle_block(const float* __restrict__ W,
                                              __half* __restrict__ T,
                                              int K, int N, int k0, int n0,
                                              float t[32][33])
{
    int tx = threadIdx.x, ty = threadIdx.y;
    #pragma unroll
    for (int i = 0; i < 32; i += 8)
        t[ty + i][tx] = W[(size_t)(k0 + ty + i) * N + n0 + tx];
    __syncthreads();
    #pragma unroll
    for (int i = 0; i < 32; i += 8) {
        float v = t[tx][ty + i];
        T[(size_t)(n0 + ty + i) * K + k0 + tx] = __float2half(v);
    }
}

// merged: Wo bf16 hi/lo (1024 blocks), w_in fp16 (4096), w_out fp16 (4096)
__global__ void wsplit3_kernel(const float* __restrict__ Wo,
                               const float* __restrict__ Win,
                               const float* __restrict__ Wout)
{
    __shared__ float t[32][33];
    int idx = blockIdx.x;
    if (idx < 1024) {
        wsplit_block(Wo, g_woh, g_wol, 1024, 1024,
                     (idx >> 5) * 32, (idx & 31) * 32, t);
    } else if (idx < 1024 + 4096) {
        int i2 = idx - 1024;
        wsingle_block(Win, g_winf, 1024, 4096,
                      (i2 >> 7) * 32, (i2 & 127) * 32, t);
    } else {
        int i2 = idx - 5120;
        wsingle_block(Wout, g_woutf, 4096, 1024,
                      (i2 >> 5) * 32, (i2 & 31) * 32, t);
    }
}

__global__ void qkvT_kernel(const float* __restrict__ Wq,
                            const float* __restrict__ Wk,
                            const float* __restrict__ Wv,
                            __nv_bfloat16* __restrict__ Th,
                            __nv_bfloat16* __restrict__ Tl)
{
    __shared__ float t[32][33];
    int z = blockIdx.z;
    int mat = z / HH, h = z - mat * HH;
    const float* W = (mat == 0 ? Wq : mat == 1 ? Wk : Wv) + (size_t)h * DD * HDIM;
    int k0 = blockIdx.y * 32, e0 = blockIdx.x * 32;
    int tx = threadIdx.x, ty = threadIdx.y;
    #pragma unroll
    for (int i = 0; i < 32; i += 8)
        t[ty + i][tx] = W[(size_t)(k0 + ty + i) * HDIM + e0 + tx];
    __syncthreads();
    int nbase = mat * 1024 + h * HDIM;
    #pragma unroll
    for (int i = 0; i < 32; i += 8) {
        float v = t[tx][ty + i];
        __nv_bfloat16 hv = __float2bfloat16(v);
        size_t o = (size_t)(nbase + e0 + ty + i) * DD + k0 + tx;
        Th[o] = hv;
        Tl[o] = __float2bfloat16(v - __bfloat162float(hv));
    }
}

// swizzled byte offset for (row, 16B-chunk ck) within a 128B-row matrix
#define GSW(r, ck) ((unsigned int)((r) * 128 + ((((ck) ^ ((r) & 7))) << 4)))

// ===================== mma.sync bf16x3 GEMM (QKV / Wo) =====================
// Block 128x256, K-chunk 64, 2-stage, 16 warps, warp 64x32, SW128 smem.
#define OFF_AH 0
#define OFF_AL 16384
#define OFF_BH 32768
#define OFF_BL 65536
#define STG_B  98304
#define GT_SMEM (2*STG_B)      // 196608

template<bool BIAS, bool RELU, bool F32OUT, bool SPLIT>
__global__ void __launch_bounds__(512, 1) gemm_tc_kernel(
    const __nv_bfloat16* __restrict__ Ah, const __nv_bfloat16* __restrict__ Al,
    const __nv_bfloat16* __restrict__ BTh, const __nv_bfloat16* __restrict__ BTl,
    const float* __restrict__ bias,
    float* __restrict__ C,
    __nv_bfloat16* __restrict__ Ch, __nv_bfloat16* __restrict__ Cl,
    int M, int N, int K)
{
    extern __shared__ __align__(128) char smem[];
    const unsigned int sb = smem_u32(smem);
    const int tid = threadIdx.x;
    const int row0 = blockIdx.y * 128;
    const int col0 = blockIdx.x * 256;

    const int wid = tid >> 5, lane = tid & 31;
    const int wm0 = (wid & 1) * 64, wn0 = (wid >> 1) * 32;
    const int lr = lane & 15, lh = lane >> 4;

    auto load_stage = [&](int c, int s) {
        unsigned int base = sb + s * STG_B;
        int k0 = c * 64;
        #pragma unroll
        for (int i = 0; i < 2; i++) {
            int lin = tid + (i << 9);
            int r = lin >> 3, ck = lin & 7;
            unsigned int so = GSW(r, ck);
            size_t ga = (size_t)(row0 + r) * K + k0 + ck * 8;
            cp16(base + OFF_AH + so, Ah + ga);
            cp16(base + OFF_AL + so, Al + ga);
        }
        #pragma unroll
        for (int i = 0; i < 4; i++) {
            int lin = tid + (i << 9);
            int r = lin >> 3, ck = lin & 7;
            unsigned int so = GSW(r, ck);
            size_t gb = (size_t)(col0 + r) * K + k0 + ck * 8;
            cp16(base + OFF_BH + so, BTh + gb);
            cp16(base + OFF_BL + so, BTl + gb);
        }
        CP_COMMIT();
    };

    float acc[4][4][4] = {};

    load_stage(0, 0);
    load_stage(1, 1);

    const int NC = K >> 6;
    for (int c = 0; c < NC; c++) {
        CP_WAIT1();
        __syncthreads();

        unsigned int base = sb + (c & 1) * STG_B;
        #pragma unroll
        for (int ks = 0; ks < 4; ks++) {
            unsigned int a_h[4][4], a_l[4][4], b_h[2][4], b_l[2][4];
            #pragma unroll
            for (int mt = 0; mt < 4; mt++) {
                int r = wm0 + mt*16 + lr;
                unsigned int ro = GSW(r, ks*2 + lh);
                ldsm4(a_h[mt], base + OFF_AH + ro);
                ldsm4(a_l[mt], base + OFF_AL + ro);
            }
            #pragma unroll
            for (int bt = 0; bt < 2; bt++) {
                int r = wn0 + bt*16 + lr;
                unsigned int ro = GSW(r, ks*2 + lh);
                ldsm4(b_h[bt], base + OFF_BH + ro);
                ldsm4(b_l[bt], base + OFF_BL + ro);
            }
            #pragma unroll
            for (int mt = 0; mt < 4; mt++) {
                #pragma unroll
                for (int nt = 0; nt < 4; nt++) {
                    int bt = nt >> 1, hf = nt & 1;
                    mma_bf16(acc[mt][nt], a_h[mt], b_h[bt][hf], b_h[bt][hf+2]);
                    mma_bf16(acc[mt][nt], a_l[mt], b_h[bt][hf], b_h[bt][hf+2]);
                    mma_bf16(acc[mt][nt], a_h[mt], b_l[bt][hf], b_l[bt][hf+2]);
                }
            }
        }

        __syncthreads();
        if (c + 2 < NC) load_stage(c + 2, c & 1);
    }

    // ---- epilogue ----
    const int gq = lane >> 2, pq = lane & 3;
    #pragma unroll
    for (int mt = 0; mt < 4; mt++) {
        #pragma unroll
        for (int nt = 0; nt < 4; nt++) {
            int col = col0 + wn0 + nt*8 + pq*2;
            float b0 = 0.f, b1 = 0.f;
            if (BIAS) { b0 = bias[col]; b1 = bias[col+1]; }
            #pragma unroll
            for (int h2 = 0; h2 < 2; h2++) {
                int row = row0 + wm0 + mt*16 + gq + h2*8;
                float v0 = acc[mt][nt][h2*2+0] + b0;
                float v1 = acc[mt][nt][h2*2+1] + b1;
                if (RELU) { v0 = fmaxf(v0, 0.f); v1 = fmaxf(v1, 0.f); }
                if (F32OUT)
                    *(float2*)(C + (size_t)row * N + col) = make_float2(v0, v1);
                if (SPLIT) {
                    unsigned int hi, lo;
                    split2(v0, v1, hi, lo);
                    *(unsigned int*)(Ch + (size_t)row * N + col) = hi;
                    *(unsigned int*)(Cl + (size_t)row * N + col) = lo;
                }
            }
        }
    }
}

// ===================== fp16 2-term GEMM (FFN up/down) =====================
// D = Ah*B + Al*B. A fp16 hi/lo, B single fp16. Block 128x256, K-chunk 64,
// 3-stage pipeline (64KB/stage), 16 warps, warp 64x32.
#define G2_AH 0
#define G2_AL 16384
#define G2_B  32768
#define G2_STG 65536
#define G2_SMEM (3*G2_STG)     // 196608

template<bool RELU, bool F32OUT, bool SPLIT>
__global__ void __launch_bounds__(512, 1) gemm2_kernel(
    const __half* __restrict__ Ah, const __half* __restrict__ Al,
    const __half* __restrict__ BT,
    const float* __restrict__ bias,
    float* __restrict__ C,
    __half* __restrict__ Ch, __half* __restrict__ Cl,
    int M, int N, int K)
{
    extern __shared__ __align__(128) char smem[];
    const unsigned int sb = smem_u32(smem);
    const int tid = threadIdx.x;
    const int row0 = blockIdx.y * 128;
    const int col0 = blockIdx.x * 256;

    const int wid = tid >> 5, lane = tid & 31;
    const int wm0 = (wid & 1) * 64, wn0 = (wid >> 1) * 32;
    const int lr = lane & 15, lh = lane >> 4;

    auto load_stage = [&](int c, int s) {
        unsigned int base = sb + s * G2_STG;
        int k0 = c * 64;
        #pragma unroll
        for (int i = 0; i < 2; i++) {
            int lin = tid + (i << 9);            // 0..1023 : A rows, 8 chunks
            int r = lin >> 3, ck = lin & 7;
            unsigned int so = GSW(r, ck);
            size_t ga = (size_t)(row0 + r) * K + k0 + ck * 8;
            cp16(base + G2_AH + so, Ah + ga);
            cp16(base + G2_AL + so, Al + ga);
        }
        #pragma unroll
        for (int i = 0; i < 4; i++) {
            int lin = tid + (i << 9);            // 0..2047 : B rows, 8 chunks
            int r = lin >> 3, ck = lin & 7;
            unsigned int so = GSW(r, ck);
            cp16(base + G2_B + so, BT + (size_t)(col0 + r) * K + k0 + ck * 8);
        }
        CP_COMMIT();
    };

    float acc[4][4][4] = {};

    load_stage(0, 0);
    load_stage(1, 1);
    load_stage(2, 2);

    const int NC = K >> 6;
    for (int c = 0; c < NC; c++) {
        CP_WAIT2();
        __syncthreads();

        unsigned int base = sb + (c % 3) * G2_STG;
        #pragma unroll
        for (int ks = 0; ks < 4; ks++) {
            unsigned int a_h[4][4], a_l[4][4], b_r[2][4];
            #pragma unroll
            for (int mt = 0; mt < 4; mt++) {
                int r = wm0 + mt*16 + lr;
                unsigned int ro = GSW(r, ks*2 + lh);
                ldsm4(a_h[mt], base + G2_AH + ro);
                ldsm4(a_l[mt], base + G2_AL + ro);
            }
            #pragma unroll
            for (int bt = 0; bt < 2; bt++) {
                int r = wn0 + bt*16 + lr;
                unsigned int ro = GSW(r, ks*2 + lh);
                ldsm4(b_r[bt], base + G2_B + ro);
            }
            #pragma unroll
            for (int mt = 0; mt < 4; mt++) {
                #pragma unroll
                for (int nt = 0; nt < 4; nt++) {
                    int bt = nt >> 1, hf = nt & 1;
                    mma_f16(acc[mt][nt], a_h[mt], b_r[bt][hf], b_r[bt][hf+2]);
                    mma_f16(acc[mt][nt], a_l[mt], b_r[bt][hf], b_r[bt][hf+2]);
                }
            }
        }

        __syncthreads();
        if (c + 3 < NC) load_stage(c + 3, (c + 3) % 3);
    }

    // ---- epilogue ----
    const int gq = lane >> 2, pq = lane & 3;
    #pragma unroll
    for (int mt = 0; mt < 4; mt++) {
        #pragma unroll
        for (int nt = 0; nt < 4; nt++) {
            int col = col0 + wn0 + nt*8 + pq*2;
            float b0 = bias[col], b1 = bias[col+1];
            #pragma unroll
            for (int h2 = 0; h2 < 2; h2++) {
                int row = row0 + wm0 + mt*16 + gq + h2*8;
                float v0 = acc[mt][nt][h2*2+0] + b0;
                float v1 = acc[mt][nt][h2*2+1] + b1;
                if (RELU) { v0 = fmaxf(v0, 0.f); v1 = fmaxf(v1, 0.f); }
                if (F32OUT)
                    *(float2*)(C + (size_t)row * N + col) = make_float2(v0, v1);
                if (SPLIT) {
                    unsigned int hi, lo;
                    split2h(v0, v1, hi, lo);
                    *(unsigned int*)(Ch + (size_t)row * N + col) = hi;
                    *(unsigned int*)(Cl + (size_t)row * N + col) = lo;
                }
            }
        }
    }
}

// ===================== tensor-core causal flash attention (bf16x3) ============
#define AP 144
#define KMAT 9216              // 64*AP
#define QMAT 18432             // 128*AP
#define FA_Q (2*QMAT)          // 36864
#define FA_STG (4*KMAT)        // 36864
#define FA_SMEM (FA_Q + 2*FA_STG)   // 110592

__global__ void __launch_bounds__(256, 1) flash_tc_kernel()
{
    const int pid = blockIdx.x, bh = blockIdx.y;
    const int b = bh >> 4, h = bh & 15;
    const int tid = threadIdx.x, wid = tid >> 5, lane = tid & 31;
    const int wm = wid * 16;
    const int lr = lane & 15, lh = lane >> 4;

    extern __shared__ __align__(16) char smem[];
    const unsigned int sb = smem_u32(smem);
    const unsigned int sQh = sb, sQl = sb + QMAT;

    for (int run = 0; run < 2; run++) {
        const int qt0 = run ? (15 - pid) : pid;
        const int NKT = 2 * qt0 + 2;

        __syncthreads();

        {
            const __nv_bfloat16* qh = g_qkvh + (size_t)(b*SS + qt0*128)*3072 + h*HDIM;
            const __nv_bfloat16* ql = g_qkvl + (size_t)(b*SS + qt0*128)*3072 + h*HDIM;
            #pragma unroll
            for (int i = 0; i < 4; i++) {
                int lin = tid + (i << 8);
                int r = lin >> 3, ck = lin & 7;
                unsigned int so = r*AP + ck*16;
                size_t g = (size_t)r*3072 + ck*8;
                cp16(sQh + so, qh + g);
                cp16(sQl + so, ql + g);
            }
            CP_COMMIT();
        }

        auto load_kv = [&](int kt, int s) {
            unsigned int base = sb + FA_Q + s * FA_STG;
            size_t rowb = (size_t)(b*SS + kt*64)*3072;
            const __nv_bfloat16* kh = g_qkvh + rowb + 1024 + h*HDIM;
            const __nv_bfloat16* kl = g_qkvl + rowb + 1024 + h*HDIM;
            const __nv_bfloat16* vh = g_qkvh + rowb + 2048 + h*HDIM;
            const __nv_bfloat16* vl = g_qkvl + rowb + 2048 + h*HDIM;
            #pragma unroll
            for (int i = 0; i < 2; i++) {
                int lin = tid + (i << 8);
                int r = lin >> 3, ck = lin & 7;
                unsigned int so = r*AP + ck*16;
                size_t g = (size_t)r*3072 + ck*8;
                cp16(base + so,          kh + g);
                cp16(base + KMAT + so,   kl + g);
                cp16(base + 2*KMAT + so, vh + g);
                cp16(base + 3*KMAT + so, vl + g);
            }
            CP_COMMIT();
        };

        load_kv(0, 0);
        load_kv(1, 1);

        float o[8][4] = {};
        float m0 = -1e30f, m1 = -1e30f, l0 = 0.f, l1 = 0.f;

        for (int kt = 0; kt < NKT; kt++) {
            if (kt < NKT - 1) CP_WAIT1(); else CP_WAIT0();
            __syncthreads();

            const unsigned int kb = sb + FA_Q + (kt & 1) * FA_STG;

            float sc[8][4] = {};
            #pragma unroll
            for (int kd = 0; kd < 4; kd++) {
                unsigned int aqh[4], aql[4];
                unsigned int qro = (unsigned int)(wm + lr)*AP + (kd*2 + lh)*16;
                ldsm4(aqh, sQh + qro);
                ldsm4(aql, sQl + qro);
                #pragma unroll
                for (int g = 0; g < 4; g++) {
                    unsigned int rkh[4], rkl[4];
                    unsigned int kro = (unsigned int)(g*16 + lr)*AP + (kd*2 + lh)*16;
                    ldsm4(rkh, kb + kro);
                    ldsm4(rkl, kb + KMAT + kro);
                    mma_bf16(sc[2*g],   aqh, rkh[0], rkh[2]);
                    mma_bf16(sc[2*g+1], aqh, rkh[1], rkh[3]);
                    mma_bf16(sc[2*g],   aqh, rkl[0], rkl[2]);
                    mma_bf16(sc[2*g+1], aqh, rkl[1], rkl[3]);
                    mma_bf16(sc[2*g],   aql, rkh[0], rkh[2]);
                    mma_bf16(sc[2*g+1], aql, rkh[1], rkh[3]);
                }
            }

            if (kt >= 2*qt0) {
                const int grow0 = qt0*128 + wm + (lane >> 2);
                const int gc0 = kt*64 + (lane & 3)*2;
                #pragma unroll
                for (int nt = 0; nt < 8; nt++) {
                    int c0l = gc0 + nt*8;
                    sc[nt][0] = (c0l     > grow0)   ? -1e30f : sc[nt][0]*0.125f;
                    sc[nt][1] = (c0l + 1 > grow0)   ? -1e30f : sc[nt][1]*0.125f;
                    sc[nt][2] = (c0l     > grow0+8) ? -1e30f : sc[nt][2]*0.125f;
                    sc[nt][3] = (c0l + 1 > grow0+8) ? -1e30f : sc[nt][3]*0.125f;
                }
            } else {
                #pragma unroll
                for (int nt = 0; nt < 8; nt++) {
                    sc[nt][0] *= 0.125f; sc[nt][1] *= 0.125f;
                    sc[nt][2] *= 0.125f; sc[nt][3] *= 0.125f;
                }
            }

            float mx0 = -1e30f, mx1 = -1e30f;
            #pragma unroll
            for (int nt = 0; nt < 8; nt++) {
                mx0 = fmaxf(mx0, fmaxf(sc[nt][0], sc[nt][1]));
                mx1 = fmaxf(mx1, fmaxf(sc[nt][2], sc[nt][3]));
            }
            mx0 = fmaxf(mx0, __shfl_xor_sync(0xffffffffu, mx0, 1));
            mx0 = fmaxf(mx0, __shfl_xor_sync(0xffffffffu, mx0, 2));
            mx1 = fmaxf(mx1, __shfl_xor_sync(0xffffffffu, mx1, 1));
            mx1 = fmaxf(mx1, __shfl_xor_sync(0xffffffffu, mx1, 2));
            float mn0 = fmaxf(m0, mx0), mn1 = fmaxf(m1, mx1);
            float cf0 = __expf(m0 - mn0), cf1 = __expf(m1 - mn1);
            m0 = mn0; m1 = mn1;
            float s0 = 0.f, s1 = 0.f;
            #pragma unroll
            for (int nt = 0; nt < 8; nt++) {
                sc[nt][0] = __expf(sc[nt][0] - mn0);
                sc[nt][1] = __expf(sc[nt][1] - mn0);
                sc[nt][2] = __expf(sc[nt][2] - mn1);
                sc[nt][3] = __expf(sc[nt][3] - mn1);
                s0 += sc[nt][0] + sc[nt][1];
                s1 += sc[nt][2] + sc[nt][3];
            }
            s0 += __shfl_xor_sync(0xffffffffu, s0, 1);
            s0 += __shfl_xor_sync(0xffffffffu, s0, 2);
            s1 += __shfl_xor_sync(0xffffffffu, s1, 1);
            s1 += __shfl_xor_sync(0xffffffffu, s1, 2);
            l0 = l0 * cf0 + s0;
            l1 = l1 * cf1 + s1;
            #pragma unroll
            for (int dt = 0; dt < 8; dt++) {
                o[dt][0] *= cf0; o[dt][1] *= cf0;
                o[dt][2] *= cf1; o[dt][3] *= cf1;
            }

            #pragma unroll
            for (int j = 0; j < 4; j++) {
                unsigned int ph[4], pl[4];
                split2(sc[2*j][0],   sc[2*j][1],   ph[0], pl[0]);
                split2(sc[2*j][2],   sc[2*j][3],   ph[1], pl[1]);
                split2(sc[2*j+1][0], sc[2*j+1][1], ph[2], pl[2]);
                split2(sc[2*j+1][2], sc[2*j+1][3], ph[3], pl[3]);
                #pragma unroll
                for (int g = 0; g < 4; g++) {
                    unsigned int rvh[4], rvl[4];
                    unsigned int vro = (unsigned int)(j*16 + lr)*AP + (g*2 + lh)*16;
                    ldsm4t(rvh, kb + 2*KMAT + vro);
                    ldsm4t(rvl, kb + 3*KMAT + vro);
                    mma_bf16(o[2*g],   ph, rvh[0], rvh[1]);
                    mma_bf16(o[2*g+1], ph, rvh[2], rvh[3]);
                    mma_bf16(o[2*g],   ph, rvl[0], rvl[1]);
                    mma_bf16(o[2*g+1], ph, rvl[2], rvl[3]);
                    mma_bf16(o[2*g],   pl, rvh[0], rvh[1]);
                    mma_bf16(o[2*g+1], pl, rvh[2], rvh[3]);
                }
            }

            __syncthreads();
            if (kt + 2 < NKT) load_kv(kt + 2, kt & 1);
        }

        const float inv0 = 1.f / l0, inv1 = 1.f / l1;
        const int row0g = qt0*128 + wm + (lane >> 2);
        __nv_bfloat16* ohp = g_ah + ((size_t)bh*SS)*HDIM;
        __nv_bfloat16* olp = g_al + ((size_t)bh*SS)*HDIM;
        #pragma unroll
        for (int dt = 0; dt < 8; dt++) {
            int d = dt*8 + (lane & 3)*2;
            unsigned int hi, lo;
            split2(o[dt][0]*inv0, o[dt][1]*inv0, hi, lo);
            *(unsigned int*)(ohp + (size_t)row0g*HDIM + d) = hi;
            *(unsigned int*)(olp + (size_t)row0g*HDIM + d) = lo;
            split2(o[dt][2]*inv1, o[dt][3]*inv1, hi, lo);
            *(unsigned int*)(ohp + (size_t)(row0g+8)*HDIM + d) = hi;
            *(unsigned int*)(olp + (size_t)(row0g+8)*HDIM + d) = lo;
        }
    }
}

// ===================== LayerNorm =====================
__device__ __forceinline__ float blk_sum(float v, float* sred)
{
    #pragma unroll
    for (int o = 16; o; o >>= 1) v += __shfl_xor_sync(0xffffffffu, v, o);
    int w = threadIdx.x >> 5;
    if ((threadIdx.x & 31) == 0) sred[w] = v;
    __syncthreads();
    float t = (threadIdx.x < 8) ? sred[threadIdx.x] : 0.f;
    if (threadIdx.x < 32) {
        #pragma unroll
        for (int o = 4; o; o >>= 1) t += __shfl_xor_sync(0xffffffffu, t, o);
        if (threadIdx.x == 0) sred[0] = t;
    }
    __syncthreads();
    float r = sred[0];
    __syncthreads();
    return r;
}

template<bool SPLIT>
__global__ void ln_kernel(const float* __restrict__ resid,
                          const float* __restrict__ y,
                          const float* __restrict__ gamma,
                          const float* __restrict__ beta,
                          float* __restrict__ outf,
                          __half* __restrict__ oh,
                          __half* __restrict__ ol)
{
    __shared__ float sred[32];
    const int row = blockIdx.x;
    const int tid = threadIdx.x;

    float4 a = ((const float4*)(resid + (size_t)row * DD))[tid];
    float4 b = ((const float4*)(y     + (size_t)row * DD))[tid];
    float4 v = make_float4(a.x + b.x, a.y + b.y, a.z + b.z, a.w + b.w);

    float total = blk_sum(v.x + v.y + v.z + v.w, sred);
    float mu = total * (1.f / DD);

    float dx = v.x - mu, dy = v.y - mu, dz = v.z - mu, dw = v.w - mu;
    float tot2 = blk_sum(dx*dx + dy*dy + dz*dz + dw*dw, sred);
    float inv = rsqrtf(tot2 * (1.f / DD) + LN_EPS);

    float4 g = ((const float4*)gamma)[tid];
    float4 be = ((const float4*)beta)[tid];
    float ov[4];
    ov[0] = dx * inv * g.x + be.x;
    ov[1] = dy * inv * g.y + be.y;
    ov[2] = dz * inv * g.z + be.z;
    ov[3] = dw * inv * g.w + be.w;
    ((float4*)(outf + (size_t)row * DD))[tid] = make_float4(ov[0], ov[1], ov[2], ov[3]);

    if (SPLIT) {
        unsigned int wh[2], wl[2];
        split2h(ov[0], ov[1], wh[0], wl[0]);
        split2h(ov[2], ov[3], wh[1], wl[1]);
        *(uint2*)(oh + (size_t)row * DD + tid * 4) = make_uint2(wh[0], wh[1]);
        *(uint2*)(ol + (size_t)row * DD + tid * 4) = make_uint2(wl[0], wl[1]);
    }
}

// ===================== launch =====================
extern "C" void kernel_launch(void* const* d_in, const int* in_sizes, int n_in,
                              void* d_out, int out_size)
{
    (void)in_sizes; (void)n_in; (void)out_size;

    const float* x     = (const float*)d_in[0];
    const float* Wq    = (const float*)d_in[1];
    const float* Wk    = (const float*)d_in[2];
    const float* Wv    = (const float*)d_in[3];
    const float* Wo    = (const float*)d_in[4];
    const float* g1    = (const float*)d_in[5];
    const float* be1   = (const float*)d_in[6];
    const float* w_in  = (const float*)d_in[7];
    const float* b_in  = (const float*)d_in[8];
    const float* w_out = (const float*)d_in[9];
    const float* b_out = (const float*)d_in[10];
    const float* g2    = (const float*)d_in[11];
    const float* be2   = (const float*)d_in[12];
    float* out = (float*)d_out;

    float *tmp, *x1;
    __nv_bfloat16 *qkvh, *qkvl, *xh, *xl, *ah, *al;
    __nv_bfloat16 *wqkvh, *wqkvl, *woh, *wol;
    __half *x1h, *x1l, *h1h, *h1l, *winf, *woutf;
    cudaGetSymbolAddress((void**)&tmp,  g_tmp);
    cudaGetSymbolAddress((void**)&x1,   g_x1);
    cudaGetSymbolAddress((void**)&qkvh, g_qkvh);  cudaGetSymbolAddress((void**)&qkvl, g_qkvl);
    cudaGetSymbolAddress((void**)&xh,   g_xh);    cudaGetSymbolAddress((void**)&xl,   g_xl);
    cudaGetSymbolAddress((void**)&ah,   g_ah);    cudaGetSymbolAddress((void**)&al,   g_al);
    cudaGetSymbolAddress((void**)&x1h,  g_x1h);   cudaGetSymbolAddress((void**)&x1l,  g_x1l);
    cudaGetSymbolAddress((void**)&h1h,  g_h1h);   cudaGetSymbolAddress((void**)&h1l,  g_h1l);
    cudaGetSymbolAddress((void**)&wqkvh, g_wqkvh); cudaGetSymbolAddress((void**)&wqkvl, g_wqkvl);
    cudaGetSymbolAddress((void**)&woh,   g_woh);   cudaGetSymbolAddress((void**)&wol,   g_wol);
    cudaGetSymbolAddress((void**)&winf,  g_winf);  cudaGetSymbolAddress((void**)&woutf, g_woutf);

    cudaFuncSetAttribute(flash_tc_kernel, cudaFuncAttributeMaxDynamicSharedMemorySize, FA_SMEM);
    cudaFuncSetAttribute(gemm_tc_kernel<false,false,false,true>, cudaFuncAttributeMaxDynamicSharedMemorySize, GT_SMEM);
    cudaFuncSetAttribute(gemm_tc_kernel<false,false,true,false>, cudaFuncAttributeMaxDynamicSharedMemorySize, GT_SMEM);
    cudaFuncSetAttribute(gemm2_kernel<true,false,true>,  cudaFuncAttributeMaxDynamicSharedMemorySize, G2_SMEM);
    cudaFuncSetAttribute(gemm2_kernel<false,true,false>, cudaFuncAttributeMaxDynamicSharedMemorySize, G2_SMEM);

    // ---- prep: split x; transpose/split weights ----
    fsplit_kernel<<<MM*DD/1024, 256>>>(x, xh, xl, MM*DD/4);
    qkvT_kernel<<<dim3(2, 32, 48), dim3(32, 8)>>>(Wq, Wk, Wv, wqkvh, wqkvl);
    wsplit3_kernel<<<9216, dim3(32, 8)>>>(Wo, w_in, w_out);

    // ---- 1) fused QKV projection (bf16x3) -> split bf16 hi/lo ----
    gemm_tc_kernel<false,false,false,true><<<dim3(3072/256, MM/128), 512, GT_SMEM>>>(
        xh, xl, wqkvh, wqkvl, nullptr, nullptr, qkvh, qkvl, MM, 3072, 1024);

    // ---- 2) causal flash attention ----
    flash_tc_kernel<<<dim3(SS/256, BB*HH), 256, FA_SMEM>>>();

    // ---- 3) output projection (bf16x3) ----
    gemm_tc_kernel<false,false,true,false><<<dim3(1024/256, MM/128), 512, GT_SMEM>>>(
        ah, al, woh, wol, nullptr, tmp, nullptr, nullptr, MM, 1024, 1024);

    // ---- 4) LN1 (x + attn@Wo), split to fp16 ----
    ln_kernel<true><<<MM, 256>>>(x, tmp, g1, be1, x1, x1h, x1l);

    // ---- 5) FFN up + bias + ReLU (fp16 2-term), split fp16 output ----
    gemm2_kernel<true,false,true><<<dim3(4096/256, MM/128), 512, G2_SMEM>>>(
        x1h, x1l, winf, b_in, nullptr, h1h, h1l, MM, 4096, 1024);

    // ---- 6) FFN down + bias (fp16 2-term) ----
    gemm2_kernel<false,true,false><<<dim3(1024/256, MM/128), 512, G2_SMEM>>>(
        h1h, h1l, woutf, b_out, tmp, nullptr, nullptr, MM, 1024, 4096);

    // ---- 7) LN2 -> output ----
    ln_kernel<false><<<MM, 256>>>(x1, tmp, g2, be2, out, nullptr, nullptr);
}

// round 10
// speedup vs baseline: 3.3342x; 1.0227x over previous
#include <cuda_runtime.h>
#include <cuda_bf16.h>
#include <cuda_fp16.h>
#include <math.h>

// Problem constants
#define BB   4
#define SS   2048
#define DD   1024
#define HH   16
#define HDIM 64
#define FF   4096
#define MM   (BB*SS)   // 8192 rows
#define LN_EPS 1e-5f

// ===================== low-level helpers =====================
__device__ __forceinline__ unsigned int smem_u32(const void* p) {
    unsigned int a;
    asm("{ .reg .u64 t; cvta.to.shared.u64 t, %1; cvt.u32.u64 %0, t; }" : "=r"(a) : "l"(p));
    return a;
}
__device__ __forceinline__ void cp16(unsigned int s, const void* g) {
    asm volatile("cp.async.cg.shared.global [%0], [%1], 16;" :: "r"(s), "l"(g));
}
#define CP_COMMIT() asm volatile("cp.async.commit_group;" ::: "memory")
#define CP_WAIT1()  asm volatile("cp.async.wait_group 1;" ::: "memory")
#define CP_WAIT2()  asm volatile("cp.async.wait_group 2;" ::: "memory")
#define CP_WAIT0()  asm volatile("cp.async.wait_group 0;" ::: "memory")

__device__ __forceinline__ void ldsm4(unsigned int* r, unsigned int addr) {
    asm volatile("ldmatrix.sync.aligned.m8n8.x4.shared.b16 {%0,%1,%2,%3}, [%4];"
        : "=r"(r[0]), "=r"(r[1]), "=r"(r[2]), "=r"(r[3]) : "r"(addr));
}
__device__ __forceinline__ void ldsm4t(unsigned int* r, unsigned int addr) {
    asm volatile("ldmatrix.sync.aligned.m8n8.x4.trans.shared.b16 {%0,%1,%2,%3}, [%4];"
        : "=r"(r[0]), "=r"(r[1]), "=r"(r[2]), "=r"(r[3]) : "r"(addr));
}
__device__ __forceinline__ void mma_bf16(float* c, const unsigned int* a,
                                         unsigned int b0, unsigned int b1) {
    asm volatile("mma.sync.aligned.m16n8k16.row.col.f32.bf16.bf16.f32 "
        "{%0,%1,%2,%3}, {%4,%5,%6,%7}, {%8,%9}, {%0,%1,%2,%3};"
        : "+f"(c[0]), "+f"(c[1]), "+f"(c[2]), "+f"(c[3])
        : "r"(a[0]), "r"(a[1]), "r"(a[2]), "r"(a[3]), "r"(b0), "r"(b1));
}
__device__ __forceinline__ void mma_f16(float* c, const unsigned int* a,
                                        unsigned int b0, unsigned int b1) {
    asm volatile("mma.sync.aligned.m16n8k16.row.col.f32.f16.f16.f32 "
        "{%0,%1,%2,%3}, {%4,%5,%6,%7}, {%8,%9}, {%0,%1,%2,%3};"
        : "+f"(c[0]), "+f"(c[1]), "+f"(c[2]), "+f"(c[3])
        : "r"(a[0]), "r"(a[1]), "r"(a[2]), "r"(a[3]), "r"(b0), "r"(b1));
}
__device__ __forceinline__ unsigned int pack_bf16(__nv_bfloat16 a, __nv_bfloat16 b) {
    return (unsigned int)__bfloat16_as_ushort(a) | ((unsigned int)__bfloat16_as_ushort(b) << 16);
}
__device__ __forceinline__ void split2(float v0, float v1, unsigned int& hi, unsigned int& lo) {
    __nv_bfloat16 h0 = __float2bfloat16(v0);
    __nv_bfloat16 h1 = __float2bfloat16(v1);
    __nv_bfloat16 l0 = __float2bfloat16(v0 - __bfloat162float(h0));
    __nv_bfloat16 l1 = __float2bfloat16(v1 - __bfloat162float(h1));
    hi = pack_bf16(h0, h1);
    lo = pack_bf16(l0, l1);
}
__device__ __forceinline__ unsigned int pack_f16(__half a, __half b) {
    return (unsigned int)__half_as_ushort(a) | ((unsigned int)__half_as_ushort(b) << 16);
}
__device__ __forceinline__ void split2h(float v0, float v1, unsigned int& hi, unsigned int& lo) {
    __half h0 = __float2half(v0);
    __half h1 = __float2half(v1);
    __half l0 = __float2half(v0 - __half2float(h0));
    __half l1 = __float2half(v1 - __half2float(h1));
    hi = pack_f16(h0, h1);
    lo = pack_f16(l0, l1);
}

// ===================== scratch (device globals) =====================
__device__ __nv_bfloat16 g_qkvh[(size_t)MM*3072], g_qkvl[(size_t)MM*3072];
__device__ __nv_bfloat16 g_xh[(size_t)MM*DD],  g_xl[(size_t)MM*DD];
__device__ __half g_ah[(size_t)MM*DD], g_al[(size_t)MM*DD];   // attention out fp16 hi/lo
__device__ float g_tmp[(size_t)MM*DD];
__device__ float g_x1[(size_t)MM*DD];
__device__ __half g_x1h[(size_t)MM*DD], g_x1l[(size_t)MM*DD];
__device__ __half g_h1h[(size_t)MM*FF], g_h1l[(size_t)MM*FF];
// transposed weights ([N,K] row-major)
__device__ __nv_bfloat16 g_wqkvh[(size_t)3072*1024], g_wqkvl[(size_t)3072*1024];
__device__ __half g_wof[(size_t)1024*1024];    // Wo fp16 single
__device__ __half g_winf[(size_t)4096*1024];   // fp16 single
__device__ __half g_woutf[(size_t)1024*4096];  // fp16 single

// ===================== prep kernels =====================
__global__ void fsplit_kernel(const float* __restrict__ in,
                              __nv_bfloat16* __restrict__ h,
                              __nv_bfloat16* __restrict__ l, int n4)
{
    int i = blockIdx.x * blockDim.x + threadIdx.x;
    if (i >= n4) return;
    float4 v = ((const float4*)in)[i];
    unsigned int ph[2], pl[2];
    split2(v.x, v.y, ph[0], pl[0]);
    split2(v.z, v.w, ph[1], pl[1]);
    ((uint2*)h)[i] = make_uint2(ph[0], ph[1]);
    ((uint2*)l)[i] = make_uint2(pl[0], pl[1]);
}

// transpose one 32x32 block of W [K,N] -> single fp16 T [N,K]
__device__ __forceinline__ void wsingle_block(const float* __restrict__ W,
                                              __half* __restrict__ T,
                                              int K, int N, int k0, int n0,
                                              float t[32][33])
{
    int tx = threadIdx.x, ty = threadIdx.y;
    #pragma unroll
    for (int i = 0; i < 32; i += 8)
        t[ty + i][tx] = W[(size_t)(k0 + ty + i) * N + n0 + tx];
    __syncthreads();
    #pragma unroll
    for (int i = 0; i < 32; i += 8) {
        float v = t[tx][ty + i];
        T[(size_t)(n0 + ty + i) * K + k0 + tx] = __float2half(v);
    }
}

// merged: Wo fp16 (1024 blocks), w_in fp16 (4096), w_out fp16 (4096)
__global__ void wsplit3_kernel(const float* __restrict__ Wo,
                               const float* __restrict__ Win,
                               const float* __restrict__ Wout)
{
    __shared__ float t[32][33];
    int idx = blockIdx.x;
    if (idx < 1024) {
        wsingle_block(Wo, g_wof, 1024, 1024,
                      (idx >> 5) * 32, (idx & 31) * 32, t);
    } else if (idx < 1024 + 4096) {
        int i2 = idx - 1024;
        wsingle_block(Win, g_winf, 1024, 4096,
                      (i2 >> 7) * 32, (i2 & 127) * 32, t);
    } else {
        int i2 = idx - 5120;
        wsingle_block(Wout, g_woutf, 4096, 1024,
                      (i2 >> 5) * 32, (i2 & 31) * 32, t);
    }
}

__global__ void qkvT_kernel(const float* __restrict__ Wq,
                            const float* __restrict__ Wk,
                            const float* __restrict__ Wv,
                            __nv_bfloat16* __restrict__ Th,
                            __nv_bfloat16* __restrict__ Tl)
{
    __shared__ float t[32][33];
    int z = blockIdx.z;
    int mat = z / HH, h = z - mat * HH;
    const float* W = (mat == 0 ? Wq : mat == 1 ? Wk : Wv) + (size_t)h * DD * HDIM;
    int k0 = blockIdx.y * 32, e0 = blockIdx.x * 32;
    int tx = threadIdx.x, ty = threadIdx.y;
    #pragma unroll
    for (int i = 0; i < 32; i += 8)
        t[ty + i][tx] = W[(size_t)(k0 + ty + i) * HDIM + e0 + tx];
    __syncthreads();
    int nbase = mat * 1024 + h * HDIM;
    #pragma unroll
    for (int i = 0; i < 32; i += 8) {
        float v = t[tx][ty + i];
        __nv_bfloat16 hv = __float2bfloat16(v);
        size_t o = (size_t)(nbase + e0 + ty + i) * DD + k0 + tx;
        Th[o] = hv;
        Tl[o] = __float2bfloat16(v - __bfloat162float(hv));
    }
}

// swizzled byte offset for (row, 16B-chunk ck) within a 128B-row matrix
#define GSW(r, ck) ((unsigned int)((r) * 128 + ((((ck) ^ ((r) & 7))) << 4)))

// ===================== mma.sync bf16x3 GEMM (QKV) =====================
// Block 128x256, K-chunk 64, 2-stage, 16 warps, warp 64x32, SW128 smem.
// MMA terms issued term-major to break accumulator dependency chains.
#define OFF_AH 0
#define OFF_AL 16384
#define OFF_BH 32768
#define OFF_BL 65536
#define STG_B  98304
#define GT_SMEM (2*STG_B)      // 196608

template<bool BIAS, bool RELU, bool F32OUT, bool SPLIT>
__global__ void __launch_bounds__(512, 1) gemm_tc_kernel(
    const __nv_bfloat16* __restrict__ Ah, const __nv_bfloat16* __restrict__ Al,
    const __nv_bfloat16* __restrict__ BTh, const __nv_bfloat16* __restrict__ BTl,
    const float* __restrict__ bias,
    float* __restrict__ C,
    __nv_bfloat16* __restrict__ Ch, __nv_bfloat16* __restrict__ Cl,
    int M, int N, int K)
{
    extern __shared__ __align__(128) char smem[];
    const unsigned int sb = smem_u32(smem);
    const int tid = threadIdx.x;
    const int row0 = blockIdx.y * 128;
    const int col0 = blockIdx.x * 256;

    const int wid = tid >> 5, lane = tid & 31;
    const int wm0 = (wid & 1) * 64, wn0 = (wid >> 1) * 32;
    const int lr = lane & 15, lh = lane >> 4;

    auto load_stage = [&](int c, int s) {
        unsigned int base = sb + s * STG_B;
        int k0 = c * 64;
        #pragma unroll
        for (int i = 0; i < 2; i++) {
            int lin = tid + (i << 9);
            int r = lin >> 3, ck = lin & 7;
            unsigned int so = GSW(r, ck);
            size_t ga = (size_t)(row0 + r) * K + k0 + ck * 8;
            cp16(base + OFF_AH + so, Ah + ga);
            cp16(base + OFF_AL + so, Al + ga);
        }
        #pragma unroll
        for (int i = 0; i < 4; i++) {
            int lin = tid + (i << 9);
            int r = lin >> 3, ck = lin & 7;
            unsigned int so = GSW(r, ck);
            size_t gb = (size_t)(col0 + r) * K + k0 + ck * 8;
            cp16(base + OFF_BH + so, BTh + gb);
            cp16(base + OFF_BL + so, BTl + gb);
        }
        CP_COMMIT();
    };

    float acc[4][4][4] = {};

    load_stage(0, 0);
    load_stage(1, 1);

    const int NC = K >> 6;
    for (int c = 0; c < NC; c++) {
        CP_WAIT1();
        __syncthreads();

        unsigned int base = sb + (c & 1) * STG_B;
        #pragma unroll
        for (int ks = 0; ks < 4; ks++) {
            unsigned int a_h[4][4], a_l[4][4], b_h[2][4], b_l[2][4];
            #pragma unroll
            for (int mt = 0; mt < 4; mt++) {
                int r = wm0 + mt*16 + lr;
                unsigned int ro = GSW(r, ks*2 + lh);
                ldsm4(a_h[mt], base + OFF_AH + ro);
                ldsm4(a_l[mt], base + OFF_AL + ro);
            }
            #pragma unroll
            for (int bt = 0; bt < 2; bt++) {
                int r = wn0 + bt*16 + lr;
                unsigned int ro = GSW(r, ks*2 + lh);
                ldsm4(b_h[bt], base + OFF_BH + ro);
                ldsm4(b_l[bt], base + OFF_BL + ro);
            }
            // term-major: 16 independent accumulators between same-acc MMAs
            #pragma unroll
            for (int mt = 0; mt < 4; mt++)
                #pragma unroll
                for (int nt = 0; nt < 4; nt++)
                    mma_bf16(acc[mt][nt], a_h[mt], b_h[nt>>1][nt&1], b_h[nt>>1][(nt&1)+2]);
            #pragma unroll
            for (int mt = 0; mt < 4; mt++)
                #pragma unroll
                for (int nt = 0; nt < 4; nt++)
                    mma_bf16(acc[mt][nt], a_l[mt], b_h[nt>>1][nt&1], b_h[nt>>1][(nt&1)+2]);
            #pragma unroll
            for (int mt = 0; mt < 4; mt++)
                #pragma unroll
                for (int nt = 0; nt < 4; nt++)
                    mma_bf16(acc[mt][nt], a_h[mt], b_l[nt>>1][nt&1], b_l[nt>>1][(nt&1)+2]);
        }

        __syncthreads();
        if (c + 2 < NC) load_stage(c + 2, c & 1);
    }

    // ---- epilogue ----
    const int gq = lane >> 2, pq = lane & 3;
    #pragma unroll
    for (int mt = 0; mt < 4; mt++) {
        #pragma unroll
        for (int nt = 0; nt < 4; nt++) {
            int col = col0 + wn0 + nt*8 + pq*2;
            float b0 = 0.f, b1 = 0.f;
            if (BIAS) { b0 = bias[col]; b1 = bias[col+1]; }
            #pragma unroll
            for (int h2 = 0; h2 < 2; h2++) {
                int row = row0 + wm0 + mt*16 + gq + h2*8;
                float v0 = acc[mt][nt][h2*2+0] + b0;
                float v1 = acc[mt][nt][h2*2+1] + b1;
                if (RELU) { v0 = fmaxf(v0, 0.f); v1 = fmaxf(v1, 0.f); }
                if (F32OUT)
                    *(float2*)(C + (size_t)row * N + col) = make_float2(v0, v1);
                if (SPLIT) {
                    unsigned int hi, lo;
                    split2(v0, v1, hi, lo);
                    *(unsigned int*)(Ch + (size_t)row * N + col) = hi;
                    *(unsigned int*)(Cl + (size_t)row * N + col) = lo;
                }
            }
        }
    }
}

// ===================== fp16 2-term GEMM (Wo / FFN up / FFN down) ==============
// D = Ah*B + Al*B. A fp16 hi/lo, B single fp16. Block 128x256, K-chunk 64,
// 3-stage pipeline (64KB/stage), 16 warps, warp 64x32. Term-major MMA order.
#define G2_AH 0
#define G2_AL 16384
#define G2_B  32768
#define G2_STG 65536
#define G2_SMEM (3*G2_STG)     // 196608

template<bool BIAS, bool RELU, bool F32OUT, bool SPLIT>
__global__ void __launch_bounds__(512, 1) gemm2_kernel(
    const __half* __restrict__ Ah, const __half* __restrict__ Al,
    const __half* __restrict__ BT,
    const float* __restrict__ bias,
    float* __restrict__ C,
    __half* __restrict__ Ch, __half* __restrict__ Cl,
    int M, int N, int K)
{
    extern __shared__ __align__(128) char smem[];
    const unsigned int sb = smem_u32(smem);
    const int tid = threadIdx.x;
    const int row0 = blockIdx.y * 128;
    const int col0 = blockIdx.x * 256;

    const int wid = tid >> 5, lane = tid & 31;
    const int wm0 = (wid & 1) * 64, wn0 = (wid >> 1) * 32;
    const int lr = lane & 15, lh = lane >> 4;

    auto load_stage = [&](int c, int s) {
        unsigned int base = sb + s * G2_STG;
        int k0 = c * 64;
        #pragma unroll
        for (int i = 0; i < 2; i++) {
            int lin = tid + (i << 9);
            int r = lin >> 3, ck = lin & 7;
            unsigned int so = GSW(r, ck);
            size_t ga = (size_t)(row0 + r) * K + k0 + ck * 8;
            cp16(base + G2_AH + so, Ah + ga);
            cp16(base + G2_AL + so, Al + ga);
        }
        #pragma unroll
        for (int i = 0; i < 4; i++) {
            int lin = tid + (i << 9);
            int r = lin >> 3, ck = lin & 7;
            unsigned int so = GSW(r, ck);
            cp16(base + G2_B + so, BT + (size_t)(col0 + r) * K + k0 + ck * 8);
        }
        CP_COMMIT();
    };

    float acc[4][4][4] = {};

    load_stage(0, 0);
    load_stage(1, 1);
    load_stage(2, 2);

    const int NC = K >> 6;
    for (int c = 0; c < NC; c++) {
        CP_WAIT2();
        __syncthreads();

        unsigned int base = sb + (c % 3) * G2_STG;
        #pragma unroll
        for (int ks = 0; ks < 4; ks++) {
            unsigned int a_h[4][4], a_l[4][4], b_r[2][4];
            #pragma unroll
            for (int mt = 0; mt < 4; mt++) {
                int r = wm0 + mt*16 + lr;
                unsigned int ro = GSW(r, ks*2 + lh);
                ldsm4(a_h[mt], base + G2_AH + ro);
                ldsm4(a_l[mt], base + G2_AL + ro);
            }
            #pragma unroll
            for (int bt = 0; bt < 2; bt++) {
                int r = wn0 + bt*16 + lr;
                unsigned int ro = GSW(r, ks*2 + lh);
                ldsm4(b_r[bt], base + G2_B + ro);
            }
            // term-major
            #pragma unroll
            for (int mt = 0; mt < 4; mt++)
                #pragma unroll
                for (int nt = 0; nt < 4; nt++)
                    mma_f16(acc[mt][nt], a_h[mt], b_r[nt>>1][nt&1], b_r[nt>>1][(nt&1)+2]);
            #pragma unroll
            for (int mt = 0; mt < 4; mt++)
                #pragma unroll
                for (int nt = 0; nt < 4; nt++)
                    mma_f16(acc[mt][nt], a_l[mt], b_r[nt>>1][nt&1], b_r[nt>>1][(nt&1)+2]);
        }

        __syncthreads();
        if (c + 3 < NC) load_stage(c + 3, (c + 3) % 3);
    }

    // ---- epilogue ----
    const int gq = lane >> 2, pq = lane & 3;
    #pragma unroll
    for (int mt = 0; mt < 4; mt++) {
        #pragma unroll
        for (int nt = 0; nt < 4; nt++) {
            int col = col0 + wn0 + nt*8 + pq*2;
            float b0 = 0.f, b1 = 0.f;
            if (BIAS) { b0 = bias[col]; b1 = bias[col+1]; }
            #pragma unroll
            for (int h2 = 0; h2 < 2; h2++) {
                int row = row0 + wm0 + mt*16 + gq + h2*8;
                float v0 = acc[mt][nt][h2*2+0] + b0;
                float v1 = acc[mt][nt][h2*2+1] + b1;
                if (RELU) { v0 = fmaxf(v0, 0.f); v1 = fmaxf(v1, 0.f); }
                if (F32OUT)
                    *(float2*)(C + (size_t)row * N + col) = make_float2(v0, v1);
                if (SPLIT) {
                    unsigned int hi, lo;
                    split2h(v0, v1, hi, lo);
                    *(unsigned int*)(Ch + (size_t)row * N + col) = hi;
                    *(unsigned int*)(Cl + (size_t)row * N + col) = lo;
                }
            }
        }
    }
}

// ===================== tensor-core causal flash attention (bf16x3) ============
#define AP 144
#define KMAT 9216              // 64*AP
#define QMAT 18432             // 128*AP
#define FA_Q (2*QMAT)          // 36864
#define FA_STG (4*KMAT)        // 36864
#define FA_SMEM (FA_Q + 2*FA_STG)   // 110592

__global__ void __launch_bounds__(256, 1) flash_tc_kernel()
{
    const int pid = blockIdx.x, bh = blockIdx.y;
    const int b = bh >> 4, h = bh & 15;
    const int tid = threadIdx.x, wid = tid >> 5, lane = tid & 31;
    const int wm = wid * 16;
    const int lr = lane & 15, lh = lane >> 4;

    extern __shared__ __align__(16) char smem[];
    const unsigned int sb = smem_u32(smem);
    const unsigned int sQh = sb, sQl = sb + QMAT;

    for (int run = 0; run < 2; run++) {
        const int qt0 = run ? (15 - pid) : pid;
        const int NKT = 2 * qt0 + 2;

        __syncthreads();

        {
            const __nv_bfloat16* qh = g_qkvh + (size_t)(b*SS + qt0*128)*3072 + h*HDIM;
            const __nv_bfloat16* ql = g_qkvl + (size_t)(b*SS + qt0*128)*3072 + h*HDIM;
            #pragma unroll
            for (int i = 0; i < 4; i++) {
                int lin = tid + (i << 8);
                int r = lin >> 3, ck = lin & 7;
                unsigned int so = r*AP + ck*16;
                size_t g = (size_t)r*3072 + ck*8;
                cp16(sQh + so, qh + g);
                cp16(sQl + so, ql + g);
            }
            CP_COMMIT();
        }

        auto load_kv = [&](int kt, int s) {
            unsigned int base = sb + FA_Q + s * FA_STG;
            size_t rowb = (size_t)(b*SS + kt*64)*3072;
            const __nv_bfloat16* kh = g_qkvh + rowb + 1024 + h*HDIM;
            const __nv_bfloat16* kl = g_qkvl + rowb + 1024 + h*HDIM;
            const __nv_bfloat16* vh = g_qkvh + rowb + 2048 + h*HDIM;
            const __nv_bfloat16* vl = g_qkvl + rowb + 2048 + h*HDIM;
            #pragma unroll
            for (int i = 0; i < 2; i++) {
                int lin = tid + (i << 8);
                int r = lin >> 3, ck = lin & 7;
                unsigned int so = r*AP + ck*16;
                size_t g = (size_t)r*3072 + ck*8;
                cp16(base + so,          kh + g);
                cp16(base + KMAT + so,   kl + g);
                cp16(base + 2*KMAT + so, vh + g);
                cp16(base + 3*KMAT + so, vl + g);
            }
            CP_COMMIT();
        };

        load_kv(0, 0);
        load_kv(1, 1);

        float o[8][4] = {};
        float m0 = -1e30f, m1 = -1e30f, l0 = 0.f, l1 = 0.f;

        for (int kt = 0; kt < NKT; kt++) {
            if (kt < NKT - 1) CP_WAIT1(); else CP_WAIT0();
            __syncthreads();

            const unsigned int kb = sb + FA_Q + (kt & 1) * FA_STG;

            float sc[8][4] = {};
            #pragma unroll
            for (int kd = 0; kd < 4; kd++) {
                unsigned int aqh[4], aql[4];
                unsigned int qro = (unsigned int)(wm + lr)*AP + (kd*2 + lh)*16;
                ldsm4(aqh, sQh + qro);
                ldsm4(aql, sQl + qro);
                #pragma unroll
                for (int g = 0; g < 4; g++) {
                    unsigned int rkh[4], rkl[4];
                    unsigned int kro = (unsigned int)(g*16 + lr)*AP + (kd*2 + lh)*16;
                    ldsm4(rkh, kb + kro);
                    ldsm4(rkl, kb + KMAT + kro);
                    mma_bf16(sc[2*g],   aqh, rkh[0], rkh[2]);
                    mma_bf16(sc[2*g+1], aqh, rkh[1], rkh[3]);
                    mma_bf16(sc[2*g],   aqh, rkl[0], rkl[2]);
                    mma_bf16(sc[2*g+1], aqh, rkl[1], rkl[3]);
                    mma_bf16(sc[2*g],   aql, rkh[0], rkh[2]);
                    mma_bf16(sc[2*g+1], aql, rkh[1], rkh[3]);
                }
            }

            if (kt >= 2*qt0) {
                const int grow0 = qt0*128 + wm + (lane >> 2);
                const int gc0 = kt*64 + (lane & 3)*2;
                #pragma unroll
                for (int nt = 0; nt < 8; nt++) {
                    int c0l = gc0 + nt*8;
                    sc[nt][0] = (c0l     > grow0)   ? -1e30f : sc[nt][0]*0.125f;
                    sc[nt][1] = (c0l + 1 > grow0)   ? -1e30f : sc[nt][1]*0.125f;
                    sc[nt][2] = (c0l     > grow0+8) ? -1e30f : sc[nt][2]*0.125f;
                    sc[nt][3] = (c0l + 1 > grow0+8) ? -1e30f : sc[nt][3]*0.125f;
                }
            } else {
                #pragma unroll
                for (int nt = 0; nt < 8; nt++) {
                    sc[nt][0] *= 0.125f; sc[nt][1] *= 0.125f;
                    sc[nt][2] *= 0.125f; sc[nt][3] *= 0.125f;
                }
            }

            float mx0 = -1e30f, mx1 = -1e30f;
            #pragma unroll
            for (int nt = 0; nt < 8; nt++) {
                mx0 = fmaxf(mx0, fmaxf(sc[nt][0], sc[nt][1]));
                mx1 = fmaxf(mx1, fmaxf(sc[nt][2], sc[nt][3]));
            }
            mx0 = fmaxf(mx0, __shfl_xor_sync(0xffffffffu, mx0, 1));
            mx0 = fmaxf(mx0, __shfl_xor_sync(0xffffffffu, mx0, 2));
            mx1 = fmaxf(mx1, __shfl_xor_sync(0xffffffffu, mx1, 1));
            mx1 = fmaxf(mx1, __shfl_xor_sync(0xffffffffu, mx1, 2));
            float mn0 = fmaxf(m0, mx0), mn1 = fmaxf(m1, mx1);
            float cf0 = __expf(m0 - mn0), cf1 = __expf(m1 - mn1);
            m0 = mn0; m1 = mn1;
            float s0 = 0.f, s1 = 0.f;
            #pragma unroll
            for (int nt = 0; nt < 8; nt++) {
                sc[nt][0] = __expf(sc[nt][0] - mn0);
                sc[nt][1] = __expf(sc[nt][1] - mn0);
                sc[nt][2] = __expf(sc[nt][2] - mn1);
                sc[nt][3] = __expf(sc[nt][3] - mn1);
                s0 += sc[nt][0] + sc[nt][1];
                s1 += sc[nt][2] + sc[nt][3];
            }
            s0 += __shfl_xor_sync(0xffffffffu, s0, 1);
            s0 += __shfl_xor_sync(0xffffffffu, s0, 2);
            s1 += __shfl_xor_sync(0xffffffffu, s1, 1);
            s1 += __shfl_xor_sync(0xffffffffu, s1, 2);
            l0 = l0 * cf0 + s0;
            l1 = l1 * cf1 + s1;
            #pragma unroll
            for (int dt = 0; dt < 8; dt++) {
                o[dt][0] *= cf0; o[dt][1] *= cf0;
                o[dt][2] *= cf1; o[dt][3] *= cf1;
            }

            #pragma unroll
            for (int j = 0; j < 4; j++) {
                unsigned int ph[4], pl[4];
                split2(sc[2*j][0],   sc[2*j][1],   ph[0], pl[0]);
                split2(sc[2*j][2],   sc[2*j][3],   ph[1], pl[1]);
                split2(sc[2*j+1][0], sc[2*j+1][1], ph[2], pl[2]);
                split2(sc[2*j+1][2], sc[2*j+1][3], ph[3], pl[3]);
                #pragma unroll
                for (int g = 0; g < 4; g++) {
                    unsigned int rvh[4], rvl[4];
                    unsigned int vro = (unsigned int)(j*16 + lr)*AP + (g*2 + lh)*16;
                    ldsm4t(rvh, kb + 2*KMAT + vro);
                    ldsm4t(rvl, kb + 3*KMAT + vro);
                    mma_bf16(o[2*g],   ph, rvh[0], rvh[1]);
                    mma_bf16(o[2*g+1], ph, rvh[2], rvh[3]);
                    mma_bf16(o[2*g],   ph, rvl[0], rvl[1]);
                    mma_bf16(o[2*g+1], ph, rvl[2], rvl[3]);
                    mma_bf16(o[2*g],   pl, rvh[0], rvh[1]);
                    mma_bf16(o[2*g+1], pl, rvh[2], rvh[3]);
                }
            }

            __syncthreads();
            if (kt + 2 < NKT) load_kv(kt + 2, kt & 1);
        }

        // ---- epilogue: normalize, split to fp16 hi/lo ----
        const float inv0 = 1.f / l0, inv1 = 1.f / l1;
        const int row0g = qt0*128 + wm + (lane >> 2);
        __half* ohp = g_ah + ((size_t)bh*SS)*HDIM;
        __half* olp = g_al + ((size_t)bh*SS)*HDIM;
        #pragma unroll
        for (int dt = 0; dt < 8; dt++) {
            int d = dt*8 + (lane & 3)*2;
            unsigned int hi, lo;
            split2h(o[dt][0]*inv0, o[dt][1]*inv0, hi, lo);
            *(unsigned int*)(ohp + (size_t)row0g*HDIM + d) = hi;
            *(unsigned int*)(olp + (size_t)row0g*HDIM + d) = lo;
            split2h(o[dt][2]*inv1, o[dt][3]*inv1, hi, lo);
            *(unsigned int*)(ohp + (size_t)(row0g+8)*HDIM + d) = hi;
            *(unsigned int*)(olp + (size_t)(row0g+8)*HDIM + d) = lo;
        }
    }
}

// ===================== LayerNorm =====================
__device__ __forceinline__ float blk_sum(float v, float* sred)
{
    #pragma unroll
    for (int o = 16; o; o >>= 1) v += __shfl_xor_sync(0xffffffffu, v, o);
    int w = threadIdx.x >> 5;
    if ((threadIdx.x & 31) == 0) sred[w] = v;
    __syncthreads();
    float t = (threadIdx.x < 8) ? sred[threadIdx.x] : 0.f;
    if (threadIdx.x < 32) {
        #pragma unroll
        for (int o = 4; o; o >>= 1) t += __shfl_xor_sync(0xffffffffu, t, o);
        if (threadIdx.x == 0) sred[0] = t;
    }
    __syncthreads();
    float r = sred[0];
    __syncthreads();
    return r;
}

template<bool SPLIT>
__global__ void ln_kernel(const float* __restrict__ resid,
                          const float* __restrict__ y,
                          const float* __restrict__ gamma,
                          const float* __restrict__ beta,
                          float* __restrict__ outf,
                          __half* __restrict__ oh,
                          __half* __restrict__ ol)
{
    __shared__ float sred[32];
    const int row = blockIdx.x;
    const int tid = threadIdx.x;

    float4 a = ((const float4*)(resid + (size_t)row * DD))[tid];
    float4 b = ((const float4*)(y     + (size_t)row * DD))[tid];
    float4 v = make_float4(a.x + b.x, a.y + b.y, a.z + b.z, a.w + b.w);

    float total = blk_sum(v.x + v.y + v.z + v.w, sred);
    float mu = total * (1.f / DD);

    float dx = v.x - mu, dy = v.y - mu, dz = v.z - mu, dw = v.w - mu;
    float tot2 = blk_sum(dx*dx + dy*dy + dz*dz + dw*dw, sred);
    float inv = rsqrtf(tot2 * (1.f / DD) + LN_EPS);

    float4 g = ((const float4*)gamma)[tid];
    float4 be = ((const float4*)beta)[tid];
    float ov[4];
    ov[0] = dx * inv * g.x + be.x;
    ov[1] = dy * inv * g.y + be.y;
    ov[2] = dz * inv * g.z + be.z;
    ov[3] = dw * inv * g.w + be.w;
    ((float4*)(outf + (size_t)row * DD))[tid] = make_float4(ov[0], ov[1], ov[2], ov[3]);

    if (SPLIT) {
        unsigned int wh[2], wl[2];
        split2h(ov[0], ov[1], wh[0], wl[0]);
        split2h(ov[2], ov[3], wh[1], wl[1]);
        *(uint2*)(oh + (size_t)row * DD + tid * 4) = make_uint2(wh[0], wh[1]);
        *(uint2*)(ol + (size_t)row * DD + tid * 4) = make_uint2(wl[0], wl[1]);
    }
}

// ===================== launch =====================
extern "C" void kernel_launch(void* const* d_in, const int* in_sizes, int n_in,
                              void* d_out, int out_size)
{
    (void)in_sizes; (void)n_in; (void)out_size;

    const float* x     = (const float*)d_in[0];
    const float* Wq    = (const float*)d_in[1];
    const float* Wk    = (const float*)d_in[2];
    const float* Wv    = (const float*)d_in[3];
    const float* Wo    = (const float*)d_in[4];
    const float* g1    = (const float*)d_in[5];
    const float* be1   = (const float*)d_in[6];
    const float* w_in  = (const float*)d_in[7];
    const float* b_in  = (const float*)d_in[8];
    const float* w_out = (const float*)d_in[9];
    const float* b_out = (const float*)d_in[10];
    const float* g2    = (const float*)d_in[11];
    const float* be2   = (const float*)d_in[12];
    float* out = (float*)d_out;

    float *tmp, *x1;
    __nv_bfloat16 *qkvh, *qkvl, *xh, *xl, *wqkvh, *wqkvl;
    __half *ah, *al, *x1h, *x1l, *h1h, *h1l, *wof, *winf, *woutf;
    cudaGetSymbolAddress((void**)&tmp,  g_tmp);
    cudaGetSymbolAddress((void**)&x1,   g_x1);
    cudaGetSymbolAddress((void**)&qkvh, g_qkvh);  cudaGetSymbolAddress((void**)&qkvl, g_qkvl);
    cudaGetSymbolAddress((void**)&xh,   g_xh);    cudaGetSymbolAddress((void**)&xl,   g_xl);
    cudaGetSymbolAddress((void**)&ah,   g_ah);    cudaGetSymbolAddress((void**)&al,   g_al);
    cudaGetSymbolAddress((void**)&x1h,  g_x1h);   cudaGetSymbolAddress((void**)&x1l,  g_x1l);
    cudaGetSymbolAddress((void**)&h1h,  g_h1h);   cudaGetSymbolAddress((void**)&h1l,  g_h1l);
    cudaGetSymbolAddress((void**)&wqkvh, g_wqkvh); cudaGetSymbolAddress((void**)&wqkvl, g_wqkvl);
    cudaGetSymbolAddress((void**)&wof,   g_wof);
    cudaGetSymbolAddress((void**)&winf,  g_winf);  cudaGetSymbolAddress((void**)&woutf, g_woutf);

    cudaFuncSetAttribute(flash_tc_kernel, cudaFuncAttributeMaxDynamicSharedMemorySize, FA_SMEM);
    cudaFuncSetAttribute(gemm_tc_kernel<false,false,false,true>, cudaFuncAttributeMaxDynamicSharedMemorySize, GT_SMEM);
    cudaFuncSetAttribute(gemm2_kernel<false,false,true,false>, cudaFuncAttributeMaxDynamicSharedMemorySize, G2_SMEM);
    cudaFuncSetAttribute(gemm2_kernel<true,true,false,true>,   cudaFuncAttributeMaxDynamicSharedMemorySize, G2_SMEM);
    cudaFuncSetAttribute(gemm2_kernel<true,false,true,false>,  cudaFuncAttributeMaxDynamicSharedMemorySize, G2_SMEM);

    // ---- prep: split x; transpose/split weights ----
    fsplit_kernel<<<MM*DD/1024, 256>>>(x, xh, xl, MM*DD/4);
    qkvT_kernel<<<dim3(2, 32, 48), dim3(32, 8)>>>(Wq, Wk, Wv, wqkvh, wqkvl);
    wsplit3_kernel<<<9216, dim3(32, 8)>>>(Wo, w_in, w_out);

    // ---- 1) fused QKV projection (bf16x3) -> split bf16 hi/lo ----
    gemm_tc_kernel<false,false,false,true><<<dim3(3072/256, MM/128), 512, GT_SMEM>>>(
        xh, xl, wqkvh, wqkvl, nullptr, nullptr, qkvh, qkvl, MM, 3072, 1024);

    // ---- 2) causal flash attention -> fp16 hi/lo ----
    flash_tc_kernel<<<dim3(SS/256, BB*HH), 256, FA_SMEM>>>();

    // ---- 3) output projection (fp16 2-term, no bias) ----
    gemm2_kernel<false,false,true,false><<<dim3(1024/256, MM/128), 512, G2_SMEM>>>(
        ah, al, wof, nullptr, tmp, nullptr, nullptr, MM, 1024, 1024);

    // ---- 4) LN1 (x + attn@Wo), split to fp16 ----
    ln_kernel<true><<<MM, 256>>>(x, tmp, g1, be1, x1, x1h, x1l);

    // ---- 5) FFN up + bias + ReLU (fp16 2-term), split fp16 output ----
    gemm2_kernel<true,true,false,true><<<dim3(4096/256, MM/128), 512, G2_SMEM>>>(
        x1h, x1l, winf, b_in, nullptr, h1h, h1l, MM, 4096, 1024);

    // ---- 6) FFN down + bias (fp16 2-term) ----
    gemm2_kernel<true,false,true,false><<<dim3(1024/256, MM/128), 512, G2_SMEM>>>(
        h1h, h1l, woutf, b_out, tmp, nullptr, nullptr, MM, 1024, 4096);

    // ---- 7) LN2 -> output ----
    ln_kernel<false><<<MM, 256>>>(x1, tmp, g2, be2, out, nullptr, nullptr);
}

// round 11
// speedup vs baseline: 3.6569x; 1.0968x over previous
#include <cuda_runtime.h>
#include <cuda_bf16.h>
#include <cuda_fp16.h>
#include <math.h>

// Problem constants
#define BB   4
#define SS   2048
#define DD   1024
#define HH   16
#define HDIM 64
#define FF   4096
#define MM   (BB*SS)   // 8192 rows
#define LN_EPS 1e-5f

// ===================== low-level helpers =====================
__device__ __forceinline__ unsigned int smem_u32(const void* p) {
    unsigned int a;
    asm("{ .reg .u64 t; cvta.to.shared.u64 t, %1; cvt.u32.u64 %0, t; }" : "=r"(a) : "l"(p));
    return a;
}
__device__ __forceinline__ void cp16(unsigned int s, const void* g) {
    asm volatile("cp.async.cg.shared.global [%0], [%1], 16;" :: "r"(s), "l"(g));
}
#define CP_COMMIT() asm volatile("cp.async.commit_group;" ::: "memory")
#define CP_WAIT1()  asm volatile("cp.async.wait_group 1;" ::: "memory")
#define CP_WAIT2()  asm volatile("cp.async.wait_group 2;" ::: "memory")
#define CP_WAIT0()  asm volatile("cp.async.wait_group 0;" ::: "memory")

__device__ __forceinline__ void ldsm4(unsigned int* r, unsigned int addr) {
    asm volatile("ldmatrix.sync.aligned.m8n8.x4.shared.b16 {%0,%1,%2,%3}, [%4];"
        : "=r"(r[0]), "=r"(r[1]), "=r"(r[2]), "=r"(r[3]) : "r"(addr));
}
__device__ __forceinline__ void ldsm4t(unsigned int* r, unsigned int addr) {
    asm volatile("ldmatrix.sync.aligned.m8n8.x4.trans.shared.b16 {%0,%1,%2,%3}, [%4];"
        : "=r"(r[0]), "=r"(r[1]), "=r"(r[2]), "=r"(r[3]) : "r"(addr));
}
__device__ __forceinline__ void mma_f16(float* c, const unsigned int* a,
                                        unsigned int b0, unsigned int b1) {
    asm volatile("mma.sync.aligned.m16n8k16.row.col.f32.f16.f16.f32 "
        "{%0,%1,%2,%3}, {%4,%5,%6,%7}, {%8,%9}, {%0,%1,%2,%3};"
        : "+f"(c[0]), "+f"(c[1]), "+f"(c[2]), "+f"(c[3])
        : "r"(a[0]), "r"(a[1]), "r"(a[2]), "r"(a[3]), "r"(b0), "r"(b1));
}
__device__ __forceinline__ unsigned int pack_f16(__half a, __half b) {
    return (unsigned int)__half_as_ushort(a) | ((unsigned int)__half_as_ushort(b) << 16);
}
__device__ __forceinline__ void split2h(float v0, float v1, unsigned int& hi, unsigned int& lo) {
    __half h0 = __float2half(v0);
    __half h1 = __float2half(v1);
    __half l0 = __float2half(v0 - __half2float(h0));
    __half l1 = __float2half(v1 - __half2float(h1));
    hi = pack_f16(h0, h1);
    lo = pack_f16(l0, l1);
}

// ===================== scratch (device globals) =====================
__device__ __half g_qkvh[(size_t)MM*3072], g_qkvl[(size_t)MM*3072];
__device__ __half g_xh[(size_t)MM*DD], g_xl[(size_t)MM*DD];
__device__ __half g_ah[(size_t)MM*DD], g_al[(size_t)MM*DD];
__device__ float g_tmp[(size_t)MM*DD];
__device__ float g_x1[(size_t)MM*DD];
__device__ __half g_x1h[(size_t)MM*DD], g_x1l[(size_t)MM*DD];
__device__ __half g_h1h[(size_t)MM*FF], g_h1l[(size_t)MM*FF];
// transposed single-fp16 weights ([N,K] row-major)
__device__ __half g_wqkvf[(size_t)3072*1024];
__device__ __half g_wof[(size_t)1024*1024];
__device__ __half g_winf[(size_t)4096*1024];
__device__ __half g_woutf[(size_t)1024*4096];

// ===================== prep kernels =====================
__global__ void fsplit_kernel(const float* __restrict__ in,
                              __half* __restrict__ h,
                              __half* __restrict__ l, int n4)
{
    int i = blockIdx.x * blockDim.x + threadIdx.x;
    if (i >= n4) return;
    float4 v = ((const float4*)in)[i];
    unsigned int ph[2], pl[2];
    split2h(v.x, v.y, ph[0], pl[0]);
    split2h(v.z, v.w, ph[1], pl[1]);
    ((uint2*)h)[i] = make_uint2(ph[0], ph[1]);
    ((uint2*)l)[i] = make_uint2(pl[0], pl[1]);
}

// transpose one 32x32 block of W [K,N] -> single fp16 T [N,K]
__device__ __forceinline__ void wsingle_block(const float* __restrict__ W,
                                              __half* __restrict__ T,
                                              int K, int N, int k0, int n0,
                                              float t[32][33])
{
    int tx = threadIdx.x, ty = threadIdx.y;
    #pragma unroll
    for (int i = 0; i < 32; i += 8)
        t[ty + i][tx] = W[(size_t)(k0 + ty + i) * N + n0 + tx];
    __syncthreads();
    #pragma unroll
    for (int i = 0; i < 32; i += 8) {
        float v = t[tx][ty + i];
        T[(size_t)(n0 + ty + i) * K + k0 + tx] = __float2half(v);
    }
}

// merged: Wo fp16 (1024 blocks), w_in fp16 (4096), w_out fp16 (4096)
__global__ void wsplit3_kernel(const float* __restrict__ Wo,
                               const float* __restrict__ Win,
                               const float* __restrict__ Wout)
{
    __shared__ float t[32][33];
    int idx = blockIdx.x;
    if (idx < 1024) {
        wsingle_block(Wo, g_wof, 1024, 1024,
                      (idx >> 5) * 32, (idx & 31) * 32, t);
    } else if (idx < 1024 + 4096) {
        int i2 = idx - 1024;
        wsingle_block(Win, g_winf, 1024, 4096,
                      (i2 >> 7) * 32, (i2 & 127) * 32, t);
    } else {
        int i2 = idx - 5120;
        wsingle_block(Wout, g_woutf, 4096, 1024,
                      (i2 >> 5) * 32, (i2 & 31) * 32, t);
    }
}

// Wq/Wk/Wv [H,D,HD] -> combined transposed single fp16 [3072, 1024]
__global__ void qkvT_kernel(const float* __restrict__ Wq,
                            const float* __restrict__ Wk,
                            const float* __restrict__ Wv,
                            __half* __restrict__ T)
{
    __shared__ float t[32][33];
    int z = blockIdx.z;
    int mat = z / HH, h = z - mat * HH;
    const float* W = (mat == 0 ? Wq : mat == 1 ? Wk : Wv) + (size_t)h * DD * HDIM;
    int k0 = blockIdx.y * 32, e0 = blockIdx.x * 32;
    int tx = threadIdx.x, ty = threadIdx.y;
    #pragma unroll
    for (int i = 0; i < 32; i += 8)
        t[ty + i][tx] = W[(size_t)(k0 + ty + i) * HDIM + e0 + tx];
    __syncthreads();
    int nbase = mat * 1024 + h * HDIM;
    #pragma unroll
    for (int i = 0; i < 32; i += 8) {
        float v = t[tx][ty + i];
        T[(size_t)(nbase + e0 + ty + i) * DD + k0 + tx] = __float2half(v);
    }
}

// swizzled byte offset for (row, 16B-chunk ck) within a 128B-row matrix
#define GSW(r, ck) ((unsigned int)((r) * 128 + ((((ck) ^ ((r) & 7))) << 4)))

// ===================== fp16 2-term GEMM (all projections) ==============
// D = Ah*B + Al*B. A fp16 hi/lo, B single fp16. Block 128x256, K-chunk 64,
// 3-stage pipeline (64KB/stage), 16 warps, warp 64x32.
#define G2_AH 0
#define G2_AL 16384
#define G2_B  32768
#define G2_STG 65536
#define G2_SMEM (3*G2_STG)     // 196608

template<bool BIAS, bool RELU, bool F32OUT, bool SPLIT>
__global__ void __launch_bounds__(512, 1) gemm2_kernel(
    const __half* __restrict__ Ah, const __half* __restrict__ Al,
    const __half* __restrict__ BT,
    const float* __restrict__ bias,
    float* __restrict__ C,
    __half* __restrict__ Ch, __half* __restrict__ Cl,
    int M, int N, int K)
{
    extern __shared__ __align__(128) char smem[];
    const unsigned int sb = smem_u32(smem);
    const int tid = threadIdx.x;
    const int row0 = blockIdx.y * 128;
    const int col0 = blockIdx.x * 256;

    const int wid = tid >> 5, lane = tid & 31;
    const int wm0 = (wid & 1) * 64, wn0 = (wid >> 1) * 32;
    const int lr = lane & 15, lh = lane >> 4;

    auto load_stage = [&](int c, int s) {
        unsigned int base = sb + s * G2_STG;
        int k0 = c * 64;
        #pragma unroll
        for (int i = 0; i < 2; i++) {
            int lin = tid + (i << 9);
            int r = lin >> 3, ck = lin & 7;
            unsigned int so = GSW(r, ck);
            size_t ga = (size_t)(row0 + r) * K + k0 + ck * 8;
            cp16(base + G2_AH + so, Ah + ga);
            cp16(base + G2_AL + so, Al + ga);
        }
        #pragma unroll
        for (int i = 0; i < 4; i++) {
            int lin = tid + (i << 9);
            int r = lin >> 3, ck = lin & 7;
            unsigned int so = GSW(r, ck);
            cp16(base + G2_B + so, BT + (size_t)(col0 + r) * K + k0 + ck * 8);
        }
        CP_COMMIT();
    };

    float acc[4][4][4] = {};

    load_stage(0, 0);
    load_stage(1, 1);
    load_stage(2, 2);

    const int NC = K >> 6;
    for (int c = 0; c < NC; c++) {
        CP_WAIT2();
        __syncthreads();

        unsigned int base = sb + (c % 3) * G2_STG;
        #pragma unroll
        for (int ks = 0; ks < 4; ks++) {
            unsigned int a_h[4][4], a_l[4][4], b_r[2][4];
            #pragma unroll
            for (int mt = 0; mt < 4; mt++) {
                int r = wm0 + mt*16 + lr;
                unsigned int ro = GSW(r, ks*2 + lh);
                ldsm4(a_h[mt], base + G2_AH + ro);
                ldsm4(a_l[mt], base + G2_AL + ro);
            }
            #pragma unroll
            for (int bt = 0; bt < 2; bt++) {
                int r = wn0 + bt*16 + lr;
                unsigned int ro = GSW(r, ks*2 + lh);
                ldsm4(b_r[bt], base + G2_B + ro);
            }
            #pragma unroll
            for (int mt = 0; mt < 4; mt++)
                #pragma unroll
                for (int nt = 0; nt < 4; nt++)
                    mma_f16(acc[mt][nt], a_h[mt], b_r[nt>>1][nt&1], b_r[nt>>1][(nt&1)+2]);
            #pragma unroll
            for (int mt = 0; mt < 4; mt++)
                #pragma unroll
                for (int nt = 0; nt < 4; nt++)
                    mma_f16(acc[mt][nt], a_l[mt], b_r[nt>>1][nt&1], b_r[nt>>1][(nt&1)+2]);
        }

        __syncthreads();
        if (c + 3 < NC) load_stage(c + 3, (c + 3) % 3);
    }

    // ---- epilogue ----
    const int gq = lane >> 2, pq = lane & 3;
    #pragma unroll
    for (int mt = 0; mt < 4; mt++) {
        #pragma unroll
        for (int nt = 0; nt < 4; nt++) {
            int col = col0 + wn0 + nt*8 + pq*2;
            float b0 = 0.f, b1 = 0.f;
            if (BIAS) { b0 = bias[col]; b1 = bias[col+1]; }
            #pragma unroll
            for (int h2 = 0; h2 < 2; h2++) {
                int row = row0 + wm0 + mt*16 + gq + h2*8;
                float v0 = acc[mt][nt][h2*2+0] + b0;
                float v1 = acc[mt][nt][h2*2+1] + b1;
                if (RELU) { v0 = fmaxf(v0, 0.f); v1 = fmaxf(v1, 0.f); }
                if (F32OUT)
                    *(float2*)(C + (size_t)row * N + col) = make_float2(v0, v1);
                if (SPLIT) {
                    unsigned int hi, lo;
                    split2h(v0, v1, hi, lo);
                    *(unsigned int*)(Ch + (size_t)row * N + col) = hi;
                    *(unsigned int*)(Cl + (size_t)row * N + col) = lo;
                }
            }
        }
    }
}

// ===================== tensor-core causal flash attention (fp16) ============
// QK: 3-term fp16 (Q hi/lo x K hi/lo, drop lo*lo); PV: 2-term (P hi/lo x V single).
// KV stage: Kh, Kl, Vh (3 mats).
#define AP 144
#define KMAT 9216              // 64*AP
#define QMAT 18432             // 128*AP
#define FA_Q (2*QMAT)          // 36864
#define FA_STG (3*KMAT)        // 27648
#define FA_SMEM (FA_Q + 2*FA_STG)   // 92160

__global__ void __launch_bounds__(256, 1) flash_tc_kernel()
{
    const int pid = blockIdx.x, bh = blockIdx.y;
    const int b = bh >> 4, h = bh & 15;
    const int tid = threadIdx.x, wid = tid >> 5, lane = tid & 31;
    const int wm = wid * 16;
    const int lr = lane & 15, lh = lane >> 4;

    extern __shared__ __align__(16) char smem[];
    const unsigned int sb = smem_u32(smem);
    const unsigned int sQh = sb, sQl = sb + QMAT;

    for (int run = 0; run < 2; run++) {
        const int qt0 = run ? (15 - pid) : pid;
        const int NKT = 2 * qt0 + 2;

        __syncthreads();

        {
            const __half* qh = g_qkvh + (size_t)(b*SS + qt0*128)*3072 + h*HDIM;
            const __half* ql = g_qkvl + (size_t)(b*SS + qt0*128)*3072 + h*HDIM;
            #pragma unroll
            for (int i = 0; i < 4; i++) {
                int lin = tid + (i << 8);
                int r = lin >> 3, ck = lin & 7;
                unsigned int so = r*AP + ck*16;
                size_t g = (size_t)r*3072 + ck*8;
                cp16(sQh + so, qh + g);
                cp16(sQl + so, ql + g);
            }
            CP_COMMIT();
        }

        auto load_kv = [&](int kt, int s) {
            unsigned int base = sb + FA_Q + s * FA_STG;
            size_t rowb = (size_t)(b*SS + kt*64)*3072;
            const __half* kh = g_qkvh + rowb + 1024 + h*HDIM;
            const __half* kl = g_qkvl + rowb + 1024 + h*HDIM;
            const __half* vh = g_qkvh + rowb + 2048 + h*HDIM;
            #pragma unroll
            for (int i = 0; i < 2; i++) {
                int lin = tid + (i << 8);
                int r = lin >> 3, ck = lin & 7;
                unsigned int so = r*AP + ck*16;
                size_t g = (size_t)r*3072 + ck*8;
                cp16(base + so,          kh + g);
                cp16(base + KMAT + so,   kl + g);
                cp16(base + 2*KMAT + so, vh + g);
            }
            CP_COMMIT();
        };

        load_kv(0, 0);
        load_kv(1, 1);

        float o[8][4] = {};
        float m0 = -1e30f, m1 = -1e30f, l0 = 0.f, l1 = 0.f;

        for (int kt = 0; kt < NKT; kt++) {
            if (kt < NKT - 1) CP_WAIT1(); else CP_WAIT0();
            __syncthreads();

            const unsigned int kb = sb + FA_Q + (kt & 1) * FA_STG;

            // ---- S = Q K^T (3-term fp16) ----
            float sc[8][4] = {};
            #pragma unroll
            for (int kd = 0; kd < 4; kd++) {
                unsigned int aqh[4], aql[4];
                unsigned int qro = (unsigned int)(wm + lr)*AP + (kd*2 + lh)*16;
                ldsm4(aqh, sQh + qro);
                ldsm4(aql, sQl + qro);
                #pragma unroll
                for (int g = 0; g < 4; g++) {
                    unsigned int rkh[4], rkl[4];
                    unsigned int kro = (unsigned int)(g*16 + lr)*AP + (kd*2 + lh)*16;
                    ldsm4(rkh, kb + kro);
                    ldsm4(rkl, kb + KMAT + kro);
                    mma_f16(sc[2*g],   aqh, rkh[0], rkh[2]);
                    mma_f16(sc[2*g+1], aqh, rkh[1], rkh[3]);
                    mma_f16(sc[2*g],   aqh, rkl[0], rkl[2]);
                    mma_f16(sc[2*g+1], aqh, rkl[1], rkl[3]);
                    mma_f16(sc[2*g],   aql, rkh[0], rkh[2]);
                    mma_f16(sc[2*g+1], aql, rkh[1], rkh[3]);
                }
            }

            if (kt >= 2*qt0) {
                const int grow0 = qt0*128 + wm + (lane >> 2);
                const int gc0 = kt*64 + (lane & 3)*2;
                #pragma unroll
                for (int nt = 0; nt < 8; nt++) {
                    int c0l = gc0 + nt*8;
                    sc[nt][0] = (c0l     > grow0)   ? -1e30f : sc[nt][0]*0.125f;
                    sc[nt][1] = (c0l + 1 > grow0)   ? -1e30f : sc[nt][1]*0.125f;
                    sc[nt][2] = (c0l     > grow0+8) ? -1e30f : sc[nt][2]*0.125f;
                    sc[nt][3] = (c0l + 1 > grow0+8) ? -1e30f : sc[nt][3]*0.125f;
                }
            } else {
                #pragma unroll
                for (int nt = 0; nt < 8; nt++) {
                    sc[nt][0] *= 0.125f; sc[nt][1] *= 0.125f;
                    sc[nt][2] *= 0.125f; sc[nt][3] *= 0.125f;
                }
            }

            float mx0 = -1e30f, mx1 = -1e30f;
            #pragma unroll
            for (int nt = 0; nt < 8; nt++) {
                mx0 = fmaxf(mx0, fmaxf(sc[nt][0], sc[nt][1]));
                mx1 = fmaxf(mx1, fmaxf(sc[nt][2], sc[nt][3]));
            }
            mx0 = fmaxf(mx0, __shfl_xor_sync(0xffffffffu, mx0, 1));
            mx0 = fmaxf(mx0, __shfl_xor_sync(0xffffffffu, mx0, 2));
            mx1 = fmaxf(mx1, __shfl_xor_sync(0xffffffffu, mx1, 1));
            mx1 = fmaxf(mx1, __shfl_xor_sync(0xffffffffu, mx1, 2));
            float mn0 = fmaxf(m0, mx0), mn1 = fmaxf(m1, mx1);
            float cf0 = __expf(m0 - mn0), cf1 = __expf(m1 - mn1);
            m0 = mn0; m1 = mn1;
            float s0 = 0.f, s1 = 0.f;
            #pragma unroll
            for (int nt = 0; nt < 8; nt++) {
                sc[nt][0] = __expf(sc[nt][0] - mn0);
                sc[nt][1] = __expf(sc[nt][1] - mn0);
                sc[nt][2] = __expf(sc[nt][2] - mn1);
                sc[nt][3] = __expf(sc[nt][3] - mn1);
                s0 += sc[nt][0] + sc[nt][1];
                s1 += sc[nt][2] + sc[nt][3];
            }
            s0 += __shfl_xor_sync(0xffffffffu, s0, 1);
            s0 += __shfl_xor_sync(0xffffffffu, s0, 2);
            s1 += __shfl_xor_sync(0xffffffffu, s1, 1);
            s1 += __shfl_xor_sync(0xffffffffu, s1, 2);
            l0 = l0 * cf0 + s0;
            l1 = l1 * cf1 + s1;
            #pragma unroll
            for (int dt = 0; dt < 8; dt++) {
                o[dt][0] *= cf0; o[dt][1] *= cf0;
                o[dt][2] *= cf1; o[dt][3] *= cf1;
            }

            // ---- O += P V (2-term: P hi/lo x single V) ----
            #pragma unroll
            for (int j = 0; j < 4; j++) {
                unsigned int ph[4], pl[4];
                split2h(sc[2*j][0],   sc[2*j][1],   ph[0], pl[0]);
                split2h(sc[2*j][2],   sc[2*j][3],   ph[1], pl[1]);
                split2h(sc[2*j+1][0], sc[2*j+1][1], ph[2], pl[2]);
                split2h(sc[2*j+1][2], sc[2*j+1][3], ph[3], pl[3]);
                #pragma unroll
                for (int g = 0; g < 4; g++) {
                    unsigned int rvh[4];
                    unsigned int vro = (unsigned int)(j*16 + lr)*AP + (g*2 + lh)*16;
                    ldsm4t(rvh, kb + 2*KMAT + vro);
                    mma_f16(o[2*g],   ph, rvh[0], rvh[1]);
                    mma_f16(o[2*g+1], ph, rvh[2], rvh[3]);
                    mma_f16(o[2*g],   pl, rvh[0], rvh[1]);
                    mma_f16(o[2*g+1], pl, rvh[2], rvh[3]);
                }
            }

            __syncthreads();
            if (kt + 2 < NKT) load_kv(kt + 2, kt & 1);
        }

        // ---- epilogue: normalize, split to fp16 hi/lo ----
        const float inv0 = 1.f / l0, inv1 = 1.f / l1;
        const int row0g = qt0*128 + wm + (lane >> 2);
        __half* ohp = g_ah + ((size_t)bh*SS)*HDIM;
        __half* olp = g_al + ((size_t)bh*SS)*HDIM;
        #pragma unroll
        for (int dt = 0; dt < 8; dt++) {
            int d = dt*8 + (lane & 3)*2;
            unsigned int hi, lo;
            split2h(o[dt][0]*inv0, o[dt][1]*inv0, hi, lo);
            *(unsigned int*)(ohp + (size_t)row0g*HDIM + d) = hi;
            *(unsigned int*)(olp + (size_t)row0g*HDIM + d) = lo;
            split2h(o[dt][2]*inv1, o[dt][3]*inv1, hi, lo);
            *(unsigned int*)(ohp + (size_t)(row0g+8)*HDIM + d) = hi;
            *(unsigned int*)(olp + (size_t)(row0g+8)*HDIM + d) = lo;
        }
    }
}

// ===================== LayerNorm =====================
__device__ __forceinline__ float blk_sum(float v, float* sred)
{
    #pragma unroll
    for (int o = 16; o; o >>= 1) v += __shfl_xor_sync(0xffffffffu, v, o);
    int w = threadIdx.x >> 5;
    if ((threadIdx.x & 31) == 0) sred[w] = v;
    __syncthreads();
    float t = (threadIdx.x < 8) ? sred[threadIdx.x] : 0.f;
    if (threadIdx.x < 32) {
        #pragma unroll
        for (int o = 4; o; o >>= 1) t += __shfl_xor_sync(0xffffffffu, t, o);
        if (threadIdx.x == 0) sred[0] = t;
    }
    __syncthreads();
    float r = sred[0];
    __syncthreads();
    return r;
}

template<bool SPLIT>
__global__ void ln_kernel(const float* __restrict__ resid,
                          const float* __restrict__ y,
                          const float* __restrict__ gamma,
                          const float* __restrict__ beta,
                          float* __restrict__ outf,
                          __half* __restrict__ oh,
                          __half* __restrict__ ol)
{
    __shared__ float sred[32];
    const int row = blockIdx.x;
    const int tid = threadIdx.x;

    float4 a = ((const float4*)(resid + (size_t)row * DD))[tid];
    float4 b = ((const float4*)(y     + (size_t)row * DD))[tid];
    float4 v = make_float4(a.x + b.x, a.y + b.y, a.z + b.z, a.w + b.w);

    float total = blk_sum(v.x + v.y + v.z + v.w, sred);
    float mu = total * (1.f / DD);

    float dx = v.x - mu, dy = v.y - mu, dz = v.z - mu, dw = v.w - mu;
    float tot2 = blk_sum(dx*dx + dy*dy + dz*dz + dw*dw, sred);
    float inv = rsqrtf(tot2 * (1.f / DD) + LN_EPS);

    float4 g = ((const float4*)gamma)[tid];
    float4 be = ((const float4*)beta)[tid];
    float ov[4];
    ov[0] = dx * inv * g.x + be.x;
    ov[1] = dy * inv * g.y + be.y;
    ov[2] = dz * inv * g.z + be.z;
    ov[3] = dw * inv * g.w + be.w;
    ((float4*)(outf + (size_t)row * DD))[tid] = make_float4(ov[0], ov[1], ov[2], ov[3]);

    if (SPLIT) {
        unsigned int wh[2], wl[2];
        split2h(ov[0], ov[1], wh[0], wl[0]);
        split2h(ov[2], ov[3], wh[1], wl[1]);
        *(uint2*)(oh + (size_t)row * DD + tid * 4) = make_uint2(wh[0], wh[1]);
        *(uint2*)(ol + (size_t)row * DD + tid * 4) = make_uint2(wl[0], wl[1]);
    }
}

// ===================== launch =====================
extern "C" void kernel_launch(void* const* d_in, const int* in_sizes, int n_in,
                              void* d_out, int out_size)
{
    (void)in_sizes; (void)n_in; (void)out_size;

    const float* x     = (const float*)d_in[0];
    const float* Wq    = (const float*)d_in[1];
    const float* Wk    = (const float*)d_in[2];
    const float* Wv    = (const float*)d_in[3];
    const float* Wo    = (const float*)d_in[4];
    const float* g1    = (const float*)d_in[5];
    const float* be1   = (const float*)d_in[6];
    const float* w_in  = (const float*)d_in[7];
    const float* b_in  = (const float*)d_in[8];
    const float* w_out = (const float*)d_in[9];
    const float* b_out = (const float*)d_in[10];
    const float* g2    = (const float*)d_in[11];
    const float* be2   = (const float*)d_in[12];
    float* out = (float*)d_out;

    float *tmp, *x1;
    __half *qkvh, *qkvl, *xh, *xl, *ah, *al, *x1h, *x1l, *h1h, *h1l;
    __half *wqkvf, *wof, *winf, *woutf;
    cudaGetSymbolAddress((void**)&tmp,  g_tmp);
    cudaGetSymbolAddress((void**)&x1,   g_x1);
    cudaGetSymbolAddress((void**)&qkvh, g_qkvh);  cudaGetSymbolAddress((void**)&qkvl, g_qkvl);
    cudaGetSymbolAddress((void**)&xh,   g_xh);    cudaGetSymbolAddress((void**)&xl,   g_xl);
    cudaGetSymbolAddress((void**)&ah,   g_ah);    cudaGetSymbolAddress((void**)&al,   g_al);
    cudaGetSymbolAddress((void**)&x1h,  g_x1h);   cudaGetSymbolAddress((void**)&x1l,  g_x1l);
    cudaGetSymbolAddress((void**)&h1h,  g_h1h);   cudaGetSymbolAddress((void**)&h1l,  g_h1l);
    cudaGetSymbolAddress((void**)&wqkvf, g_wqkvf);
    cudaGetSymbolAddress((void**)&wof,   g_wof);
    cudaGetSymbolAddress((void**)&winf,  g_winf);  cudaGetSymbolAddress((void**)&woutf, g_woutf);

    cudaFuncSetAttribute(flash_tc_kernel, cudaFuncAttributeMaxDynamicSharedMemorySize, FA_SMEM);
    cudaFuncSetAttribute(gemm2_kernel<false,false,false,true>, cudaFuncAttributeMaxDynamicSharedMemorySize, G2_SMEM);
    cudaFuncSetAttribute(gemm2_kernel<false,false,true,false>, cudaFuncAttributeMaxDynamicSharedMemorySize, G2_SMEM);
    cudaFuncSetAttribute(gemm2_kernel<true,true,false,true>,   cudaFuncAttributeMaxDynamicSharedMemorySize, G2_SMEM);
    cudaFuncSetAttribute(gemm2_kernel<true,false,true,false>,  cudaFuncAttributeMaxDynamicSharedMemorySize, G2_SMEM);

    // ---- prep: split x to fp16; transpose weights to single fp16 ----
    fsplit_kernel<<<MM*DD/1024, 256>>>(x, xh, xl, MM*DD/4);
    qkvT_kernel<<<dim3(2, 32, 48), dim3(32, 8)>>>(Wq, Wk, Wv, wqkvf);
    wsplit3_kernel<<<9216, dim3(32, 8)>>>(Wo, w_in, w_out);

    // ---- 1) fused QKV projection (fp16 2-term) -> split fp16 hi/lo ----
    gemm2_kernel<false,false,false,true><<<dim3(3072/256, MM/128), 512, G2_SMEM>>>(
        xh, xl, wqkvf, nullptr, nullptr, qkvh, qkvl, MM, 3072, 1024);

    // ---- 2) causal flash attention -> fp16 hi/lo ----
    flash_tc_kernel<<<dim3(SS/256, BB*HH), 256, FA_SMEM>>>();

    // ---- 3) output projection (fp16 2-term, no bias) ----
    gemm2_kernel<false,false,true,false><<<dim3(1024/256, MM/128), 512, G2_SMEM>>>(
        ah, al, wof, nullptr, tmp, nullptr, nullptr, MM, 1024, 1024);

    // ---- 4) LN1 (x + attn@Wo), split to fp16 ----
    ln_kernel<true><<<MM, 256>>>(x, tmp, g1, be1, x1, x1h, x1l);

    // ---- 5) FFN up + bias + ReLU (fp16 2-term), split fp16 output ----
    gemm2_kernel<true,true,false,true><<<dim3(4096/256, MM/128), 512, G2_SMEM>>>(
        x1h, x1l, winf, b_in, nullptr, h1h, h1l, MM, 4096, 1024);

    // ---- 6) FFN down + bias (fp16 2-term) ----
    gemm2_kernel<true,false,true,false><<<dim3(1024/256, MM/128), 512, G2_SMEM>>>(
        h1h, h1l, woutf, b_out, tmp, nullptr, nullptr, MM, 1024, 4096);

    // ---- 7) LN2 -> output ----
    ln_kernel<false><<<MM, 256>>>(x1, tmp, g2, be2, out, nullptr, nullptr);
}

// round 12
// speedup vs baseline: 4.8169x; 1.3172x over previous
#include <cuda_runtime.h>
#include <cuda_bf16.h>
#include <cuda_fp16.h>
#include <math.h>

// Problem constants
#define BB   4
#define SS   2048
#define DD   1024
#define HH   16
#define HDIM 64
#define FF   4096
#define MM   (BB*SS)   // 8192 rows
#define LN_EPS 1e-5f

// ===================== low-level helpers =====================
__device__ __forceinline__ unsigned int smem_u32(const void* p) {
    unsigned int a;
    asm("{ .reg .u64 t; cvta.to.shared.u64 t, %1; cvt.u32.u64 %0, t; }" : "=r"(a) : "l"(p));
    return a;
}
__device__ __forceinline__ void cp16(unsigned int s, const void* g) {
    asm volatile("cp.async.cg.shared.global [%0], [%1], 16;" :: "r"(s), "l"(g));
}
#define CP_COMMIT() asm volatile("cp.async.commit_group;" ::: "memory")
#define CP_WAIT1()  asm volatile("cp.async.wait_group 1;" ::: "memory")
#define CP_WAIT2()  asm volatile("cp.async.wait_group 2;" ::: "memory")
#define CP_WAIT0()  asm volatile("cp.async.wait_group 0;" ::: "memory")

__device__ __forceinline__ void ldsm4(unsigned int* r, unsigned int addr) {
    asm volatile("ldmatrix.sync.aligned.m8n8.x4.shared.b16 {%0,%1,%2,%3}, [%4];"
        : "=r"(r[0]), "=r"(r[1]), "=r"(r[2]), "=r"(r[3]) : "r"(addr));
}
__device__ __forceinline__ void ldsm4t(unsigned int* r, unsigned int addr) {
    asm volatile("ldmatrix.sync.aligned.m8n8.x4.trans.shared.b16 {%0,%1,%2,%3}, [%4];"
        : "=r"(r[0]), "=r"(r[1]), "=r"(r[2]), "=r"(r[3]) : "r"(addr));
}
__device__ __forceinline__ void mma_f16(float* c, const unsigned int* a,
                                        unsigned int b0, unsigned int b1) {
    asm volatile("mma.sync.aligned.m16n8k16.row.col.f32.f16.f16.f32 "
        "{%0,%1,%2,%3}, {%4,%5,%6,%7}, {%8,%9}, {%0,%1,%2,%3};"
        : "+f"(c[0]), "+f"(c[1]), "+f"(c[2]), "+f"(c[3])
        : "r"(a[0]), "r"(a[1]), "r"(a[2]), "r"(a[3]), "r"(b0), "r"(b1));
}
__device__ __forceinline__ unsigned int pack_f16(__half a, __half b) {
    return (unsigned int)__half_as_ushort(a) | ((unsigned int)__half_as_ushort(b) << 16);
}
__device__ __forceinline__ void split2h(float v0, float v1, unsigned int& hi, unsigned int& lo) {
    __half h0 = __float2half(v0);
    __half h1 = __float2half(v1);
    __half l0 = __float2half(v0 - __half2float(h0));
    __half l1 = __float2half(v1 - __half2float(h1));
    hi = pack_f16(h0, h1);
    lo = pack_f16(l0, l1);
}

// ===================== scratch (device globals) =====================
__device__ __half g_qkvh[(size_t)MM*3072], g_qkvl[(size_t)MM*3072];
__device__ __half g_xh[(size_t)MM*DD], g_xl[(size_t)MM*DD];
__device__ __half g_ah[(size_t)MM*DD], g_al[(size_t)MM*DD];
__device__ float g_tmp[(size_t)MM*DD];
__device__ float g_x1[(size_t)MM*DD];
__device__ __half g_x1f[(size_t)MM*DD];        // LN1 out, single fp16
__device__ __half g_h1f[(size_t)MM*FF];        // FFN hidden, single fp16
// transposed single-fp16 weights ([N,K] row-major)
__device__ __half g_wqkvf[(size_t)3072*1024];
__device__ __half g_wof[(size_t)1024*1024];
__device__ __half g_winf[(size_t)4096*1024];
__device__ __half g_woutf[(size_t)1024*4096];

// ===================== prep kernels =====================
__global__ void fsplit_kernel(const float* __restrict__ in,
                              __half* __restrict__ h,
                              __half* __restrict__ l, int n4)
{
    int i = blockIdx.x * blockDim.x + threadIdx.x;
    if (i >= n4) return;
    float4 v = ((const float4*)in)[i];
    unsigned int ph[2], pl[2];
    split2h(v.x, v.y, ph[0], pl[0]);
    split2h(v.z, v.w, ph[1], pl[1]);
    ((uint2*)h)[i] = make_uint2(ph[0], ph[1]);
    ((uint2*)l)[i] = make_uint2(pl[0], pl[1]);
}

// transpose one 32x32 block of W [K,N] -> single fp16 T [N,K]
__device__ __forceinline__ void wsingle_block(const float* __restrict__ W,
                                              __half* __restrict__ T,
                                              int K, int N, int k0, int n0,
                                              float t[32][33])
{
    int tx = threadIdx.x, ty = threadIdx.y;
    #pragma unroll
    for (int i = 0; i < 32; i += 8)
        t[ty + i][tx] = W[(size_t)(k0 + ty + i) * N + n0 + tx];
    __syncthreads();
    #pragma unroll
    for (int i = 0; i < 32; i += 8) {
        float v = t[tx][ty + i];
        T[(size_t)(n0 + ty + i) * K + k0 + tx] = __float2half(v);
    }
}

// merged: Wo fp16 (1024 blocks), w_in fp16 (4096), w_out fp16 (4096)
__global__ void wsplit3_kernel(const float* __restrict__ Wo,
                               const float* __restrict__ Win,
                               const float* __restrict__ Wout)
{
    __shared__ float t[32][33];
    int idx = blockIdx.x;
    if (idx < 1024) {
        wsingle_block(Wo, g_wof, 1024, 1024,
                      (idx >> 5) * 32, (idx & 31) * 32, t);
    } else if (idx < 1024 + 4096) {
        int i2 = idx - 1024;
        wsingle_block(Win, g_winf, 1024, 4096,
                      (i2 >> 7) * 32, (i2 & 127) * 32, t);
    } else {
        int i2 = idx - 5120;
        wsingle_block(Wout, g_woutf, 4096, 1024,
                      (i2 >> 5) * 32, (i2 & 31) * 32, t);
    }
}

// Wq/Wk/Wv [H,D,HD] -> combined transposed single fp16 [3072, 1024]
__global__ void qkvT_kernel(const float* __restrict__ Wq,
                            const float* __restrict__ Wk,
                            const float* __restrict__ Wv,
                            __half* __restrict__ T)
{
    __shared__ float t[32][33];
    int z = blockIdx.z;
    int mat = z / HH, h = z - mat * HH;
    const float* W = (mat == 0 ? Wq : mat == 1 ? Wk : Wv) + (size_t)h * DD * HDIM;
    int k0 = blockIdx.y * 32, e0 = blockIdx.x * 32;
    int tx = threadIdx.x, ty = threadIdx.y;
    #pragma unroll
    for (int i = 0; i < 32; i += 8)
        t[ty + i][tx] = W[(size_t)(k0 + ty + i) * HDIM + e0 + tx];
    __syncthreads();
    int nbase = mat * 1024 + h * HDIM;
    #pragma unroll
    for (int i = 0; i < 32; i += 8) {
        float v = t[tx][ty + i];
        T[(size_t)(nbase + e0 + ty + i) * DD + k0 + tx] = __float2half(v);
    }
}

// swizzled byte offset for (row, 16B-chunk ck) within a 128B-row matrix
#define GSW(r, ck) ((unsigned int)((r) * 128 + ((((ck) ^ ((r) & 7))) << 4)))

// ===================== fp16 2-term GEMM (QKV / Wo) ==============
// D = Ah*B + Al*B. Block 128x256, K-chunk 64, 3-stage (64KB/stage), 16 warps.
#define G2_AH 0
#define G2_AL 16384
#define G2_B  32768
#define G2_STG 65536
#define G2_SMEM (3*G2_STG)     // 196608

template<bool BIAS, bool RELU, bool F32OUT, bool SPLIT>
__global__ void __launch_bounds__(512, 1) gemm2_kernel(
    const __half* __restrict__ Ah, const __half* __restrict__ Al,
    const __half* __restrict__ BT,
    const float* __restrict__ bias,
    float* __restrict__ C,
    __half* __restrict__ Ch, __half* __restrict__ Cl,
    int M, int N, int K)
{
    extern __shared__ __align__(128) char smem[];
    const unsigned int sb = smem_u32(smem);
    const int tid = threadIdx.x;
    const int row0 = blockIdx.y * 128;
    const int col0 = blockIdx.x * 256;

    const int wid = tid >> 5, lane = tid & 31;
    const int wm0 = (wid & 1) * 64, wn0 = (wid >> 1) * 32;
    const int lr = lane & 15, lh = lane >> 4;

    auto load_stage = [&](int c, int s) {
        unsigned int base = sb + s * G2_STG;
        int k0 = c * 64;
        #pragma unroll
        for (int i = 0; i < 2; i++) {
            int lin = tid + (i << 9);
            int r = lin >> 3, ck = lin & 7;
            unsigned int so = GSW(r, ck);
            size_t ga = (size_t)(row0 + r) * K + k0 + ck * 8;
            cp16(base + G2_AH + so, Ah + ga);
            cp16(base + G2_AL + so, Al + ga);
        }
        #pragma unroll
        for (int i = 0; i < 4; i++) {
            int lin = tid + (i << 9);
            int r = lin >> 3, ck = lin & 7;
            unsigned int so = GSW(r, ck);
            cp16(base + G2_B + so, BT + (size_t)(col0 + r) * K + k0 + ck * 8);
        }
        CP_COMMIT();
    };

    float acc[4][4][4] = {};

    load_stage(0, 0);
    load_stage(1, 1);
    load_stage(2, 2);

    const int NC = K >> 6;
    for (int c = 0; c < NC; c++) {
        CP_WAIT2();
        __syncthreads();

        unsigned int base = sb + (c % 3) * G2_STG;
        #pragma unroll
        for (int ks = 0; ks < 4; ks++) {
            unsigned int a_h[4][4], a_l[4][4], b_r[2][4];
            #pragma unroll
            for (int mt = 0; mt < 4; mt++) {
                int r = wm0 + mt*16 + lr;
                unsigned int ro = GSW(r, ks*2 + lh);
                ldsm4(a_h[mt], base + G2_AH + ro);
                ldsm4(a_l[mt], base + G2_AL + ro);
            }
            #pragma unroll
            for (int bt = 0; bt < 2; bt++) {
                int r = wn0 + bt*16 + lr;
                unsigned int ro = GSW(r, ks*2 + lh);
                ldsm4(b_r[bt], base + G2_B + ro);
            }
            #pragma unroll
            for (int mt = 0; mt < 4; mt++)
                #pragma unroll
                for (int nt = 0; nt < 4; nt++)
                    mma_f16(acc[mt][nt], a_h[mt], b_r[nt>>1][nt&1], b_r[nt>>1][(nt&1)+2]);
            #pragma unroll
            for (int mt = 0; mt < 4; mt++)
                #pragma unroll
                for (int nt = 0; nt < 4; nt++)
                    mma_f16(acc[mt][nt], a_l[mt], b_r[nt>>1][nt&1], b_r[nt>>1][(nt&1)+2]);
        }

        __syncthreads();
        if (c + 3 < NC) load_stage(c + 3, (c + 3) % 3);
    }

    // ---- epilogue ----
    const int gq = lane >> 2, pq = lane & 3;
    #pragma unroll
    for (int mt = 0; mt < 4; mt++) {
        #pragma unroll
        for (int nt = 0; nt < 4; nt++) {
            int col = col0 + wn0 + nt*8 + pq*2;
            float b0 = 0.f, b1 = 0.f;
            if (BIAS) { b0 = bias[col]; b1 = bias[col+1]; }
            #pragma unroll
            for (int h2 = 0; h2 < 2; h2++) {
                int row = row0 + wm0 + mt*16 + gq + h2*8;
                float v0 = acc[mt][nt][h2*2+0] + b0;
                float v1 = acc[mt][nt][h2*2+1] + b1;
                if (RELU) { v0 = fmaxf(v0, 0.f); v1 = fmaxf(v1, 0.f); }
                if (F32OUT)
                    *(float2*)(C + (size_t)row * N + col) = make_float2(v0, v1);
                if (SPLIT) {
                    unsigned int hi, lo;
                    split2h(v0, v1, hi, lo);
                    *(unsigned int*)(Ch + (size_t)row * N + col) = hi;
                    *(unsigned int*)(Cl + (size_t)row * N + col) = lo;
                }
            }
        }
    }
}

// ===================== single-fp16 1-term GEMM (FFN up/down) ==============
// D = A*B. A single fp16 [M,K], B single fp16 [N,K]. Block 128x256,
// K-chunk 64, 3-stage (48KB/stage), 16 warps, warp 64x32.
#define G1_A  0
#define G1_B  16384
#define G1_STG 49152
#define G1_SMEM (3*G1_STG)     // 147456

template<bool BIAS, bool RELU, bool F32OUT, bool HALFOUT>
__global__ void __launch_bounds__(512, 1) gemm1_kernel(
    const __half* __restrict__ A,
    const __half* __restrict__ BT,
    const float* __restrict__ bias,
    float* __restrict__ C,
    __half* __restrict__ Ch,
    int M, int N, int K)
{
    extern __shared__ __align__(128) char smem[];
    const unsigned int sb = smem_u32(smem);
    const int tid = threadIdx.x;
    const int row0 = blockIdx.y * 128;
    const int col0 = blockIdx.x * 256;

    const int wid = tid >> 5, lane = tid & 31;
    const int wm0 = (wid & 1) * 64, wn0 = (wid >> 1) * 32;
    const int lr = lane & 15, lh = lane >> 4;

    auto load_stage = [&](int c, int s) {
        unsigned int base = sb + s * G1_STG;
        int k0 = c * 64;
        #pragma unroll
        for (int i = 0; i < 2; i++) {
            int lin = tid + (i << 9);            // 0..1023 : A rows, 8 chunks
            int r = lin >> 3, ck = lin & 7;
            unsigned int so = GSW(r, ck);
            cp16(base + G1_A + so, A + (size_t)(row0 + r) * K + k0 + ck * 8);
        }
        #pragma unroll
        for (int i = 0; i < 4; i++) {
            int lin = tid + (i << 9);            // 0..2047 : B rows, 8 chunks
            int r = lin >> 3, ck = lin & 7;
            unsigned int so = GSW(r, ck);
            cp16(base + G1_B + so, BT + (size_t)(col0 + r) * K + k0 + ck * 8);
        }
        CP_COMMIT();
    };

    float acc[4][4][4] = {};

    load_stage(0, 0);
    load_stage(1, 1);
    load_stage(2, 2);

    const int NC = K >> 6;
    for (int c = 0; c < NC; c++) {
        CP_WAIT2();
        __syncthreads();

        unsigned int base = sb + (c % 3) * G1_STG;
        #pragma unroll
        for (int ks = 0; ks < 4; ks++) {
            unsigned int a_r[4][4], b_r[2][4];
            #pragma unroll
            for (int mt = 0; mt < 4; mt++) {
                int r = wm0 + mt*16 + lr;
                unsigned int ro = GSW(r, ks*2 + lh);
                ldsm4(a_r[mt], base + G1_A + ro);
            }
            #pragma unroll
            for (int bt = 0; bt < 2; bt++) {
                int r = wn0 + bt*16 + lr;
                unsigned int ro = GSW(r, ks*2 + lh);
                ldsm4(b_r[bt], base + G1_B + ro);
            }
            #pragma unroll
            for (int mt = 0; mt < 4; mt++)
                #pragma unroll
                for (int nt = 0; nt < 4; nt++)
                    mma_f16(acc[mt][nt], a_r[mt], b_r[nt>>1][nt&1], b_r[nt>>1][(nt&1)+2]);
        }

        __syncthreads();
        if (c + 3 < NC) load_stage(c + 3, (c + 3) % 3);
    }

    // ---- epilogue ----
    const int gq = lane >> 2, pq = lane & 3;
    #pragma unroll
    for (int mt = 0; mt < 4; mt++) {
        #pragma unroll
        for (int nt = 0; nt < 4; nt++) {
            int col = col0 + wn0 + nt*8 + pq*2;
            float b0 = 0.f, b1 = 0.f;
            if (BIAS) { b0 = bias[col]; b1 = bias[col+1]; }
            #pragma unroll
            for (int h2 = 0; h2 < 2; h2++) {
                int row = row0 + wm0 + mt*16 + gq + h2*8;
                float v0 = acc[mt][nt][h2*2+0] + b0;
                float v1 = acc[mt][nt][h2*2+1] + b1;
                if (RELU) { v0 = fmaxf(v0, 0.f); v1 = fmaxf(v1, 0.f); }
                if (F32OUT)
                    *(float2*)(C + (size_t)row * N + col) = make_float2(v0, v1);
                if (HALFOUT)
                    *(unsigned int*)(Ch + (size_t)row * N + col) =
                        pack_f16(__float2half(v0), __float2half(v1));
            }
        }
    }
}

// ===================== tensor-core causal flash attention (fp16) ============
// QK: 3-term fp16; PV: 2-term (P hi/lo x single V). KV stage: Kh, Kl, Vh.
#define AP 144
#define KMAT 9216              // 64*AP
#define QMAT 18432             // 128*AP
#define FA_Q (2*QMAT)          // 36864
#define FA_STG (3*KMAT)        // 27648
#define FA_SMEM (FA_Q + 2*FA_STG)   // 92160

__global__ void __launch_bounds__(256, 1) flash_tc_kernel()
{
    const int pid = blockIdx.x, bh = blockIdx.y;
    const int b = bh >> 4, h = bh & 15;
    const int tid = threadIdx.x, wid = tid >> 5, lane = tid & 31;
    const int wm = wid * 16;
    const int lr = lane & 15, lh = lane >> 4;

    extern __shared__ __align__(16) char smem[];
    const unsigned int sb = smem_u32(smem);
    const unsigned int sQh = sb, sQl = sb + QMAT;

    for (int run = 0; run < 2; run++) {
        const int qt0 = run ? (15 - pid) : pid;
        const int NKT = 2 * qt0 + 2;

        __syncthreads();

        {
            const __half* qh = g_qkvh + (size_t)(b*SS + qt0*128)*3072 + h*HDIM;
            const __half* ql = g_qkvl + (size_t)(b*SS + qt0*128)*3072 + h*HDIM;
            #pragma unroll
            for (int i = 0; i < 4; i++) {
                int lin = tid + (i << 8);
                int r = lin >> 3, ck = lin & 7;
                unsigned int so = r*AP + ck*16;
                size_t g = (size_t)r*3072 + ck*8;
                cp16(sQh + so, qh + g);
                cp16(sQl + so, ql + g);
            }
            CP_COMMIT();
        }

        auto load_kv = [&](int kt, int s) {
            unsigned int base = sb + FA_Q + s * FA_STG;
            size_t rowb = (size_t)(b*SS + kt*64)*3072;
            const __half* kh = g_qkvh + rowb + 1024 + h*HDIM;
            const __half* kl = g_qkvl + rowb + 1024 + h*HDIM;
            const __half* vh = g_qkvh + rowb + 2048 + h*HDIM;
            #pragma unroll
            for (int i = 0; i < 2; i++) {
                int lin = tid + (i << 8);
                int r = lin >> 3, ck = lin & 7;
                unsigned int so = r*AP + ck*16;
                size_t g = (size_t)r*3072 + ck*8;
                cp16(base + so,          kh + g);
                cp16(base + KMAT + so,   kl + g);
                cp16(base + 2*KMAT + so, vh + g);
            }
            CP_COMMIT();
        };

        load_kv(0, 0);
        load_kv(1, 1);

        float o[8][4] = {};
        float m0 = -1e30f, m1 = -1e30f, l0 = 0.f, l1 = 0.f;

        for (int kt = 0; kt < NKT; kt++) {
            if (kt < NKT - 1) CP_WAIT1(); else CP_WAIT0();
            __syncthreads();

            const unsigned int kb = sb + FA_Q + (kt & 1) * FA_STG;

            float sc[8][4] = {};
            #pragma unroll
            for (int kd = 0; kd < 4; kd++) {
                unsigned int aqh[4], aql[4];
                unsigned int qro = (unsigned int)(wm + lr)*AP + (kd*2 + lh)*16;
                ldsm4(aqh, sQh + qro);
                ldsm4(aql, sQl + qro);
                #pragma unroll
                for (int g = 0; g < 4; g++) {
                    unsigned int rkh[4], rkl[4];
                    unsigned int kro = (unsigned int)(g*16 + lr)*AP + (kd*2 + lh)*16;
                    ldsm4(rkh, kb + kro);
                    ldsm4(rkl, kb + KMAT + kro);
                    mma_f16(sc[2*g],   aqh, rkh[0], rkh[2]);
                    mma_f16(sc[2*g+1], aqh, rkh[1], rkh[3]);
                    mma_f16(sc[2*g],   aqh, rkl[0], rkl[2]);
                    mma_f16(sc[2*g+1], aqh, rkl[1], rkl[3]);
                    mma_f16(sc[2*g],   aql, rkh[0], rkh[2]);
                    mma_f16(sc[2*g+1], aql, rkh[1], rkh[3]);
                }
            }

            if (kt >= 2*qt0) {
                const int grow0 = qt0*128 + wm + (lane >> 2);
                const int gc0 = kt*64 + (lane & 3)*2;
                #pragma unroll
                for (int nt = 0; nt < 8; nt++) {
                    int c0l = gc0 + nt*8;
                    sc[nt][0] = (c0l     > grow0)   ? -1e30f : sc[nt][0]*0.125f;
                    sc[nt][1] = (c0l + 1 > grow0)   ? -1e30f : sc[nt][1]*0.125f;
                    sc[nt][2] = (c0l     > grow0+8) ? -1e30f : sc[nt][2]*0.125f;
                    sc[nt][3] = (c0l + 1 > grow0+8) ? -1e30f : sc[nt][3]*0.125f;
                }
            } else {
                #pragma unroll
                for (int nt = 0; nt < 8; nt++) {
                    sc[nt][0] *= 0.125f; sc[nt][1] *= 0.125f;
                    sc[nt][2] *= 0.125f; sc[nt][3] *= 0.125f;
                }
            }

            float mx0 = -1e30f, mx1 = -1e30f;
            #pragma unroll
            for (int nt = 0; nt < 8; nt++) {
                mx0 = fmaxf(mx0, fmaxf(sc[nt][0], sc[nt][1]));
                mx1 = fmaxf(mx1, fmaxf(sc[nt][2], sc[nt][3]));
            }
            mx0 = fmaxf(mx0, __shfl_xor_sync(0xffffffffu, mx0, 1));
            mx0 = fmaxf(mx0, __shfl_xor_sync(0xffffffffu, mx0, 2));
            mx1 = fmaxf(mx1, __shfl_xor_sync(0xffffffffu, mx1, 1));
            mx1 = fmaxf(mx1, __shfl_xor_sync(0xffffffffu, mx1, 2));
            float mn0 = fmaxf(m0, mx0), mn1 = fmaxf(m1, mx1);
            float cf0 = __expf(m0 - mn0), cf1 = __expf(m1 - mn1);
            m0 = mn0; m1 = mn1;
            float s0 = 0.f, s1 = 0.f;
            #pragma unroll
            for (int nt = 0; nt < 8; nt++) {
                sc[nt][0] = __expf(sc[nt][0] - mn0);
                sc[nt][1] = __expf(sc[nt][1] - mn0);
                sc[nt][2] = __expf(sc[nt][2] - mn1);
                sc[nt][3] = __expf(sc[nt][3] - mn1);
                s0 += sc[nt][0] + sc[nt][1];
                s1 += sc[nt][2] + sc[nt][3];
            }
            s0 += __shfl_xor_sync(0xffffffffu, s0, 1);
            s0 += __shfl_xor_sync(0xffffffffu, s0, 2);
            s1 += __shfl_xor_sync(0xffffffffu, s1, 1);
            s1 += __shfl_xor_sync(0xffffffffu, s1, 2);
            l0 = l0 * cf0 + s0;
            l1 = l1 * cf1 + s1;
            #pragma unroll
            for (int dt = 0; dt < 8; dt++) {
                o[dt][0] *= cf0; o[dt][1] *= cf0;
                o[dt][2] *= cf1; o[dt][3] *= cf1;
            }

            #pragma unroll
            for (int j = 0; j < 4; j++) {
                unsigned int ph[4], pl[4];
                split2h(sc[2*j][0],   sc[2*j][1],   ph[0], pl[0]);
                split2h(sc[2*j][2],   sc[2*j][3],   ph[1], pl[1]);
                split2h(sc[2*j+1][0], sc[2*j+1][1], ph[2], pl[2]);
                split2h(sc[2*j+1][2], sc[2*j+1][3], ph[3], pl[3]);
                #pragma unroll
                for (int g = 0; g < 4; g++) {
                    unsigned int rvh[4];
                    unsigned int vro = (unsigned int)(j*16 + lr)*AP + (g*2 + lh)*16;
                    ldsm4t(rvh, kb + 2*KMAT + vro);
                    mma_f16(o[2*g],   ph, rvh[0], rvh[1]);
                    mma_f16(o[2*g+1], ph, rvh[2], rvh[3]);
                    mma_f16(o[2*g],   pl, rvh[0], rvh[1]);
                    mma_f16(o[2*g+1], pl, rvh[2], rvh[3]);
                }
            }

            __syncthreads();
            if (kt + 2 < NKT) load_kv(kt + 2, kt & 1);
        }

        const float inv0 = 1.f / l0, inv1 = 1.f / l1;
        const int row0g = qt0*128 + wm + (lane >> 2);
        __half* ohp = g_ah + ((size_t)bh*SS)*HDIM;
        __half* olp = g_al + ((size_t)bh*SS)*HDIM;
        #pragma unroll
        for (int dt = 0; dt < 8; dt++) {
            int d = dt*8 + (lane & 3)*2;
            unsigned int hi, lo;
            split2h(o[dt][0]*inv0, o[dt][1]*inv0, hi, lo);
            *(unsigned int*)(ohp + (size_t)row0g*HDIM + d) = hi;
            *(unsigned int*)(olp + (size_t)row0g*HDIM + d) = lo;
            split2h(o[dt][2]*inv1, o[dt][3]*inv1, hi, lo);
            *(unsigned int*)(ohp + (size_t)(row0g+8)*HDIM + d) = hi;
            *(unsigned int*)(olp + (size_t)(row0g+8)*HDIM + d) = lo;
        }
    }
}

// ===================== LayerNorm =====================
__device__ __forceinline__ float blk_sum(float v, float* sred)
{
    #pragma unroll
    for (int o = 16; o; o >>= 1) v += __shfl_xor_sync(0xffffffffu, v, o);
    int w = threadIdx.x >> 5;
    if ((threadIdx.x & 31) == 0) sred[w] = v;
    __syncthreads();
    float t = (threadIdx.x < 8) ? sred[threadIdx.x] : 0.f;
    if (threadIdx.x < 32) {
        #pragma unroll
        for (int o = 4; o; o >>= 1) t += __shfl_xor_sync(0xffffffffu, t, o);
        if (threadIdx.x == 0) sred[0] = t;
    }
    __syncthreads();
    float r = sred[0];
    __syncthreads();
    return r;
}

// OUTH: also emit single-fp16 copy
template<bool OUTH>
__global__ void ln_kernel(const float* __restrict__ resid,
                          const float* __restrict__ y,
                          const float* __restrict__ gamma,
                          const float* __restrict__ beta,
                          float* __restrict__ outf,
                          __half* __restrict__ oh)
{
    __shared__ float sred[32];
    const int row = blockIdx.x;
    const int tid = threadIdx.x;

    float4 a = ((const float4*)(resid + (size_t)row * DD))[tid];
    float4 b = ((const float4*)(y     + (size_t)row * DD))[tid];
    float4 v = make_float4(a.x + b.x, a.y + b.y, a.z + b.z, a.w + b.w);

    float total = blk_sum(v.x + v.y + v.z + v.w, sred);
    float mu = total * (1.f / DD);

    float dx = v.x - mu, dy = v.y - mu, dz = v.z - mu, dw = v.w - mu;
    float tot2 = blk_sum(dx*dx + dy*dy + dz*dz + dw*dw, sred);
    float inv = rsqrtf(tot2 * (1.f / DD) + LN_EPS);

    float4 g = ((const float4*)gamma)[tid];
    float4 be = ((const float4*)beta)[tid];
    float ov[4];
    ov[0] = dx * inv * g.x + be.x;
    ov[1] = dy * inv * g.y + be.y;
    ov[2] = dz * inv * g.z + be.z;
    ov[3] = dw * inv * g.w + be.w;
    ((float4*)(outf + (size_t)row * DD))[tid] = make_float4(ov[0], ov[1], ov[2], ov[3]);

    if (OUTH) {
        unsigned int w0 = pack_f16(__float2half(ov[0]), __float2half(ov[1]));
        unsigned int w1 = pack_f16(__float2half(ov[2]), __float2half(ov[3]));
        *(uint2*)(oh + (size_t)row * DD + tid * 4) = make_uint2(w0, w1);
    }
}

// ===================== launch =====================
extern "C" void kernel_launch(void* const* d_in, const int* in_sizes, int n_in,
                              void* d_out, int out_size)
{
    (void)in_sizes; (void)n_in; (void)out_size;

    const float* x     = (const float*)d_in[0];
    const float* Wq    = (const float*)d_in[1];
    const float* Wk    = (const float*)d_in[2];
    const float* Wv    = (const float*)d_in[3];
    const float* Wo    = (const float*)d_in[4];
    const float* g1    = (const float*)d_in[5];
    const float* be1   = (const float*)d_in[6];
    const float* w_in  = (const float*)d_in[7];
    const float* b_in  = (const float*)d_in[8];
    const float* w_out = (const float*)d_in[9];
    const float* b_out = (const float*)d_in[10];
    const float* g2    = (const float*)d_in[11];
    const float* be2   = (const float*)d_in[12];
    float* out = (float*)d_out;

    float *tmp, *x1;
    __half *qkvh, *qkvl, *xh, *xl, *ah, *al, *x1f, *h1f;
    __half *wqkvf, *wof, *winf, *woutf;
    cudaGetSymbolAddress((void**)&tmp,  g_tmp);
    cudaGetSymbolAddress((void**)&x1,   g_x1);
    cudaGetSymbolAddress((void**)&qkvh, g_qkvh);  cudaGetSymbolAddress((void**)&qkvl, g_qkvl);
    cudaGetSymbolAddress((void**)&xh,   g_xh);    cudaGetSymbolAddress((void**)&xl,   g_xl);
    cudaGetSymbolAddress((void**)&ah,   g_ah);    cudaGetSymbolAddress((void**)&al,   g_al);
    cudaGetSymbolAddress((void**)&x1f,  g_x1f);
    cudaGetSymbolAddress((void**)&h1f,  g_h1f);
    cudaGetSymbolAddress((void**)&wqkvf, g_wqkvf);
    cudaGetSymbolAddress((void**)&wof,   g_wof);
    cudaGetSymbolAddress((void**)&winf,  g_winf);  cudaGetSymbolAddress((void**)&woutf, g_woutf);

    cudaFuncSetAttribute(flash_tc_kernel, cudaFuncAttributeMaxDynamicSharedMemorySize, FA_SMEM);
    cudaFuncSetAttribute(gemm2_kernel<false,false,false,true>, cudaFuncAttributeMaxDynamicSharedMemorySize, G2_SMEM);
    cudaFuncSetAttribute(gemm2_kernel<false,false,true,false>, cudaFuncAttributeMaxDynamicSharedMemorySize, G2_SMEM);
    cudaFuncSetAttribute(gemm1_kernel<true,true,false,true>,  cudaFuncAttributeMaxDynamicSharedMemorySize, G1_SMEM);
    cudaFuncSetAttribute(gemm1_kernel<true,false,true,false>, cudaFuncAttributeMaxDynamicSharedMemorySize, G1_SMEM);

    // ---- prep: split x to fp16; transpose weights to single fp16 ----
    fsplit_kernel<<<MM*DD/1024, 256>>>(x, xh, xl, MM*DD/4);
    qkvT_kernel<<<dim3(2, 32, 48), dim3(32, 8)>>>(Wq, Wk, Wv, wqkvf);
    wsplit3_kernel<<<9216, dim3(32, 8)>>>(Wo, w_in, w_out);

    // ---- 1) fused QKV projection (fp16 2-term) -> split fp16 hi/lo ----
    gemm2_kernel<false,false,false,true><<<dim3(3072/256, MM/128), 512, G2_SMEM>>>(
        xh, xl, wqkvf, nullptr, nullptr, qkvh, qkvl, MM, 3072, 1024);

    // ---- 2) causal flash attention -> fp16 hi/lo ----
    flash_tc_kernel<<<dim3(SS/256, BB*HH), 256, FA_SMEM>>>();

    // ---- 3) output projection (fp16 2-term, no bias) ----
    gemm2_kernel<false,false,true,false><<<dim3(1024/256, MM/128), 512, G2_SMEM>>>(
        ah, al, wof, nullptr, tmp, nullptr, nullptr, MM, 1024, 1024);

    // ---- 4) LN1 (x + attn@Wo) -> fp32 + single fp16 ----
    ln_kernel<true><<<MM, 256>>>(x, tmp, g1, be1, x1, x1f);

    // ---- 5) FFN up + bias + ReLU (single fp16 1-term) -> single fp16 ----
    gemm1_kernel<true,true,false,true><<<dim3(4096/256, MM/128), 512, G1_SMEM>>>(
        x1f, winf, b_in, nullptr, h1f, MM, 4096, 1024);

    // ---- 6) FFN down + bias (single fp16 1-term) -> fp32 ----
    gemm1_kernel<true,false,true,false><<<dim3(1024/256, MM/128), 512, G1_SMEM>>>(
        h1f, woutf, b_out, tmp, nullptr, MM, 1024, 4096);

    // ---- 7) LN2 -> output ----
    ln_kernel<false><<<MM, 256>>>(x1, tmp, g2, be2, out, nullptr);
}

// round 13
// speedup vs baseline: 6.8362x; 1.4192x over previous
#include <cuda_runtime.h>
#include <cuda_bf16.h>
#include <cuda_fp16.h>
#include <math.h>

// Problem constants
#define BB   4
#define SS   2048
#define DD   1024
#define HH   16
#define HDIM 64
#define FF   4096
#define MM   (BB*SS)   // 8192 rows
#define LN_EPS 1e-5f

// ===================== low-level helpers =====================
__device__ __forceinline__ unsigned int smem_u32(const void* p) {
    unsigned int a;
    asm("{ .reg .u64 t; cvta.to.shared.u64 t, %1; cvt.u32.u64 %0, t; }" : "=r"(a) : "l"(p));
    return a;
}
__device__ __forceinline__ void cp16(unsigned int s, const void* g) {
    asm volatile("cp.async.cg.shared.global [%0], [%1], 16;" :: "r"(s), "l"(g));
}
#define CP_COMMIT() asm volatile("cp.async.commit_group;" ::: "memory")
#define CP_WAIT1()  asm volatile("cp.async.wait_group 1;" ::: "memory")
#define CP_WAIT2()  asm volatile("cp.async.wait_group 2;" ::: "memory")
#define CP_WAIT0()  asm volatile("cp.async.wait_group 0;" ::: "memory")

__device__ __forceinline__ void ldsm4(unsigned int* r, unsigned int addr) {
    asm volatile("ldmatrix.sync.aligned.m8n8.x4.shared.b16 {%0,%1,%2,%3}, [%4];"
        : "=r"(r[0]), "=r"(r[1]), "=r"(r[2]), "=r"(r[3]) : "r"(addr));
}
__device__ __forceinline__ void ldsm4t(unsigned int* r, unsigned int addr) {
    asm volatile("ldmatrix.sync.aligned.m8n8.x4.trans.shared.b16 {%0,%1,%2,%3}, [%4];"
        : "=r"(r[0]), "=r"(r[1]), "=r"(r[2]), "=r"(r[3]) : "r"(addr));
}
__device__ __forceinline__ void mma_f16(float* c, const unsigned int* a,
                                        unsigned int b0, unsigned int b1) {
    asm volatile("mma.sync.aligned.m16n8k16.row.col.f32.f16.f16.f32 "
        "{%0,%1,%2,%3}, {%4,%5,%6,%7}, {%8,%9}, {%0,%1,%2,%3};"
        : "+f"(c[0]), "+f"(c[1]), "+f"(c[2]), "+f"(c[3])
        : "r"(a[0]), "r"(a[1]), "r"(a[2]), "r"(a[3]), "r"(b0), "r"(b1));
}
__device__ __forceinline__ unsigned int pack_f16(__half a, __half b) {
    return (unsigned int)__half_as_ushort(a) | ((unsigned int)__half_as_ushort(b) << 16);
}
__device__ __forceinline__ unsigned int pack2f(float a, float b) {
    return pack_f16(__float2half(a), __float2half(b));
}

// ===================== scratch (device globals) =====================
__device__ __half g_xf[(size_t)MM*DD];
__device__ __half g_qkvf[(size_t)MM*3072];
__device__ __half g_af[(size_t)MM*DD];         // attention out single fp16
__device__ float g_tmp[(size_t)MM*DD];
__device__ float g_x1[(size_t)MM*DD];
__device__ __half g_x1f[(size_t)MM*DD];
__device__ __half g_h1f[(size_t)MM*FF];
// transposed single-fp16 weights ([N,K] row-major)
__device__ __half g_wqkvf[(size_t)3072*1024];
__device__ __half g_wof[(size_t)1024*1024];
__device__ __half g_winf[(size_t)4096*1024];
__device__ __half g_woutf[(size_t)1024*4096];

// ===================== prep kernels =====================
__global__ void fconvert_kernel(const float* __restrict__ in,
                                __half* __restrict__ o, int n4)
{
    int i = blockIdx.x * blockDim.x + threadIdx.x;
    if (i >= n4) return;
    float4 v = ((const float4*)in)[i];
    ((uint2*)o)[i] = make_uint2(pack2f(v.x, v.y), pack2f(v.z, v.w));
}

// transpose one 32x32 block of W [K,N] -> single fp16 T [N,K]
__device__ __forceinline__ void wsingle_block(const float* __restrict__ W,
                                              __half* __restrict__ T,
                                              int K, int N, int k0, int n0,
                                              float t[32][33])
{
    int tx = threadIdx.x, ty = threadIdx.y;
    #pragma unroll
    for (int i = 0; i < 32; i += 8)
        t[ty + i][tx] = W[(size_t)(k0 + ty + i) * N + n0 + tx];
    __syncthreads();
    #pragma unroll
    for (int i = 0; i < 32; i += 8) {
        float v = t[tx][ty + i];
        T[(size_t)(n0 + ty + i) * K + k0 + tx] = __float2half(v);
    }
}

// merged: Wo fp16 (1024 blocks), w_in fp16 (4096), w_out fp16 (4096)
__global__ void wsplit3_kernel(const float* __restrict__ Wo,
                               const float* __restrict__ Win,
                               const float* __restrict__ Wout)
{
    __shared__ float t[32][33];
    int idx = blockIdx.x;
    if (idx < 1024) {
        wsingle_block(Wo, g_wof, 1024, 1024,
                      (idx >> 5) * 32, (idx & 31) * 32, t);
    } else if (idx < 1024 + 4096) {
        int i2 = idx - 1024;
        wsingle_block(Win, g_winf, 1024, 4096,
                      (i2 >> 7) * 32, (i2 & 127) * 32, t);
    } else {
        int i2 = idx - 5120;
        wsingle_block(Wout, g_woutf, 4096, 1024,
                      (i2 >> 5) * 32, (i2 & 31) * 32, t);
    }
}

// Wq/Wk/Wv [H,D,HD] -> combined transposed single fp16 [3072, 1024]
__global__ void qkvT_kernel(const float* __restrict__ Wq,
                            const float* __restrict__ Wk,
                            const float* __restrict__ Wv,
                            __half* __restrict__ T)
{
    __shared__ float t[32][33];
    int z = blockIdx.z;
    int mat = z / HH, h = z - mat * HH;
    const float* W = (mat == 0 ? Wq : mat == 1 ? Wk : Wv) + (size_t)h * DD * HDIM;
    int k0 = blockIdx.y * 32, e0 = blockIdx.x * 32;
    int tx = threadIdx.x, ty = threadIdx.y;
    #pragma unroll
    for (int i = 0; i < 32; i += 8)
        t[ty + i][tx] = W[(size_t)(k0 + ty + i) * HDIM + e0 + tx];
    __syncthreads();
    int nbase = mat * 1024 + h * HDIM;
    #pragma unroll
    for (int i = 0; i < 32; i += 8) {
        float v = t[tx][ty + i];
        T[(size_t)(nbase + e0 + ty + i) * DD + k0 + tx] = __float2half(v);
    }
}

// swizzled byte offset for (row, 16B-chunk ck) within a 128B-row matrix
#define GSW(r, ck) ((unsigned int)((r) * 128 + ((((ck) ^ ((r) & 7))) << 4)))

// ===================== single-fp16 1-term GEMM (all projections) ==============
// D = A*B. A single fp16 [M,K], B single fp16 [N,K]. Block 128x256,
// K-chunk 64, 3-stage (48KB/stage), 16 warps, warp 64x32.
#define G1_A  0
#define G1_B  16384
#define G1_STG 49152
#define G1_SMEM (3*G1_STG)     // 147456

template<bool BIAS, bool RELU, bool F32OUT, bool HALFOUT>
__global__ void __launch_bounds__(512, 1) gemm1_kernel(
    const __half* __restrict__ A,
    const __half* __restrict__ BT,
    const float* __restrict__ bias,
    float* __restrict__ C,
    __half* __restrict__ Ch,
    int M, int N, int K)
{
    extern __shared__ __align__(128) char smem[];
    const unsigned int sb = smem_u32(smem);
    const int tid = threadIdx.x;
    const int row0 = blockIdx.y * 128;
    const int col0 = blockIdx.x * 256;

    const int wid = tid >> 5, lane = tid & 31;
    const int wm0 = (wid & 1) * 64, wn0 = (wid >> 1) * 32;
    const int lr = lane & 15, lh = lane >> 4;

    auto load_stage = [&](int c, int s) {
        unsigned int base = sb + s * G1_STG;
        int k0 = c * 64;
        #pragma unroll
        for (int i = 0; i < 2; i++) {
            int lin = tid + (i << 9);
            int r = lin >> 3, ck = lin & 7;
            unsigned int so = GSW(r, ck);
            cp16(base + G1_A + so, A + (size_t)(row0 + r) * K + k0 + ck * 8);
        }
        #pragma unroll
        for (int i = 0; i < 4; i++) {
            int lin = tid + (i << 9);
            int r = lin >> 3, ck = lin & 7;
            unsigned int so = GSW(r, ck);
            cp16(base + G1_B + so, BT + (size_t)(col0 + r) * K + k0 + ck * 8);
        }
        CP_COMMIT();
    };

    float acc[4][4][4] = {};

    load_stage(0, 0);
    load_stage(1, 1);
    load_stage(2, 2);

    const int NC = K >> 6;
    for (int c = 0; c < NC; c++) {
        CP_WAIT2();
        __syncthreads();

        unsigned int base = sb + (c % 3) * G1_STG;
        #pragma unroll
        for (int ks = 0; ks < 4; ks++) {
            unsigned int a_r[4][4], b_r[2][4];
            #pragma unroll
            for (int mt = 0; mt < 4; mt++) {
                int r = wm0 + mt*16 + lr;
                unsigned int ro = GSW(r, ks*2 + lh);
                ldsm4(a_r[mt], base + G1_A + ro);
            }
            #pragma unroll
            for (int bt = 0; bt < 2; bt++) {
                int r = wn0 + bt*16 + lr;
                unsigned int ro = GSW(r, ks*2 + lh);
                ldsm4(b_r[bt], base + G1_B + ro);
            }
            #pragma unroll
            for (int mt = 0; mt < 4; mt++)
                #pragma unroll
                for (int nt = 0; nt < 4; nt++)
                    mma_f16(acc[mt][nt], a_r[mt], b_r[nt>>1][nt&1], b_r[nt>>1][(nt&1)+2]);
        }

        __syncthreads();
        if (c + 3 < NC) load_stage(c + 3, (c + 3) % 3);
    }

    // ---- epilogue ----
    const int gq = lane >> 2, pq = lane & 3;
    #pragma unroll
    for (int mt = 0; mt < 4; mt++) {
        #pragma unroll
        for (int nt = 0; nt < 4; nt++) {
            int col = col0 + wn0 + nt*8 + pq*2;
            float b0 = 0.f, b1 = 0.f;
            if (BIAS) { b0 = bias[col]; b1 = bias[col+1]; }
            #pragma unroll
            for (int h2 = 0; h2 < 2; h2++) {
                int row = row0 + wm0 + mt*16 + gq + h2*8;
                float v0 = acc[mt][nt][h2*2+0] + b0;
                float v1 = acc[mt][nt][h2*2+1] + b1;
                if (RELU) { v0 = fmaxf(v0, 0.f); v1 = fmaxf(v1, 0.f); }
                if (F32OUT)
                    *(float2*)(C + (size_t)row * N + col) = make_float2(v0, v1);
                if (HALFOUT)
                    *(unsigned int*)(Ch + (size_t)row * N + col) = pack2f(v0, v1);
            }
        }
    }
}

// ===================== tensor-core causal flash attention (single fp16) =======
// QK: 1-term; PV: 1-term. KV stage: K, V (2 mats). Q single.
#define AP 144
#define KMAT 9216              // 64*AP
#define QMAT 18432             // 128*AP
#define FA_STG (2*KMAT)        // 18432
#define FA_SMEM (QMAT + 2*FA_STG)   // 55296

__global__ void __launch_bounds__(256, 1) flash_tc_kernel()
{
    const int pid = blockIdx.x, bh = blockIdx.y;
    const int b = bh >> 4, h = bh & 15;
    const int tid = threadIdx.x, wid = tid >> 5, lane = tid & 31;
    const int wm = wid * 16;
    const int lr = lane & 15, lh = lane >> 4;

    extern __shared__ __align__(16) char smem[];
    const unsigned int sb = smem_u32(smem);
    const unsigned int sQ = sb;

    for (int run = 0; run < 2; run++) {
        const int qt0 = run ? (15 - pid) : pid;
        const int NKT = 2 * qt0 + 2;

        __syncthreads();   // previous run fully done with smem

        // ---- load Q tile (128 rows, single fp16) ----
        {
            const __half* q = g_qkvf + (size_t)(b*SS + qt0*128)*3072 + h*HDIM;
            #pragma unroll
            for (int i = 0; i < 4; i++) {
                int lin = tid + (i << 8);
                int r = lin >> 3, ck = lin & 7;
                cp16(sQ + r*AP + ck*16, q + (size_t)r*3072 + ck*8);
            }
            CP_COMMIT();
        }

        auto load_kv = [&](int kt, int s) {
            unsigned int base = sb + QMAT + s * FA_STG;
            size_t rowb = (size_t)(b*SS + kt*64)*3072;
            const __half* k = g_qkvf + rowb + 1024 + h*HDIM;
            const __half* v = g_qkvf + rowb + 2048 + h*HDIM;
            #pragma unroll
            for (int i = 0; i < 2; i++) {
                int lin = tid + (i << 8);
                int r = lin >> 3, ck = lin & 7;
                unsigned int so = r*AP + ck*16;
                size_t g = (size_t)r*3072 + ck*8;
                cp16(base + so,        k + g);
                cp16(base + KMAT + so, v + g);
            }
            CP_COMMIT();
        };

        load_kv(0, 0);
        load_kv(1, 1);

        float o[8][4] = {};
        float m0 = -1e30f, m1 = -1e30f, l0 = 0.f, l1 = 0.f;

        for (int kt = 0; kt < NKT; kt++) {
            if (kt < NKT - 1) CP_WAIT1(); else CP_WAIT0();
            __syncthreads();

            const unsigned int kb = sb + QMAT + (kt & 1) * FA_STG;

            // ---- S = Q K^T ----
            float sc[8][4] = {};
            #pragma unroll
            for (int kd = 0; kd < 4; kd++) {
                unsigned int aq[4];
                unsigned int qro = (unsigned int)(wm + lr)*AP + (kd*2 + lh)*16;
                ldsm4(aq, sQ + qro);
                #pragma unroll
                for (int g = 0; g < 4; g++) {
                    unsigned int rk[4];
                    unsigned int kro = (unsigned int)(g*16 + lr)*AP + (kd*2 + lh)*16;
                    ldsm4(rk, kb + kro);
                    mma_f16(sc[2*g],   aq, rk[0], rk[2]);
                    mma_f16(sc[2*g+1], aq, rk[1], rk[3]);
                }
            }

            // ---- scale + causal mask ----
            if (kt >= 2*qt0) {
                const int grow0 = qt0*128 + wm + (lane >> 2);
                const int gc0 = kt*64 + (lane & 3)*2;
                #pragma unroll
                for (int nt = 0; nt < 8; nt++) {
                    int c0l = gc0 + nt*8;
                    sc[nt][0] = (c0l     > grow0)   ? -1e30f : sc[nt][0]*0.125f;
                    sc[nt][1] = (c0l + 1 > grow0)   ? -1e30f : sc[nt][1]*0.125f;
                    sc[nt][2] = (c0l     > grow0+8) ? -1e30f : sc[nt][2]*0.125f;
                    sc[nt][3] = (c0l + 1 > grow0+8) ? -1e30f : sc[nt][3]*0.125f;
                }
            } else {
                #pragma unroll
                for (int nt = 0; nt < 8; nt++) {
                    sc[nt][0] *= 0.125f; sc[nt][1] *= 0.125f;
                    sc[nt][2] *= 0.125f; sc[nt][3] *= 0.125f;
                }
            }

            // ---- online softmax ----
            float mx0 = -1e30f, mx1 = -1e30f;
            #pragma unroll
            for (int nt = 0; nt < 8; nt++) {
                mx0 = fmaxf(mx0, fmaxf(sc[nt][0], sc[nt][1]));
                mx1 = fmaxf(mx1, fmaxf(sc[nt][2], sc[nt][3]));
            }
            mx0 = fmaxf(mx0, __shfl_xor_sync(0xffffffffu, mx0, 1));
            mx0 = fmaxf(mx0, __shfl_xor_sync(0xffffffffu, mx0, 2));
            mx1 = fmaxf(mx1, __shfl_xor_sync(0xffffffffu, mx1, 1));
            mx1 = fmaxf(mx1, __shfl_xor_sync(0xffffffffu, mx1, 2));
            float mn0 = fmaxf(m0, mx0), mn1 = fmaxf(m1, mx1);
            float cf0 = __expf(m0 - mn0), cf1 = __expf(m1 - mn1);
            m0 = mn0; m1 = mn1;
            float s0 = 0.f, s1 = 0.f;
            #pragma unroll
            for (int nt = 0; nt < 8; nt++) {
                sc[nt][0] = __expf(sc[nt][0] - mn0);
                sc[nt][1] = __expf(sc[nt][1] - mn0);
                sc[nt][2] = __expf(sc[nt][2] - mn1);
                sc[nt][3] = __expf(sc[nt][3] - mn1);
                s0 += sc[nt][0] + sc[nt][1];
                s1 += sc[nt][2] + sc[nt][3];
            }
            s0 += __shfl_xor_sync(0xffffffffu, s0, 1);
            s0 += __shfl_xor_sync(0xffffffffu, s0, 2);
            s1 += __shfl_xor_sync(0xffffffffu, s1, 1);
            s1 += __shfl_xor_sync(0xffffffffu, s1, 2);
            l0 = l0 * cf0 + s0;
            l1 = l1 * cf1 + s1;
            #pragma unroll
            for (int dt = 0; dt < 8; dt++) {
                o[dt][0] *= cf0; o[dt][1] *= cf0;
                o[dt][2] *= cf1; o[dt][3] *= cf1;
            }

            // ---- O += P V (single fp16 P) ----
            #pragma unroll
            for (int j = 0; j < 4; j++) {
                unsigned int ph[4];
                ph[0] = pack2f(sc[2*j][0],   sc[2*j][1]);
                ph[1] = pack2f(sc[2*j][2],   sc[2*j][3]);
                ph[2] = pack2f(sc[2*j+1][0], sc[2*j+1][1]);
                ph[3] = pack2f(sc[2*j+1][2], sc[2*j+1][3]);
                #pragma unroll
                for (int g = 0; g < 4; g++) {
                    unsigned int rv[4];
                    unsigned int vro = (unsigned int)(j*16 + lr)*AP + (g*2 + lh)*16;
                    ldsm4t(rv, kb + KMAT + vro);
                    mma_f16(o[2*g],   ph, rv[0], rv[1]);
                    mma_f16(o[2*g+1], ph, rv[2], rv[3]);
                }
            }

            __syncthreads();
            if (kt + 2 < NKT) load_kv(kt + 2, kt & 1);
        }

        // ---- epilogue: normalize, single fp16 out ----
        const float inv0 = 1.f / l0, inv1 = 1.f / l1;
        const int row0g = qt0*128 + wm + (lane >> 2);
        __half* op = g_af + ((size_t)bh*SS)*HDIM;
        #pragma unroll
        for (int dt = 0; dt < 8; dt++) {
            int d = dt*8 + (lane & 3)*2;
            *(unsigned int*)(op + (size_t)row0g*HDIM + d) =
                pack2f(o[dt][0]*inv0, o[dt][1]*inv0);
            *(unsigned int*)(op + (size_t)(row0g+8)*HDIM + d) =
                pack2f(o[dt][2]*inv1, o[dt][3]*inv1);
        }
    }
}

// ===================== LayerNorm =====================
__device__ __forceinline__ float blk_sum(float v, float* sred)
{
    #pragma unroll
    for (int o = 16; o; o >>= 1) v += __shfl_xor_sync(0xffffffffu, v, o);
    int w = threadIdx.x >> 5;
    if ((threadIdx.x & 31) == 0) sred[w] = v;
    __syncthreads();
    float t = (threadIdx.x < 8) ? sred[threadIdx.x] : 0.f;
    if (threadIdx.x < 32) {
        #pragma unroll
        for (int o = 4; o; o >>= 1) t += __shfl_xor_sync(0xffffffffu, t, o);
        if (threadIdx.x == 0) sred[0] = t;
    }
    __syncthreads();
    float r = sred[0];
    __syncthreads();
    return r;
}

template<bool OUTH>
__global__ void ln_kernel(const float* __restrict__ resid,
                          const float* __restrict__ y,
                          const float* __restrict__ gamma,
                          const float* __restrict__ beta,
                          float* __restrict__ outf,
                          __half* __restrict__ oh)
{
    __shared__ float sred[32];
    const int row = blockIdx.x;
    const int tid = threadIdx.x;

    float4 a = ((const float4*)(resid + (size_t)row * DD))[tid];
    float4 b = ((const float4*)(y     + (size_t)row * DD))[tid];
    float4 v = make_float4(a.x + b.x, a.y + b.y, a.z + b.z, a.w + b.w);

    float total = blk_sum(v.x + v.y + v.z + v.w, sred);
    float mu = total * (1.f / DD);

    float dx = v.x - mu, dy = v.y - mu, dz = v.z - mu, dw = v.w - mu;
    float tot2 = blk_sum(dx*dx + dy*dy + dz*dz + dw*dw, sred);
    float inv = rsqrtf(tot2 * (1.f / DD) + LN_EPS);

    float4 g = ((const float4*)gamma)[tid];
    float4 be = ((const float4*)beta)[tid];
    float ov[4];
    ov[0] = dx * inv * g.x + be.x;
    ov[1] = dy * inv * g.y + be.y;
    ov[2] = dz * inv * g.z + be.z;
    ov[3] = dw * inv * g.w + be.w;
    ((float4*)(outf + (size_t)row * DD))[tid] = make_float4(ov[0], ov[1], ov[2], ov[3]);

    if (OUTH) {
        *(uint2*)(oh + (size_t)row * DD + tid * 4) =
            make_uint2(pack2f(ov[0], ov[1]), pack2f(ov[2], ov[3]));
    }
}

// ===================== launch =====================
extern "C" void kernel_launch(void* const* d_in, const int* in_sizes, int n_in,
                              void* d_out, int out_size)
{
    (void)in_sizes; (void)n_in; (void)out_size;

    const float* x     = (const float*)d_in[0];
    const float* Wq    = (const float*)d_in[1];
    const float* Wk    = (const float*)d_in[2];
    const float* Wv    = (const float*)d_in[3];
    const float* Wo    = (const float*)d_in[4];
    const float* g1    = (const float*)d_in[5];
    const float* be1   = (const float*)d_in[6];
    const float* w_in  = (const float*)d_in[7];
    const float* b_in  = (const float*)d_in[8];
    const float* w_out = (const float*)d_in[9];
    const float* b_out = (const float*)d_in[10];
    const float* g2    = (const float*)d_in[11];
    const float* be2   = (const float*)d_in[12];
    float* out = (float*)d_out;

    float *tmp, *x1;
    __half *xf, *qkvf, *af, *x1f, *h1f;
    __half *wqkvf, *wof, *winf, *woutf;
    cudaGetSymbolAddress((void**)&tmp,  g_tmp);
    cudaGetSymbolAddress((void**)&x1,   g_x1);
    cudaGetSymbolAddress((void**)&xf,   g_xf);
    cudaGetSymbolAddress((void**)&qkvf, g_qkvf);
    cudaGetSymbolAddress((void**)&af,   g_af);
    cudaGetSymbolAddress((void**)&x1f,  g_x1f);
    cudaGetSymbolAddress((void**)&h1f,  g_h1f);
    cudaGetSymbolAddress((void**)&wqkvf, g_wqkvf);
    cudaGetSymbolAddress((void**)&wof,   g_wof);
    cudaGetSymbolAddress((void**)&winf,  g_winf);
    cudaGetSymbolAddress((void**)&woutf, g_woutf);

    cudaFuncSetAttribute(flash_tc_kernel, cudaFuncAttributeMaxDynamicSharedMemorySize, FA_SMEM);
    cudaFuncSetAttribute(gemm1_kernel<false,false,false,true>, cudaFuncAttributeMaxDynamicSharedMemorySize, G1_SMEM);
    cudaFuncSetAttribute(gemm1_kernel<false,false,true,false>, cudaFuncAttributeMaxDynamicSharedMemorySize, G1_SMEM);
    cudaFuncSetAttribute(gemm1_kernel<true,true,false,true>,   cudaFuncAttributeMaxDynamicSharedMemorySize, G1_SMEM);
    cudaFuncSetAttribute(gemm1_kernel<true,false,true,false>,  cudaFuncAttributeMaxDynamicSharedMemorySize, G1_SMEM);

    // ---- prep: convert x; transpose weights to single fp16 ----
    fconvert_kernel<<<MM*DD/1024, 256>>>(x, xf, MM*DD/4);
    qkvT_kernel<<<dim3(2, 32, 48), dim3(32, 8)>>>(Wq, Wk, Wv, wqkvf);
    wsplit3_kernel<<<9216, dim3(32, 8)>>>(Wo, w_in, w_out);

    // ---- 1) fused QKV projection (single fp16) ----
    gemm1_kernel<false,false,false,true><<<dim3(3072/256, MM/128), 512, G1_SMEM>>>(
        xf, wqkvf, nullptr, nullptr, qkvf, MM, 3072, 1024);

    // ---- 2) causal flash attention (single fp16) ----
    flash_tc_kernel<<<dim3(SS/256, BB*HH), 256, FA_SMEM>>>();

    // ---- 3) output projection ----
    gemm1_kernel<false,false,true,false><<<dim3(1024/256, MM/128), 512, G1_SMEM>>>(
        af, wof, nullptr, tmp, nullptr, MM, 1024, 1024);

    // ---- 4) LN1 (x + attn@Wo) -> fp32 + fp16 ----
    ln_kernel<true><<<MM, 256>>>(x, tmp, g1, be1, x1, x1f);

    // ---- 5) FFN up + bias + ReLU -> fp16 ----
    gemm1_kernel<true,true,false,true><<<dim3(4096/256, MM/128), 512, G1_SMEM>>>(
        x1f, winf, b_in, nullptr, h1f, MM, 4096, 1024);

    // ---- 6) FFN down + bias -> fp32 ----
    gemm1_kernel<true,false,true,false><<<dim3(1024/256, MM/128), 512, G1_SMEM>>>(
        h1f, woutf, b_out, tmp, nullptr, MM, 1024, 4096);

    // ---- 7) LN2 -> output ----
    ln_kernel<false><<<MM, 256>>>(x1, tmp, g2, be2, out, nullptr);
}

// round 14
// speedup vs baseline: 7.3288x; 1.0721x over previous
#include <cuda_runtime.h>
#include <cuda_bf16.h>
#include <cuda_fp16.h>
#include <math.h>

// Problem constants
#define BB   4
#define SS   2048
#define DD   1024
#define HH   16
#define HDIM 64
#define FF   4096
#define MM   (BB*SS)   // 8192 rows
#define LN_EPS 1e-5f

// ===================== low-level helpers =====================
__device__ __forceinline__ unsigned int smem_u32(const void* p) {
    unsigned int a;
    asm("{ .reg .u64 t; cvta.to.shared.u64 t, %1; cvt.u32.u64 %0, t; }" : "=r"(a) : "l"(p));
    return a;
}
__device__ __forceinline__ void cp16(unsigned int s, const void* g) {
    asm volatile("cp.async.cg.shared.global [%0], [%1], 16;" :: "r"(s), "l"(g));
}
#define CP_COMMIT() asm volatile("cp.async.commit_group;" ::: "memory")
#define CP_WAIT1()  asm volatile("cp.async.wait_group 1;" ::: "memory")
#define CP_WAIT2()  asm volatile("cp.async.wait_group 2;" ::: "memory")
#define CP_WAIT0()  asm volatile("cp.async.wait_group 0;" ::: "memory")

__device__ __forceinline__ void ldsm4(unsigned int* r, unsigned int addr) {
    asm volatile("ldmatrix.sync.aligned.m8n8.x4.shared.b16 {%0,%1,%2,%3}, [%4];"
        : "=r"(r[0]), "=r"(r[1]), "=r"(r[2]), "=r"(r[3]) : "r"(addr));
}
__device__ __forceinline__ void ldsm4t(unsigned int* r, unsigned int addr) {
    asm volatile("ldmatrix.sync.aligned.m8n8.x4.trans.shared.b16 {%0,%1,%2,%3}, [%4];"
        : "=r"(r[0]), "=r"(r[1]), "=r"(r[2]), "=r"(r[3]) : "r"(addr));
}
__device__ __forceinline__ void mma_f16(float* c, const unsigned int* a,
                                        unsigned int b0, unsigned int b1) {
    asm volatile("mma.sync.aligned.m16n8k16.row.col.f32.f16.f16.f32 "
        "{%0,%1,%2,%3}, {%4,%5,%6,%7}, {%8,%9}, {%0,%1,%2,%3};"
        : "+f"(c[0]), "+f"(c[1]), "+f"(c[2]), "+f"(c[3])
        : "r"(a[0]), "r"(a[1]), "r"(a[2]), "r"(a[3]), "r"(b0), "r"(b1));
}
__device__ __forceinline__ unsigned int pack_f16(__half a, __half b) {
    return (unsigned int)__half_as_ushort(a) | ((unsigned int)__half_as_ushort(b) << 16);
}
__device__ __forceinline__ unsigned int pack2f(float a, float b) {
    return pack_f16(__float2half(a), __float2half(b));
}

// ===================== scratch (device globals) =====================
__device__ __half g_xf[(size_t)MM*DD];
__device__ __half g_qkvf[(size_t)MM*3072];
__device__ __half g_af[(size_t)MM*DD];         // attention out single fp16
__device__ float g_tmp[(size_t)MM*DD];
__device__ float g_x1[(size_t)MM*DD];
__device__ __half g_x1f[(size_t)MM*DD];
__device__ __half g_h1f[(size_t)MM*FF];
// transposed single-fp16 weights ([N,K] row-major)
__device__ __half g_wqkvf[(size_t)3072*1024];
__device__ __half g_wof[(size_t)1024*1024];
__device__ __half g_winf[(size_t)4096*1024];
__device__ __half g_woutf[(size_t)1024*4096];

// ===================== prep kernels =====================
__global__ void fconvert_kernel(const float* __restrict__ in,
                                __half* __restrict__ o, int n4)
{
    int i = blockIdx.x * blockDim.x + threadIdx.x;
    if (i >= n4) return;
    float4 v = ((const float4*)in)[i];
    ((uint2*)o)[i] = make_uint2(pack2f(v.x, v.y), pack2f(v.z, v.w));
}

// transpose one 32x32 block of W [K,N] -> single fp16 T [N,K]
__device__ __forceinline__ void wsingle_block(const float* __restrict__ W,
                                              __half* __restrict__ T,
                                              int K, int N, int k0, int n0,
                                              float t[32][33])
{
    int tx = threadIdx.x, ty = threadIdx.y;
    #pragma unroll
    for (int i = 0; i < 32; i += 8)
        t[ty + i][tx] = W[(size_t)(k0 + ty + i) * N + n0 + tx];
    __syncthreads();
    #pragma unroll
    for (int i = 0; i < 32; i += 8) {
        float v = t[tx][ty + i];
        T[(size_t)(n0 + ty + i) * K + k0 + tx] = __float2half(v);
    }
}

// merged: Wo fp16 (1024 blocks), w_in fp16 (4096), w_out fp16 (4096)
__global__ void wsplit3_kernel(const float* __restrict__ Wo,
                               const float* __restrict__ Win,
                               const float* __restrict__ Wout)
{
    __shared__ float t[32][33];
    int idx = blockIdx.x;
    if (idx < 1024) {
        wsingle_block(Wo, g_wof, 1024, 1024,
                      (idx >> 5) * 32, (idx & 31) * 32, t);
    } else if (idx < 1024 + 4096) {
        int i2 = idx - 1024;
        wsingle_block(Win, g_winf, 1024, 4096,
                      (i2 >> 7) * 32, (i2 & 127) * 32, t);
    } else {
        int i2 = idx - 5120;
        wsingle_block(Wout, g_woutf, 4096, 1024,
                      (i2 >> 5) * 32, (i2 & 31) * 32, t);
    }
}

// Wq/Wk/Wv [H,D,HD] -> combined transposed single fp16 [3072, 1024]
__global__ void qkvT_kernel(const float* __restrict__ Wq,
                            const float* __restrict__ Wk,
                            const float* __restrict__ Wv,
                            __half* __restrict__ T)
{
    __shared__ float t[32][33];
    int z = blockIdx.z;
    int mat = z / HH, h = z - mat * HH;
    const float* W = (mat == 0 ? Wq : mat == 1 ? Wk : Wv) + (size_t)h * DD * HDIM;
    int k0 = blockIdx.y * 32, e0 = blockIdx.x * 32;
    int tx = threadIdx.x, ty = threadIdx.y;
    #pragma unroll
    for (int i = 0; i < 32; i += 8)
        t[ty + i][tx] = W[(size_t)(k0 + ty + i) * HDIM + e0 + tx];
    __syncthreads();
    int nbase = mat * 1024 + h * HDIM;
    #pragma unroll
    for (int i = 0; i < 32; i += 8) {
        float v = t[tx][ty + i];
        T[(size_t)(nbase + e0 + ty + i) * DD + k0 + tx] = __float2half(v);
    }
}

// swizzled byte offset for (row, 16B-chunk ck) within a 128B-row matrix
#define GSW(r, ck) ((unsigned int)((r) * 128 + ((((ck) ^ ((r) & 7))) << 4)))

// ===================== single-fp16 GEMM, 2 CTAs/SM ==============
// D = A*B. Block 128x128, 256 threads (8 warps, warp 64x32), K-chunk 64,
// 3-stage (32KB/stage, 96KB total) -> 2 CTAs co-resident per SM.
#define G1_A  0
#define G1_B  16384
#define G1_STG 32768
#define G1_SMEM (3*G1_STG)     // 98304

template<bool BIAS, bool RELU, bool F32OUT, bool HALFOUT>
__global__ void __launch_bounds__(256, 2) gemm1_kernel(
    const __half* __restrict__ A,
    const __half* __restrict__ BT,
    const float* __restrict__ bias,
    float* __restrict__ C,
    __half* __restrict__ Ch,
    int M, int N, int K)
{
    extern __shared__ __align__(128) char smem[];
    const unsigned int sb = smem_u32(smem);
    const int tid = threadIdx.x;
    const int row0 = blockIdx.y * 128;
    const int col0 = blockIdx.x * 128;

    const int wid = tid >> 5, lane = tid & 31;
    const int wm0 = (wid & 1) * 64, wn0 = (wid >> 1) * 32;
    const int lr = lane & 15, lh = lane >> 4;

    auto load_stage = [&](int c, int s) {
        unsigned int base = sb + s * G1_STG;
        int k0 = c * 64;
        #pragma unroll
        for (int i = 0; i < 4; i++) {
            int lin = tid + (i << 8);            // 0..1023 : A rows 0..127
            int r = lin >> 3, ck = lin & 7;
            unsigned int so = GSW(r, ck);
            cp16(base + G1_A + so, A + (size_t)(row0 + r) * K + k0 + ck * 8);
        }
        #pragma unroll
        for (int i = 0; i < 4; i++) {
            int lin = tid + (i << 8);            // 0..1023 : B rows 0..127
            int r = lin >> 3, ck = lin & 7;
            unsigned int so = GSW(r, ck);
            cp16(base + G1_B + so, BT + (size_t)(col0 + r) * K + k0 + ck * 8);
        }
        CP_COMMIT();
    };

    float acc[4][4][4] = {};

    load_stage(0, 0);
    load_stage(1, 1);
    load_stage(2, 2);

    const int NC = K >> 6;
    for (int c = 0; c < NC; c++) {
        CP_WAIT2();
        __syncthreads();

        unsigned int base = sb + (c % 3) * G1_STG;
        #pragma unroll
        for (int ks = 0; ks < 4; ks++) {
            unsigned int a_r[4][4], b_r[2][4];
            #pragma unroll
            for (int mt = 0; mt < 4; mt++) {
                int r = wm0 + mt*16 + lr;
                unsigned int ro = GSW(r, ks*2 + lh);
                ldsm4(a_r[mt], base + G1_A + ro);
            }
            #pragma unroll
            for (int bt = 0; bt < 2; bt++) {
                int r = wn0 + bt*16 + lr;
                unsigned int ro = GSW(r, ks*2 + lh);
                ldsm4(b_r[bt], base + G1_B + ro);
            }
            #pragma unroll
            for (int mt = 0; mt < 4; mt++)
                #pragma unroll
                for (int nt = 0; nt < 4; nt++)
                    mma_f16(acc[mt][nt], a_r[mt], b_r[nt>>1][nt&1], b_r[nt>>1][(nt&1)+2]);
        }

        __syncthreads();
        if (c + 3 < NC) load_stage(c + 3, (c + 3) % 3);
    }

    // ---- epilogue ----
    const int gq = lane >> 2, pq = lane & 3;
    #pragma unroll
    for (int mt = 0; mt < 4; mt++) {
        #pragma unroll
        for (int nt = 0; nt < 4; nt++) {
            int col = col0 + wn0 + nt*8 + pq*2;
            float b0 = 0.f, b1 = 0.f;
            if (BIAS) { b0 = bias[col]; b1 = bias[col+1]; }
            #pragma unroll
            for (int h2 = 0; h2 < 2; h2++) {
                int row = row0 + wm0 + mt*16 + gq + h2*8;
                float v0 = acc[mt][nt][h2*2+0] + b0;
                float v1 = acc[mt][nt][h2*2+1] + b1;
                if (RELU) { v0 = fmaxf(v0, 0.f); v1 = fmaxf(v1, 0.f); }
                if (F32OUT)
                    *(float2*)(C + (size_t)row * N + col) = make_float2(v0, v1);
                if (HALFOUT)
                    *(unsigned int*)(Ch + (size_t)row * N + col) = pack2f(v0, v1);
            }
        }
    }
}

// ===================== tensor-core causal flash attention (single fp16) =======
#define AP 144
#define KMAT 9216              // 64*AP
#define QMAT 18432             // 128*AP
#define FA_STG (2*KMAT)        // 18432
#define FA_SMEM (QMAT + 2*FA_STG)   // 55296

__global__ void __launch_bounds__(256, 1) flash_tc_kernel()
{
    const int pid = blockIdx.x, bh = blockIdx.y;
    const int b = bh >> 4, h = bh & 15;
    const int tid = threadIdx.x, wid = tid >> 5, lane = tid & 31;
    const int wm = wid * 16;
    const int lr = lane & 15, lh = lane >> 4;

    extern __shared__ __align__(16) char smem[];
    const unsigned int sb = smem_u32(smem);
    const unsigned int sQ = sb;

    for (int run = 0; run < 2; run++) {
        const int qt0 = run ? (15 - pid) : pid;
        const int NKT = 2 * qt0 + 2;

        __syncthreads();

        {
            const __half* q = g_qkvf + (size_t)(b*SS + qt0*128)*3072 + h*HDIM;
            #pragma unroll
            for (int i = 0; i < 4; i++) {
                int lin = tid + (i << 8);
                int r = lin >> 3, ck = lin & 7;
                cp16(sQ + r*AP + ck*16, q + (size_t)r*3072 + ck*8);
            }
            CP_COMMIT();
        }

        auto load_kv = [&](int kt, int s) {
            unsigned int base = sb + QMAT + s * FA_STG;
            size_t rowb = (size_t)(b*SS + kt*64)*3072;
            const __half* k = g_qkvf + rowb + 1024 + h*HDIM;
            const __half* v = g_qkvf + rowb + 2048 + h*HDIM;
            #pragma unroll
            for (int i = 0; i < 2; i++) {
                int lin = tid + (i << 8);
                int r = lin >> 3, ck = lin & 7;
                unsigned int so = r*AP + ck*16;
                size_t g = (size_t)r*3072 + ck*8;
                cp16(base + so,        k + g);
                cp16(base + KMAT + so, v + g);
            }
            CP_COMMIT();
        };

        load_kv(0, 0);
        load_kv(1, 1);

        float o[8][4] = {};
        float m0 = -1e30f, m1 = -1e30f, l0 = 0.f, l1 = 0.f;

        for (int kt = 0; kt < NKT; kt++) {
            if (kt < NKT - 1) CP_WAIT1(); else CP_WAIT0();
            __syncthreads();

            const unsigned int kb = sb + QMAT + (kt & 1) * FA_STG;

            float sc[8][4] = {};
            #pragma unroll
            for (int kd = 0; kd < 4; kd++) {
                unsigned int aq[4];
                unsigned int qro = (unsigned int)(wm + lr)*AP + (kd*2 + lh)*16;
                ldsm4(aq, sQ + qro);
                #pragma unroll
                for (int g = 0; g < 4; g++) {
                    unsigned int rk[4];
                    unsigned int kro = (unsigned int)(g*16 + lr)*AP + (kd*2 + lh)*16;
                    ldsm4(rk, kb + kro);
                    mma_f16(sc[2*g],   aq, rk[0], rk[2]);
                    mma_f16(sc[2*g+1], aq, rk[1], rk[3]);
                }
            }

            if (kt >= 2*qt0) {
                const int grow0 = qt0*128 + wm + (lane >> 2);
                const int gc0 = kt*64 + (lane & 3)*2;
                #pragma unroll
                for (int nt = 0; nt < 8; nt++) {
                    int c0l = gc0 + nt*8;
                    sc[nt][0] = (c0l     > grow0)   ? -1e30f : sc[nt][0]*0.125f;
                    sc[nt][1] = (c0l + 1 > grow0)   ? -1e30f : sc[nt][1]*0.125f;
                    sc[nt][2] = (c0l     > grow0+8) ? -1e30f : sc[nt][2]*0.125f;
                    sc[nt][3] = (c0l + 1 > grow0+8) ? -1e30f : sc[nt][3]*0.125f;
                }
            } else {
                #pragma unroll
                for (int nt = 0; nt < 8; nt++) {
                    sc[nt][0] *= 0.125f; sc[nt][1] *= 0.125f;
                    sc[nt][2] *= 0.125f; sc[nt][3] *= 0.125f;
                }
            }

            float mx0 = -1e30f, mx1 = -1e30f;
            #pragma unroll
            for (int nt = 0; nt < 8; nt++) {
                mx0 = fmaxf(mx0, fmaxf(sc[nt][0], sc[nt][1]));
                mx1 = fmaxf(mx1, fmaxf(sc[nt][2], sc[nt][3]));
            }
            mx0 = fmaxf(mx0, __shfl_xor_sync(0xffffffffu, mx0, 1));
            mx0 = fmaxf(mx0, __shfl_xor_sync(0xffffffffu, mx0, 2));
            mx1 = fmaxf(mx1, __shfl_xor_sync(0xffffffffu, mx1, 1));
            mx1 = fmaxf(mx1, __shfl_xor_sync(0xffffffffu, mx1, 2));
            float mn0 = fmaxf(m0, mx0), mn1 = fmaxf(m1, mx1);
            float cf0 = __expf(m0 - mn0), cf1 = __expf(m1 - mn1);
            m0 = mn0; m1 = mn1;
            float s0 = 0.f, s1 = 0.f;
            #pragma unroll
            for (int nt = 0; nt < 8; nt++) {
                sc[nt][0] = __expf(sc[nt][0] - mn0);
                sc[nt][1] = __expf(sc[nt][1] - mn0);
                sc[nt][2] = __expf(sc[nt][2] - mn1);
                sc[nt][3] = __expf(sc[nt][3] - mn1);
                s0 += sc[nt][0] + sc[nt][1];
                s1 += sc[nt][2] + sc[nt][3];
            }
            s0 += __shfl_xor_sync(0xffffffffu, s0, 1);
            s0 += __shfl_xor_sync(0xffffffffu, s0, 2);
            s1 += __shfl_xor_sync(0xffffffffu, s1, 1);
            s1 += __shfl_xor_sync(0xffffffffu, s1, 2);
            l0 = l0 * cf0 + s0;
            l1 = l1 * cf1 + s1;
            #pragma unroll
            for (int dt = 0; dt < 8; dt++) {
                o[dt][0] *= cf0; o[dt][1] *= cf0;
                o[dt][2] *= cf1; o[dt][3] *= cf1;
            }

            #pragma unroll
            for (int j = 0; j < 4; j++) {
                unsigned int ph[4];
                ph[0] = pack2f(sc[2*j][0],   sc[2*j][1]);
                ph[1] = pack2f(sc[2*j][2],   sc[2*j][3]);
                ph[2] = pack2f(sc[2*j+1][0], sc[2*j+1][1]);
                ph[3] = pack2f(sc[2*j+1][2], sc[2*j+1][3]);
                #pragma unroll
                for (int g = 0; g < 4; g++) {
                    unsigned int rv[4];
                    unsigned int vro = (unsigned int)(j*16 + lr)*AP + (g*2 + lh)*16;
                    ldsm4t(rv, kb + KMAT + vro);
                    mma_f16(o[2*g],   ph, rv[0], rv[1]);
                    mma_f16(o[2*g+1], ph, rv[2], rv[3]);
                }
            }

            __syncthreads();
            if (kt + 2 < NKT) load_kv(kt + 2, kt & 1);
        }

        const float inv0 = 1.f / l0, inv1 = 1.f / l1;
        const int row0g = qt0*128 + wm + (lane >> 2);
        __half* op = g_af + ((size_t)bh*SS)*HDIM;
        #pragma unroll
        for (int dt = 0; dt < 8; dt++) {
            int d = dt*8 + (lane & 3)*2;
            *(unsigned int*)(op + (size_t)row0g*HDIM + d) =
                pack2f(o[dt][0]*inv0, o[dt][1]*inv0);
            *(unsigned int*)(op + (size_t)(row0g+8)*HDIM + d) =
                pack2f(o[dt][2]*inv1, o[dt][3]*inv1);
        }
    }
}

// ===================== LayerNorm =====================
__device__ __forceinline__ float blk_sum(float v, float* sred)
{
    #pragma unroll
    for (int o = 16; o; o >>= 1) v += __shfl_xor_sync(0xffffffffu, v, o);
    int w = threadIdx.x >> 5;
    if ((threadIdx.x & 31) == 0) sred[w] = v;
    __syncthreads();
    float t = (threadIdx.x < 8) ? sred[threadIdx.x] : 0.f;
    if (threadIdx.x < 32) {
        #pragma unroll
        for (int o = 4; o; o >>= 1) t += __shfl_xor_sync(0xffffffffu, t, o);
        if (threadIdx.x == 0) sred[0] = t;
    }
    __syncthreads();
    float r = sred[0];
    __syncthreads();
    return r;
}

template<bool OUTH>
__global__ void ln_kernel(const float* __restrict__ resid,
                          const float* __restrict__ y,
                          const float* __restrict__ gamma,
                          const float* __restrict__ beta,
                          float* __restrict__ outf,
                          __half* __restrict__ oh)
{
    __shared__ float sred[32];
    const int row = blockIdx.x;
    const int tid = threadIdx.x;

    float4 a = ((const float4*)(resid + (size_t)row * DD))[tid];
    float4 b = ((const float4*)(y     + (size_t)row * DD))[tid];
    float4 v = make_float4(a.x + b.x, a.y + b.y, a.z + b.z, a.w + b.w);

    float total = blk_sum(v.x + v.y + v.z + v.w, sred);
    float mu = total * (1.f / DD);

    float dx = v.x - mu, dy = v.y - mu, dz = v.z - mu, dw = v.w - mu;
    float tot2 = blk_sum(dx*dx + dy*dy + dz*dz + dw*dw, sred);
    float inv = rsqrtf(tot2 * (1.f / DD) + LN_EPS);

    float4 g = ((const float4*)gamma)[tid];
    float4 be = ((const float4*)beta)[tid];
    float ov[4];
    ov[0] = dx * inv * g.x + be.x;
    ov[1] = dy * inv * g.y + be.y;
    ov[2] = dz * inv * g.z + be.z;
    ov[3] = dw * inv * g.w + be.w;
    ((float4*)(outf + (size_t)row * DD))[tid] = make_float4(ov[0], ov[1], ov[2], ov[3]);

    if (OUTH) {
        *(uint2*)(oh + (size_t)row * DD + tid * 4) =
            make_uint2(pack2f(ov[0], ov[1]), pack2f(ov[2], ov[3]));
    }
}

// ===================== launch =====================
extern "C" void kernel_launch(void* const* d_in, const int* in_sizes, int n_in,
                              void* d_out, int out_size)
{
    (void)in_sizes; (void)n_in; (void)out_size;

    const float* x     = (const float*)d_in[0];
    const float* Wq    = (const float*)d_in[1];
    const float* Wk    = (const float*)d_in[2];
    const float* Wv    = (const float*)d_in[3];
    const float* Wo    = (const float*)d_in[4];
    const float* g1    = (const float*)d_in[5];
    const float* be1   = (const float*)d_in[6];
    const float* w_in  = (const float*)d_in[7];
    const float* b_in  = (const float*)d_in[8];
    const float* w_out = (const float*)d_in[9];
    const float* b_out = (const float*)d_in[10];
    const float* g2    = (const float*)d_in[11];
    const float* be2   = (const float*)d_in[12];
    float* out = (float*)d_out;

    float *tmp, *x1;
    __half *xf, *qkvf, *af, *x1f, *h1f;
    __half *wqkvf, *wof, *winf, *woutf;
    cudaGetSymbolAddress((void**)&tmp,  g_tmp);
    cudaGetSymbolAddress((void**)&x1,   g_x1);
    cudaGetSymbolAddress((void**)&xf,   g_xf);
    cudaGetSymbolAddress((void**)&qkvf, g_qkvf);
    cudaGetSymbolAddress((void**)&af,   g_af);
    cudaGetSymbolAddress((void**)&x1f,  g_x1f);
    cudaGetSymbolAddress((void**)&h1f,  g_h1f);
    cudaGetSymbolAddress((void**)&wqkvf, g_wqkvf);
    cudaGetSymbolAddress((void**)&wof,   g_wof);
    cudaGetSymbolAddress((void**)&winf,  g_winf);
    cudaGetSymbolAddress((void**)&woutf, g_woutf);

    cudaFuncSetAttribute(flash_tc_kernel, cudaFuncAttributeMaxDynamicSharedMemorySize, FA_SMEM);
    cudaFuncSetAttribute(gemm1_kernel<false,false,false,true>, cudaFuncAttributeMaxDynamicSharedMemorySize, G1_SMEM);
    cudaFuncSetAttribute(gemm1_kernel<false,false,true,false>, cudaFuncAttributeMaxDynamicSharedMemorySize, G1_SMEM);
    cudaFuncSetAttribute(gemm1_kernel<true,true,false,true>,   cudaFuncAttributeMaxDynamicSharedMemorySize, G1_SMEM);
    cudaFuncSetAttribute(gemm1_kernel<true,false,true,false>,  cudaFuncAttributeMaxDynamicSharedMemorySize, G1_SMEM);

    // ---- prep: convert x; transpose weights to single fp16 ----
    fconvert_kernel<<<MM*DD/1024, 256>>>(x, xf, MM*DD/4);
    qkvT_kernel<<<dim3(2, 32, 48), dim3(32, 8)>>>(Wq, Wk, Wv, wqkvf);
    wsplit3_kernel<<<9216, dim3(32, 8)>>>(Wo, w_in, w_out);

    // ---- 1) fused QKV projection (single fp16) ----
    gemm1_kernel<false,false,false,true><<<dim3(3072/128, MM/128), 256, G1_SMEM>>>(
        xf, wqkvf, nullptr, nullptr, qkvf, MM, 3072, 1024);

    // ---- 2) causal flash attention (single fp16) ----
    flash_tc_kernel<<<dim3(SS/256, BB*HH), 256, FA_SMEM>>>();

    // ---- 3) output projection ----
    gemm1_kernel<false,false,true,false><<<dim3(1024/128, MM/128), 256, G1_SMEM>>>(
        af, wof, nullptr, tmp, nullptr, MM, 1024, 1024);

    // ---- 4) LN1 (x + attn@Wo) -> fp32 + fp16 ----
    ln_kernel<true><<<MM, 256>>>(x, tmp, g1, be1, x1, x1f);

    // ---- 5) FFN up + bias + ReLU -> fp16 ----
    gemm1_kernel<true,true,false,true><<<dim3(4096/128, MM/128), 256, G1_SMEM>>>(
        x1f, winf, b_in, nullptr, h1f, MM, 4096, 1024);

    // ---- 6) FFN down + bias -> fp32 ----
    gemm1_kernel<true,false,true,false><<<dim3(1024/128, MM/128), 256, G1_SMEM>>>(
        h1f, woutf, b_out, tmp, nullptr, MM, 1024, 4096);

    // ---- 7) LN2 -> output ----
    ln_kernel<false><<<MM, 256>>>(x1, tmp, g2, be2, out, nullptr);
}